// round 7
// baseline (speedup 1.0000x reference)
#include <cuda_runtime.h>
#include <math.h>

#define Bn   2
#define Sn   2048
#define En   1024
#define Hn   16
#define Dn   64
#define NEXP 8
#define NTOK (Bn*Sn)          // 4096
#define BHn  (Bn*Hn)          // 32
#define ROTSTRIDE ((size_t)BHn*Sn*Dn)

// ---------------- scratch ----------------
__device__ float g_lin [(size_t)3*NTOK*En];
__device__ float g_rot [(size_t)3*BHn*Sn*Dn];
__device__ float g_vt  [(size_t)BHn*Dn*Sn];        // V transposed (bh, d, s)
__device__ float g_probs[(size_t)BHn*Sn*Sn];       // 512 MB
__device__ float g_attn[(size_t)NTOK*En];
__device__ float g_sel [(size_t)2*NTOK*En];
__device__ float g_moe [(size_t)NTOK*En];
__device__ float g_gateflat[2*NTOK];
__device__ int   g_list[NEXP*NTOK];
__device__ int   g_cnt [NEXP];

__global__ void zero_cnt_kernel() {
    if (threadIdx.x < NEXP) g_cnt[threadIdx.x] = 0;
}

// ---------------- tf32 helpers ----------------
__device__ __forceinline__ unsigned f2tf(float x) {
    unsigned r;
    asm("cvt.rna.tf32.f32 %0, %1;" : "=r"(r) : "f"(x));
    return r;
}
__device__ __forceinline__ void mma8(float* c, const unsigned* a, const unsigned* b) {
    asm volatile(
        "mma.sync.aligned.m16n8k8.row.col.f32.tf32.tf32.f32 "
        "{%0,%1,%2,%3}, {%4,%5,%6,%7}, {%8,%9}, {%0,%1,%2,%3};\n"
        : "+f"(c[0]), "+f"(c[1]), "+f"(c[2]), "+f"(c[3])
        : "r"(a[0]), "r"(a[1]), "r"(a[2]), "r"(a[3]), "r"(b[0]), "r"(b[1]));
}
template<int SPLIT>
__device__ __forceinline__ uint2 pack_tf(float v) {
    unsigned hi = f2tf(v);
    unsigned lo = 0u;
    if (SPLIT) lo = f2tf(v - __uint_as_float(hi));
    return make_uint2(hi, lo);
}

// ---------------- pipelined packed-tf32 GEMM ----------------
// C[z] = alpha * A[z][M][K] * B[z][N][K]^T (+bias) (+resid)
// MODE 0: plain   MODE 1: QKV (z picks B/bias, C plane)
// MODE 2: PV scatter into head layout   MODE 3: expert gather/scatter
template<int BN, int SPLIT, int MODE>
__global__ void __launch_bounds__(256)
gemm_pk(const float* __restrict__ A0,
        const float* __restrict__ B0, const float* __restrict__ B1,
        const float* __restrict__ B2,
        const float* __restrict__ bias0, const float* __restrict__ bias1,
        const float* __restrict__ bias2,
        const float* __restrict__ resid,
        float* __restrict__ Cg,
        int N, int K,
        long long sAz, long long sBz, long long sCz,
        float alpha)
{
    constexpr int WC   = (BN == 128) ? 4 : 2;
    constexpr int MT   = (BN == 128) ? 4 : 2;
    constexpr int ASTG = 128 * 32;
    constexpr int BSTG = BN * 32;
    constexpr int BL   = (BN * 32) / 1024;

    extern __shared__ uint2 sm[];
    uint2* Asm = sm;               // [2][ASTG]
    uint2* Bsm = sm + 2 * ASTG;    // [2][BSTG]

    __shared__ int   rowflat[128];
    __shared__ float rowgate[128];

    const int tid = threadIdx.x;
    const int z   = blockIdx.z;
    const int m0  = blockIdx.y * 128;
    const int n0  = blockIdx.x * BN;

    int cnt = 0;
    if (MODE == 3) {
        cnt = g_cnt[z];
        if (m0 >= cnt) return;
        if (tid < 128) {
            int m = m0 + tid;
            int fl = (m < cnt) ? g_list[z * NTOK + m] : 0;
            rowflat[tid] = fl;
            rowgate[tid] = (m < cnt) ? g_gateflat[fl] : 0.f;
        }
        __syncthreads();
    }

    const float* A = A0 + (size_t)z * sAz;
    const float* B;
    const float* bias;
    if (MODE == 1) {
        B    = (z == 0) ? B0 : ((z == 1) ? B1 : B2);
        bias = (z == 0) ? bias0 : ((z == 1) ? bias1 : bias2);
    } else if (MODE == 3) {
        B    = B0 + (size_t)z * sBz;
        bias = bias0 + (size_t)z * En;
    } else {
        B    = B0 + (size_t)z * sBz;
        bias = bias0;
    }

    // per-thread gmem pointers (fixed across k-tiles)
    const float* aP[4]; int aR[4], aC[4];
    #pragma unroll
    for (int l = 0; l < 4; l++) {
        int idx = l * 256 + tid;
        int r = idx >> 3, c4 = (idx & 7) << 2;
        aR[l] = r; aC[l] = c4;
        const float* base = (MODE == 3)
            ? (g_attn + (size_t)(rowflat[r] >> 1) * En)
            : (A + (size_t)(m0 + r) * K);
        aP[l] = base + c4;
    }
    const float* bP[BL]; int bR[BL], bC[BL];
    #pragma unroll
    for (int l = 0; l < BL; l++) {
        int idx = l * 256 + tid;
        int r = idx >> 3, c4 = (idx & 7) << 2;
        bR[l] = r; bC[l] = c4;
        bP[l] = B + (size_t)(n0 + r) * K + c4;
    }

    const int lane = tid & 31, warp = tid >> 5;
    const int grp  = lane >> 2, qd = lane & 3;
    const int m0w  = (warp / WC) * (16 * MT);
    const int n0w  = (warp % WC) * 32;
    const int sw   = grp << 2;

    float acc[MT][4][4];
    #pragma unroll
    for (int i = 0; i < MT; i++)
        #pragma unroll
        for (int j = 0; j < 4; j++)
            #pragma unroll
            for (int c = 0; c < 4; c++) acc[i][j][c] = 0.f;

    float4 ra[4], rb[BL];

    auto stash = [&](int stg) {
        #pragma unroll
        for (int l = 0; l < 4; l++) {
            uint2* d = Asm + stg * ASTG + aR[l] * 32;
            int s = (aR[l] & 7) << 2;
            d[(aC[l] + 0) ^ s] = pack_tf<SPLIT>(ra[l].x);
            d[(aC[l] + 1) ^ s] = pack_tf<SPLIT>(ra[l].y);
            d[(aC[l] + 2) ^ s] = pack_tf<SPLIT>(ra[l].z);
            d[(aC[l] + 3) ^ s] = pack_tf<SPLIT>(ra[l].w);
        }
        #pragma unroll
        for (int l = 0; l < BL; l++) {
            uint2* d = Bsm + stg * BSTG + bR[l] * 32;
            int s = (bR[l] & 7) << 2;
            d[(bC[l] + 0) ^ s] = pack_tf<SPLIT>(rb[l].x);
            d[(bC[l] + 1) ^ s] = pack_tf<SPLIT>(rb[l].y);
            d[(bC[l] + 2) ^ s] = pack_tf<SPLIT>(rb[l].z);
            d[(bC[l] + 3) ^ s] = pack_tf<SPLIT>(rb[l].w);
        }
    };

    // prologue
    #pragma unroll
    for (int l = 0; l < 4;  l++) ra[l] = *(const float4*)(aP[l]);
    #pragma unroll
    for (int l = 0; l < BL; l++) rb[l] = *(const float4*)(bP[l]);
    stash(0);
    __syncthreads();

    const int NTILE = K >> 5;
    for (int t = 0; t < NTILE; t++) {
        if (t + 1 < NTILE) {
            int off = (t + 1) << 5;
            #pragma unroll
            for (int l = 0; l < 4;  l++) ra[l] = *(const float4*)(aP[l] + off);
            #pragma unroll
            for (int l = 0; l < BL; l++) rb[l] = *(const float4*)(bP[l] + off);
        }
        const uint2* Ab = Asm + (t & 1) * ASTG + (m0w + grp) * 32;
        const uint2* Bb = Bsm + (t & 1) * BSTG + (n0w + grp) * 32;
        #pragma unroll
        for (int kk = 0; kk < 32; kk += 8) {
            int c0 = (kk + qd)     ^ sw;
            int c1 = (kk + qd + 4) ^ sw;
            uint2 bf[4][2];
            #pragma unroll
            for (int nt = 0; nt < 4; nt++) {
                bf[nt][0] = Bb[nt * 256 + c0];
                bf[nt][1] = Bb[nt * 256 + c1];
            }
            #pragma unroll
            for (int mt = 0; mt < MT; mt++) {
                const uint2* Ar = Ab + mt * 512;
                uint2 a0 = Ar[c0], a1 = Ar[256 + c0];
                uint2 a2 = Ar[c1], a3 = Ar[256 + c1];
                unsigned ah[4] = { a0.x, a1.x, a2.x, a3.x };
                #pragma unroll
                for (int nt = 0; nt < 4; nt++) {
                    unsigned bh2[2] = { bf[nt][0].x, bf[nt][1].x };
                    mma8(acc[mt][nt], ah, bh2);
                    if (SPLIT) {
                        unsigned al[4]  = { a0.y, a1.y, a2.y, a3.y };
                        unsigned bl2[2] = { bf[nt][0].y, bf[nt][1].y };
                        mma8(acc[mt][nt], al, bh2);
                        mma8(acc[mt][nt], ah, bl2);
                    }
                }
            }
        }
        if (t + 1 < NTILE) {
            stash((t + 1) & 1);
            __syncthreads();
        }
    }

    // epilogue
    #pragma unroll
    for (int mt = 0; mt < MT; mt++) {
        #pragma unroll
        for (int h = 0; h < 2; h++) {
            int mloc = m0w + mt * 16 + grp + h * 8;
            int r = m0 + mloc;
            if (MODE == 3 && r >= cnt) continue;
            #pragma unroll
            for (int nt = 0; nt < 4; nt++) {
                int col = n0w + nt * 8 + 2 * qd;
                int gc  = n0 + col;
                float v0 = acc[mt][nt][2 * h + 0] * alpha;
                float v1 = acc[mt][nt][2 * h + 1] * alpha;
                if (MODE == 3) {
                    float gtv = rowgate[mloc];
                    v0 = gtv * (v0 + bias[gc]);
                    v1 = gtv * (v1 + bias[gc + 1]);
                    *(float2*)(g_sel + (size_t)rowflat[mloc] * En + gc) =
                        make_float2(v0, v1);
                } else if (MODE == 2) {
                    int bb = z >> 4, hh = z & 15;
                    *(float2*)(Cg + ((size_t)(bb * Sn + r)) * En + hh * 64 + gc) =
                        make_float2(v0, v1);
                } else {
                    if (bias)  { v0 += bias[gc]; v1 += bias[gc + 1]; }
                    if (resid) {
                        const float* rr = resid + (size_t)r * N + gc;
                        v0 += rr[0]; v1 += rr[1];
                    }
                    float* dst = (MODE == 1)
                        ? (Cg + (size_t)z * ((size_t)NTOK * En) + (size_t)r * N + gc)
                        : (Cg + (size_t)z * sCz + (size_t)r * N + gc);
                    *(float2*)dst = make_float2(v0, v1);
                }
            }
        }
    }
}

// ---------------- RoPE + transpose ----------------
__global__ void rope_transpose_kernel()
{
    int idx = blockIdx.x * blockDim.x + threadIdx.x;
    int i = idx & 31;
    int h = (idx >> 5) & 15;
    int s = (idx >> 9) & (Sn - 1);
    int b = idx >> 20;

    float inv = powf(10000.0f, -(float)(2 * i) / 64.0f);
    float sn, cs;
    sincosf((float)s * inv, &sn, &cs);

    size_t in_base  = ((size_t)(b * Sn + s)) * En + h * 64;
    size_t out_base = ((size_t)((b * Hn + h) * Sn + s)) * 64;
    const size_t lin_stride = (size_t)NTOK * En;

    {
        const float* src = g_lin + in_base;
        float x1 = src[i], x2 = src[i + 32];
        g_rot[out_base + i]      = x1 * cs - x2 * sn;
        g_rot[out_base + i + 32] = x2 * cs + x1 * sn;
    }
    {
        const float* src = g_lin + lin_stride + in_base;
        float x1 = src[i], x2 = src[i + 32];
        g_rot[ROTSTRIDE + out_base + i]      = x1 * cs - x2 * sn;
        g_rot[ROTSTRIDE + out_base + i + 32] = x2 * cs + x1 * sn;
    }
    {
        const float* src = g_lin + 2 * lin_stride + in_base;
        g_rot[2 * ROTSTRIDE + out_base + i]      = src[i];
        g_rot[2 * ROTSTRIDE + out_base + i + 32] = src[i + 32];
    }
}

// ---------------- V transpose: (bh, s, d) -> (bh, d, s) ----------------
__global__ void __launch_bounds__(256)
vtrans_kernel()
{
    __shared__ float t[32][33];
    const int bh = blockIdx.z;
    const int s0 = blockIdx.x * 32;
    const int d0 = blockIdx.y * 32;
    const float* src = g_rot + 2 * ROTSTRIDE + (size_t)bh * Sn * Dn;
    float* dst = g_vt + (size_t)bh * Dn * Sn;
    const int tx = threadIdx.x & 31, ty = threadIdx.x >> 5;
    #pragma unroll
    for (int i = ty; i < 32; i += 8)
        t[i][tx] = src[(size_t)(s0 + i) * Dn + d0 + tx];
    __syncthreads();
    #pragma unroll
    for (int i = ty; i < 32; i += 8)
        dst[(size_t)(d0 + i) * Sn + s0 + tx] = t[tx][i];
}

// ---------------- row softmax (in place) ----------------
__global__ void __launch_bounds__(256)
softmax_kernel(float* __restrict__ probs)
{
    __shared__ float redm[8], reds[8];
    float4* p4 = (float4*)(probs + (size_t)blockIdx.x * Sn);
    const int tid = threadIdx.x;
    const int lane = tid & 31, warp = tid >> 5;

    float4 a = p4[tid], b = p4[tid + 256];
    float m = fmaxf(fmaxf(fmaxf(a.x, a.y), fmaxf(a.z, a.w)),
                    fmaxf(fmaxf(b.x, b.y), fmaxf(b.z, b.w)));
    #pragma unroll
    for (int o = 16; o; o >>= 1) m = fmaxf(m, __shfl_xor_sync(0xffffffffu, m, o));
    if (lane == 0) redm[warp] = m;
    __syncthreads();
    float mm = redm[0];
    #pragma unroll
    for (int w = 1; w < 8; w++) mm = fmaxf(mm, redm[w]);

    a.x = __expf(a.x - mm); a.y = __expf(a.y - mm);
    a.z = __expf(a.z - mm); a.w = __expf(a.w - mm);
    b.x = __expf(b.x - mm); b.y = __expf(b.y - mm);
    b.z = __expf(b.z - mm); b.w = __expf(b.w - mm);
    float s = (a.x + a.y + a.z + a.w) + (b.x + b.y + b.z + b.w);
    #pragma unroll
    for (int o = 16; o; o >>= 1) s += __shfl_xor_sync(0xffffffffu, s, o);
    if (lane == 0) reds[warp] = s;
    __syncthreads();
    float ss = 0.f;
    #pragma unroll
    for (int w = 0; w < 8; w++) ss += reds[w];
    float invs = 1.f / ss;

    a.x *= invs; a.y *= invs; a.z *= invs; a.w *= invs;
    b.x *= invs; b.y *= invs; b.z *= invs; b.w *= invs;
    p4[tid] = a; p4[tid + 256] = b;
}

// ---------------- gate + top-2 + dispatch ----------------
__global__ void __launch_bounds__(128)
gate_topk_kernel(const float* __restrict__ gw, const float* __restrict__ gb)
{
    const int warp = threadIdx.x >> 5;
    const int lane = threadIdx.x & 31;
    const int t = blockIdx.x * 4 + warp;

    float acc[NEXP];
    #pragma unroll
    for (int e = 0; e < NEXP; e++) acc[e] = 0.f;
    const float* xr = g_attn + (size_t)t * En;
    for (int i = lane; i < En; i += 32) {
        float xv = xr[i];
        #pragma unroll
        for (int e = 0; e < NEXP; e++) acc[e] += xv * gw[e * En + i];
    }
    #pragma unroll
    for (int e = 0; e < NEXP; e++) {
        #pragma unroll
        for (int off = 16; off; off >>= 1)
            acc[e] += __shfl_xor_sync(0xffffffffu, acc[e], off);
    }
    if (lane == 0) {
        float lg[NEXP];
        float m = -1e30f;
        #pragma unroll
        for (int e = 0; e < NEXP; e++) { lg[e] = acc[e] + gb[e]; m = fmaxf(m, lg[e]); }
        float sum = 0.f;
        #pragma unroll
        for (int e = 0; e < NEXP; e++) { lg[e] = __expf(lg[e] - m); sum += lg[e]; }
        float invs = 1.f / sum;
        int i0 = 0;
        #pragma unroll
        for (int e = 1; e < NEXP; e++) if (lg[e] > lg[i0]) i0 = e;
        int i1 = (i0 == 0) ? 1 : 0;
        #pragma unroll
        for (int e = 0; e < NEXP; e++) if (e != i0 && lg[e] > lg[i1]) i1 = e;

        int p0 = atomicAdd(&g_cnt[i0], 1);
        g_list[i0 * NTOK + p0] = t * 2;
        g_gateflat[t * 2] = lg[i0] * invs;
        int p1 = atomicAdd(&g_cnt[i1], 1);
        g_list[i1 * NTOK + p1] = t * 2 + 1;
        g_gateflat[t * 2 + 1] = lg[i1] * invs;
    }
}

// ---------------- combine expert slots ----------------
__global__ void combine_kernel()
{
    size_t i = (size_t)blockIdx.x * blockDim.x + threadIdx.x;
    size_t row = i >> 8;
    size_t col = i & 255;
    const float4* s4 = (const float4*)g_sel;
    float4 a = s4[(2 * row) * 256 + col];
    float4 b = s4[(2 * row + 1) * 256 + col];
    ((float4*)g_moe)[i] = make_float4(a.x + b.x, a.y + b.y, a.z + b.z, a.w + b.w);
}

// ---------------- launch ----------------
extern "C" void kernel_launch(void* const* d_in, const int* in_sizes, int n_in,
                              void* d_out, int out_size)
{
    const float* x     = (const float*)d_in[0];
    const float* q_w   = (const float*)d_in[1];
    const float* q_b   = (const float*)d_in[2];
    const float* k_w   = (const float*)d_in[3];
    const float* k_b   = (const float*)d_in[4];
    const float* v_w   = (const float*)d_in[5];
    const float* v_b   = (const float*)d_in[6];
    const float* gatew = (const float*)d_in[7];
    const float* gateb = (const float*)d_in[8];
    const float* ew    = (const float*)d_in[9];
    const float* eb    = (const float*)d_in[10];
    const float* ffn_w = (const float*)d_in[11];
    const float* ffn_b = (const float*)d_in[12];
    float* out = (float*)d_out;

    float *lin, *rot, *vt, *probs, *attn, *moe;
    cudaGetSymbolAddress((void**)&lin,   g_lin);
    cudaGetSymbolAddress((void**)&rot,   g_rot);
    cudaGetSymbolAddress((void**)&vt,    g_vt);
    cudaGetSymbolAddress((void**)&probs, g_probs);
    cudaGetSymbolAddress((void**)&attn,  g_attn);
    cudaGetSymbolAddress((void**)&moe,   g_moe);

    const int SM128 = 2 * (128 * 32 + 128 * 32) * 8;   // 131072
    const int SM64  = 2 * (128 * 32 +  64 * 32) * 8;   //  98304
    cudaFuncSetAttribute(gemm_pk<128,1,1>, cudaFuncAttributeMaxDynamicSharedMemorySize, SM128);
    cudaFuncSetAttribute(gemm_pk<128,1,0>, cudaFuncAttributeMaxDynamicSharedMemorySize, SM128);
    cudaFuncSetAttribute(gemm_pk< 64,1,2>, cudaFuncAttributeMaxDynamicSharedMemorySize, SM64);
    cudaFuncSetAttribute(gemm_pk<128,0,3>, cudaFuncAttributeMaxDynamicSharedMemorySize, SM128);
    cudaFuncSetAttribute(gemm_pk<128,0,0>, cudaFuncAttributeMaxDynamicSharedMemorySize, SM128);

    zero_cnt_kernel<<<1, 32>>>();

    // fused QKV projections (3xTF32): grid.z picks q/k/v
    gemm_pk<128,1,1><<<dim3(En/128, NTOK/128, 3), 256, SM128>>>(
        x, q_w, k_w, v_w, q_b, k_b, v_b, nullptr, lin,
        En, En, 0, 0, 0, 1.f);

    rope_transpose_kernel<<<(Bn * Sn * Hn * 32) / 256, 256>>>();
    vtrans_kernel<<<dim3(Sn/32, Dn/32, BHn), 256>>>();

    // scores = Q K^T / 8 (3xTF32)
    gemm_pk<128,1,0><<<dim3(Sn/128, Sn/128, BHn), 256, SM128>>>(
        rot, rot + ROTSTRIDE, nullptr, nullptr, nullptr, nullptr, nullptr, nullptr,
        probs, Sn, Dn,
        (long long)Sn * Dn, (long long)Sn * Dn, (long long)Sn * Sn, 0.125f);

    softmax_kernel<<<BHn * Sn, 256>>>(probs);

    // attn_out = P V (3xTF32), B = V^T, scatter into head layout
    gemm_pk<64,1,2><<<dim3(1, Sn/128, BHn), 256, SM64>>>(
        probs, vt, nullptr, nullptr, nullptr, nullptr, nullptr, nullptr,
        attn, Dn, Sn,
        (long long)Sn * Sn, (long long)Dn * Sn, 0, 1.f);

    gate_topk_kernel<<<NTOK / 4, 128>>>(gatew, gateb);

    // expert GEMM (plain tf32, gathered)
    gemm_pk<128,0,3><<<dim3(En/128, NTOK/128, NEXP), 256, SM128>>>(
        attn, ew, nullptr, nullptr, eb, nullptr, nullptr, nullptr,
        nullptr, En, En,
        0, (long long)En * En, 0, 1.f);

    combine_kernel<<<(NTOK * (En / 4)) / 256, 256>>>();

    // final FFN + bias + residual (plain tf32)
    gemm_pk<128,0,0><<<dim3(En/128, NTOK/128, 1), 256, SM128>>>(
        moe, ffn_w, nullptr, nullptr, ffn_b, nullptr, nullptr, x,
        out, En, En, 0, 0, 0, 1.f);
}

// round 8
// speedup vs baseline: 1.1381x; 1.1381x over previous
#include <cuda_runtime.h>
#include <math.h>

#define Bn   2
#define Sn   2048
#define En   1024
#define Hn   16
#define Dn   64
#define NEXP 8
#define NTOK (Bn*Sn)          // 4096
#define BHn  (Bn*Hn)          // 32
#define ROTSTRIDE ((size_t)BHn*Sn*Dn)

// ---------------- scratch ----------------
__device__ float g_lin [(size_t)3*NTOK*En];
__device__ float g_rot [(size_t)3*BHn*Sn*Dn];
__device__ float g_vt  [(size_t)BHn*Dn*Sn];        // V transposed (bh, d, s)
__device__ float g_probs[(size_t)BHn*Sn*Sn];       // 512 MB
__device__ float g_attn[(size_t)NTOK*En];
__device__ float g_sel [(size_t)2*NTOK*En];
__device__ float g_moe [(size_t)NTOK*En];
__device__ float g_gateflat[2*NTOK];
__device__ int   g_list[NEXP*NTOK];
__device__ int   g_cnt [NEXP];

__global__ void zero_cnt_kernel() {
    if (threadIdx.x < NEXP) g_cnt[threadIdx.x] = 0;
}

// ---------------- tf32 helpers ----------------
__device__ __forceinline__ unsigned f2tf(float x) {
    unsigned r;
    asm("cvt.rna.tf32.f32 %0, %1;" : "=r"(r) : "f"(x));
    return r;
}
__device__ __forceinline__ void mma8(float* c, const unsigned* a, const unsigned* b) {
    asm volatile(
        "mma.sync.aligned.m16n8k8.row.col.f32.tf32.tf32.f32 "
        "{%0,%1,%2,%3}, {%4,%5,%6,%7}, {%8,%9}, {%0,%1,%2,%3};\n"
        : "+f"(c[0]), "+f"(c[1]), "+f"(c[2]), "+f"(c[3])
        : "r"(a[0]), "r"(a[1]), "r"(a[2]), "r"(a[3]), "r"(b[0]), "r"(b[1]));
}

template<int SPLIT> struct SEl;
template<> struct SEl<1> { using T = uint2; };
template<> struct SEl<0> { using T = unsigned; };

__device__ __forceinline__ unsigned tf_hi(uint2 v)    { return v.x; }
__device__ __forceinline__ unsigned tf_lo(uint2 v)    { return v.y; }
__device__ __forceinline__ unsigned tf_hi(unsigned v) { return v; }
__device__ __forceinline__ unsigned tf_lo(unsigned)   { return 0u; }

__device__ __forceinline__ uint2 mk_split(float v) {
    unsigned h = f2tf(v);
    return make_uint2(h, f2tf(v - __uint_as_float(h)));
}
// store 4 consecutive packed elements (split: 2x uint4, plain: 1x uint4)
__device__ __forceinline__ void stash4(uint2* d, float4 v) {
    uint2 p0 = mk_split(v.x), p1 = mk_split(v.y);
    uint2 p2 = mk_split(v.z), p3 = mk_split(v.w);
    *(uint4*)(d)     = make_uint4(p0.x, p0.y, p1.x, p1.y);
    *(uint4*)(d + 2) = make_uint4(p2.x, p2.y, p3.x, p3.y);
}
__device__ __forceinline__ void stash4(unsigned* d, float4 v) {
    *(uint4*)d = make_uint4(f2tf(v.x), f2tf(v.y), f2tf(v.z), f2tf(v.w));
}

// ---------------- packed-tf32 GEMM (round-5 structure, pre-packed smem) ----------------
// C[z] = alpha * A[z][M][K] * B[z][N][K]^T (+bias) (+resid)
// c_attn=1: scatter C into per-head layout of Cg.
template<int BN, int SPLIT>
__global__ void __launch_bounds__(256)
mma_gemm(const float* __restrict__ Ag, const float* __restrict__ Bg,
         const float* __restrict__ bias, const float* __restrict__ resid,
         float* __restrict__ Cg, int M, int N, int K,
         long long sAz, long long sBz, long long sCz,
         float alpha, int c_attn)
{
    constexpr int WC = (BN == 128) ? 4 : 2;
    constexpr int MT = (BN == 128) ? 4 : 2;
    constexpr int BL = (BN == 128) ? 4 : 2;
    using E = typename SEl<SPLIT>::T;

    extern __shared__ char smraw[];
    E* As = (E*)smraw;          // [128][36]
    E* Bs = As + 128 * 36;      // [BN][36]

    const int z = blockIdx.z;
    const float* A = Ag + (size_t)z * sAz;
    const float* B = Bg + (size_t)z * sBz;

    const int tid  = threadIdx.x;
    const int lane = tid & 31;
    const int warp = tid >> 5;
    const int grp  = lane >> 2;
    const int qd   = lane & 3;
    const int m0   = blockIdx.y * 128;
    const int n0   = blockIdx.x * BN;
    const int m0w  = (warp / WC) * (16 * MT);
    const int n0w  = (warp % WC) * 32;

    float acc[MT][4][4];
    #pragma unroll
    for (int i = 0; i < MT; i++)
        #pragma unroll
        for (int j = 0; j < 4; j++)
            #pragma unroll
            for (int c = 0; c < 4; c++) acc[i][j][c] = 0.f;

    for (int kt = 0; kt < K; kt += 32) {
        #pragma unroll
        for (int l = 0; l < 4; l++) {
            int idx = l * 256 + tid;
            int r = idx >> 3, c = (idx & 7) << 2;
            float4 v = *(const float4*)(A + (size_t)(m0 + r) * K + kt + c);
            stash4(As + r * 36 + c, v);
        }
        #pragma unroll
        for (int l = 0; l < BL; l++) {
            int idx = l * 256 + tid;
            int r = idx >> 3, c = (idx & 7) << 2;
            float4 v = *(const float4*)(B + (size_t)(n0 + r) * K + kt + c);
            stash4(Bs + r * 36 + c, v);
        }
        __syncthreads();

        #pragma unroll
        for (int kk = 0; kk < 32; kk += 8) {
            const int c0 = kk + qd, c1 = c0 + 4;
            E bf0[4], bf1[4];
            #pragma unroll
            for (int nt = 0; nt < 4; nt++) {
                const E* Bb = Bs + (n0w + nt * 8 + grp) * 36;
                bf0[nt] = Bb[c0]; bf1[nt] = Bb[c1];
            }
            #pragma unroll
            for (int mt = 0; mt < MT; mt++) {
                const E* Ar = As + (m0w + mt * 16 + grp) * 36;
                E a0 = Ar[c0], a1 = Ar[8 * 36 + c0];
                E a2 = Ar[c1], a3 = Ar[8 * 36 + c1];
                unsigned ah[4] = { tf_hi(a0), tf_hi(a1), tf_hi(a2), tf_hi(a3) };
                #pragma unroll
                for (int nt = 0; nt < 4; nt++) {
                    unsigned bh2[2] = { tf_hi(bf0[nt]), tf_hi(bf1[nt]) };
                    mma8(acc[mt][nt], ah, bh2);
                    if (SPLIT) {
                        unsigned al4[4] = { tf_lo(a0), tf_lo(a1), tf_lo(a2), tf_lo(a3) };
                        unsigned bl2[2] = { tf_lo(bf0[nt]), tf_lo(bf1[nt]) };
                        mma8(acc[mt][nt], al4, bh2);
                        mma8(acc[mt][nt], ah, bl2);
                    }
                }
            }
        }
        __syncthreads();
    }

    #pragma unroll
    for (int mt = 0; mt < MT; mt++) {
        #pragma unroll
        for (int h = 0; h < 2; h++) {
            int r = m0 + m0w + mt * 16 + grp + h * 8;
            #pragma unroll
            for (int nt = 0; nt < 4; nt++) {
                int col = n0w + nt * 8 + 2 * qd;
                int gc  = n0 + col;
                float v0 = acc[mt][nt][2 * h + 0] * alpha;
                float v1 = acc[mt][nt][2 * h + 1] * alpha;
                if (bias)  { v0 += bias[gc]; v1 += bias[gc + 1]; }
                if (resid) {
                    const float* rr = resid + (size_t)r * N + gc;
                    v0 += rr[0]; v1 += rr[1];
                }
                float2* dst;
                if (c_attn) {
                    int bb = z >> 4, hh = z & 15;
                    dst = (float2*)(Cg + ((size_t)(bb * Sn + r)) * En + hh * 64 + gc);
                } else {
                    dst = (float2*)(Cg + (size_t)z * sCz + (size_t)r * N + gc);
                }
                *dst = make_float2(v0, v1);
            }
        }
    }
}

// ---------------- grouped expert GEMM (gathered rows, plain tf32, packed smem) ----------------
__global__ void __launch_bounds__(256)
expert_mma(const float* __restrict__ ew, const float* __restrict__ eb)
{
    const int e   = blockIdx.z;
    const int cnt = g_cnt[e];
    const int m0  = blockIdx.y * 128;
    if (m0 >= cnt) return;
    const int n0  = blockIdx.x * 128;

    extern __shared__ char smraw[];
    unsigned* As = (unsigned*)smraw;   // [128][36]
    unsigned* Bs = As + 128 * 36;      // [128][36]
    __shared__ int   rowflat[128];
    __shared__ float rowgate[128];

    const int tid = threadIdx.x;
    if (tid < 128) {
        int m = m0 + tid;
        int fl = (m < cnt) ? g_list[e * NTOK + m] : 0;
        rowflat[tid] = fl;
        rowgate[tid] = (m < cnt) ? g_gateflat[fl] : 0.f;
    }
    __syncthreads();

    const float* W = ew + (size_t)e * En * En;
    const int lane = tid & 31, warp = tid >> 5;
    const int grp  = lane >> 2, qd = lane & 3;
    const int m0w  = (warp / 4) * 64;
    const int n0w  = (warp % 4) * 32;

    float acc[4][4][4];
    #pragma unroll
    for (int i = 0; i < 4; i++)
        #pragma unroll
        for (int j = 0; j < 4; j++)
            #pragma unroll
            for (int c = 0; c < 4; c++) acc[i][j][c] = 0.f;

    for (int kt = 0; kt < En; kt += 32) {
        #pragma unroll
        for (int l = 0; l < 4; l++) {
            int idx = l * 256 + tid;
            int r = idx >> 3, c = (idx & 7) << 2;
            int tok = rowflat[r] >> 1;
            float4 va = *(const float4*)(g_attn + (size_t)tok * En + kt + c);
            stash4(As + r * 36 + c, va);
            float4 vb = *(const float4*)(W + (size_t)(n0 + r) * En + kt + c);
            stash4(Bs + r * 36 + c, vb);
        }
        __syncthreads();
        #pragma unroll
        for (int kk = 0; kk < 32; kk += 8) {
            const int c0 = kk + qd, c1 = c0 + 4;
            unsigned bf0[4], bf1[4];
            #pragma unroll
            for (int nt = 0; nt < 4; nt++) {
                const unsigned* Bb = Bs + (n0w + nt * 8 + grp) * 36;
                bf0[nt] = Bb[c0]; bf1[nt] = Bb[c1];
            }
            #pragma unroll
            for (int mt = 0; mt < 4; mt++) {
                const unsigned* Ar = As + (m0w + mt * 16 + grp) * 36;
                unsigned ah[4] = { Ar[c0], Ar[8 * 36 + c0], Ar[c1], Ar[8 * 36 + c1] };
                #pragma unroll
                for (int nt = 0; nt < 4; nt++) {
                    unsigned bh2[2] = { bf0[nt], bf1[nt] };
                    mma8(acc[mt][nt], ah, bh2);
                }
            }
        }
        __syncthreads();
    }

    #pragma unroll
    for (int mt = 0; mt < 4; mt++) {
        #pragma unroll
        for (int h = 0; h < 2; h++) {
            int mloc = m0w + mt * 16 + grp + h * 8;
            if (m0 + mloc >= cnt) continue;
            int fl = rowflat[mloc];
            float gtv = rowgate[mloc];
            #pragma unroll
            for (int nt = 0; nt < 4; nt++) {
                int gc = n0 + n0w + nt * 8 + 2 * qd;
                float v0 = gtv * (acc[mt][nt][2 * h + 0] + eb[(size_t)e * En + gc]);
                float v1 = gtv * (acc[mt][nt][2 * h + 1] + eb[(size_t)e * En + gc + 1]);
                *(float2*)(g_sel + (size_t)fl * En + gc) = make_float2(v0, v1);
            }
        }
    }
}

// ---------------- RoPE + transpose ----------------
__global__ void rope_transpose_kernel()
{
    int idx = blockIdx.x * blockDim.x + threadIdx.x;
    int i = idx & 31;
    int h = (idx >> 5) & 15;
    int s = (idx >> 9) & (Sn - 1);
    int b = idx >> 20;

    float inv = powf(10000.0f, -(float)(2 * i) / 64.0f);
    float sn, cs;
    sincosf((float)s * inv, &sn, &cs);

    size_t in_base  = ((size_t)(b * Sn + s)) * En + h * 64;
    size_t out_base = ((size_t)((b * Hn + h) * Sn + s)) * 64;
    const size_t lin_stride = (size_t)NTOK * En;

    {
        const float* src = g_lin + in_base;
        float x1 = src[i], x2 = src[i + 32];
        g_rot[out_base + i]      = x1 * cs - x2 * sn;
        g_rot[out_base + i + 32] = x2 * cs + x1 * sn;
    }
    {
        const float* src = g_lin + lin_stride + in_base;
        float x1 = src[i], x2 = src[i + 32];
        g_rot[ROTSTRIDE + out_base + i]      = x1 * cs - x2 * sn;
        g_rot[ROTSTRIDE + out_base + i + 32] = x2 * cs + x1 * sn;
    }
    {
        const float* src = g_lin + 2 * lin_stride + in_base;
        g_rot[2 * ROTSTRIDE + out_base + i]      = src[i];
        g_rot[2 * ROTSTRIDE + out_base + i + 32] = src[i + 32];
    }
}

// ---------------- V transpose: (bh, s, d) -> (bh, d, s) ----------------
__global__ void __launch_bounds__(256)
vtrans_kernel()
{
    __shared__ float t[32][33];
    const int bh = blockIdx.z;
    const int s0 = blockIdx.x * 32;
    const int d0 = blockIdx.y * 32;
    const float* src = g_rot + 2 * ROTSTRIDE + (size_t)bh * Sn * Dn;
    float* dst = g_vt + (size_t)bh * Dn * Sn;
    const int tx = threadIdx.x & 31, ty = threadIdx.x >> 5;
    #pragma unroll
    for (int i = ty; i < 32; i += 8)
        t[i][tx] = src[(size_t)(s0 + i) * Dn + d0 + tx];
    __syncthreads();
    #pragma unroll
    for (int i = ty; i < 32; i += 8)
        dst[(size_t)(d0 + i) * Sn + s0 + tx] = t[tx][i];
}

// ---------------- row softmax (in place) ----------------
__global__ void __launch_bounds__(256)
softmax_kernel(float* __restrict__ probs)
{
    __shared__ float redm[8], reds[8];
    float4* p4 = (float4*)(probs + (size_t)blockIdx.x * Sn);
    const int tid = threadIdx.x;
    const int lane = tid & 31, warp = tid >> 5;

    float4 a = p4[tid], b = p4[tid + 256];
    float m = fmaxf(fmaxf(fmaxf(a.x, a.y), fmaxf(a.z, a.w)),
                    fmaxf(fmaxf(b.x, b.y), fmaxf(b.z, b.w)));
    #pragma unroll
    for (int o = 16; o; o >>= 1) m = fmaxf(m, __shfl_xor_sync(0xffffffffu, m, o));
    if (lane == 0) redm[warp] = m;
    __syncthreads();
    float mm = redm[0];
    #pragma unroll
    for (int w = 1; w < 8; w++) mm = fmaxf(mm, redm[w]);

    a.x = __expf(a.x - mm); a.y = __expf(a.y - mm);
    a.z = __expf(a.z - mm); a.w = __expf(a.w - mm);
    b.x = __expf(b.x - mm); b.y = __expf(b.y - mm);
    b.z = __expf(b.z - mm); b.w = __expf(b.w - mm);
    float s = (a.x + a.y + a.z + a.w) + (b.x + b.y + b.z + b.w);
    #pragma unroll
    for (int o = 16; o; o >>= 1) s += __shfl_xor_sync(0xffffffffu, s, o);
    if (lane == 0) reds[warp] = s;
    __syncthreads();
    float ss = 0.f;
    #pragma unroll
    for (int w = 0; w < 8; w++) ss += reds[w];
    float invs = 1.f / ss;

    a.x *= invs; a.y *= invs; a.z *= invs; a.w *= invs;
    b.x *= invs; b.y *= invs; b.z *= invs; b.w *= invs;
    p4[tid] = a; p4[tid + 256] = b;
}

// ---------------- gate + top-2 + dispatch ----------------
__global__ void __launch_bounds__(128)
gate_topk_kernel(const float* __restrict__ gw, const float* __restrict__ gb)
{
    const int warp = threadIdx.x >> 5;
    const int lane = threadIdx.x & 31;
    const int t = blockIdx.x * 4 + warp;

    float acc[NEXP];
    #pragma unroll
    for (int e = 0; e < NEXP; e++) acc[e] = 0.f;
    const float* xr = g_attn + (size_t)t * En;
    for (int i = lane; i < En; i += 32) {
        float xv = xr[i];
        #pragma unroll
        for (int e = 0; e < NEXP; e++) acc[e] += xv * gw[e * En + i];
    }
    #pragma unroll
    for (int e = 0; e < NEXP; e++) {
        #pragma unroll
        for (int off = 16; off; off >>= 1)
            acc[e] += __shfl_xor_sync(0xffffffffu, acc[e], off);
    }
    if (lane == 0) {
        float lg[NEXP];
        float m = -1e30f;
        #pragma unroll
        for (int e = 0; e < NEXP; e++) { lg[e] = acc[e] + gb[e]; m = fmaxf(m, lg[e]); }
        float sum = 0.f;
        #pragma unroll
        for (int e = 0; e < NEXP; e++) { lg[e] = __expf(lg[e] - m); sum += lg[e]; }
        float invs = 1.f / sum;
        int i0 = 0;
        #pragma unroll
        for (int e = 1; e < NEXP; e++) if (lg[e] > lg[i0]) i0 = e;
        int i1 = (i0 == 0) ? 1 : 0;
        #pragma unroll
        for (int e = 0; e < NEXP; e++) if (e != i0 && lg[e] > lg[i1]) i1 = e;

        int p0 = atomicAdd(&g_cnt[i0], 1);
        g_list[i0 * NTOK + p0] = t * 2;
        g_gateflat[t * 2] = lg[i0] * invs;
        int p1 = atomicAdd(&g_cnt[i1], 1);
        g_list[i1 * NTOK + p1] = t * 2 + 1;
        g_gateflat[t * 2 + 1] = lg[i1] * invs;
    }
}

// ---------------- combine expert slots ----------------
__global__ void combine_kernel()
{
    size_t i = (size_t)blockIdx.x * blockDim.x + threadIdx.x;
    size_t row = i >> 8;
    size_t col = i & 255;
    const float4* s4 = (const float4*)g_sel;
    float4 a = s4[(2 * row) * 256 + col];
    float4 b = s4[(2 * row + 1) * 256 + col];
    ((float4*)g_moe)[i] = make_float4(a.x + b.x, a.y + b.y, a.z + b.z, a.w + b.w);
}

// ---------------- launch ----------------
extern "C" void kernel_launch(void* const* d_in, const int* in_sizes, int n_in,
                              void* d_out, int out_size)
{
    const float* x     = (const float*)d_in[0];
    const float* q_w   = (const float*)d_in[1];
    const float* q_b   = (const float*)d_in[2];
    const float* k_w   = (const float*)d_in[3];
    const float* k_b   = (const float*)d_in[4];
    const float* v_w   = (const float*)d_in[5];
    const float* v_b   = (const float*)d_in[6];
    const float* gatew = (const float*)d_in[7];
    const float* gateb = (const float*)d_in[8];
    const float* ew    = (const float*)d_in[9];
    const float* eb    = (const float*)d_in[10];
    const float* ffn_w = (const float*)d_in[11];
    const float* ffn_b = (const float*)d_in[12];
    float* out = (float*)d_out;

    float *lin, *rot, *vt, *probs, *attn, *moe;
    cudaGetSymbolAddress((void**)&lin,   g_lin);
    cudaGetSymbolAddress((void**)&rot,   g_rot);
    cudaGetSymbolAddress((void**)&vt,    g_vt);
    cudaGetSymbolAddress((void**)&probs, g_probs);
    cudaGetSymbolAddress((void**)&attn,  g_attn);
    cudaGetSymbolAddress((void**)&moe,   g_moe);

    const int SMQ = (128 + 128) * 36 * 8;   // 73728  split, BN=128
    const int SMP = (128 +  64) * 36 * 8;   // 55296  split, BN=64
    const int SMF = (128 + 128) * 36 * 4;   // 36864  plain, BN=128
    cudaFuncSetAttribute(mma_gemm<128,1>, cudaFuncAttributeMaxDynamicSharedMemorySize, SMQ);
    cudaFuncSetAttribute(mma_gemm< 64,1>, cudaFuncAttributeMaxDynamicSharedMemorySize, SMP);
    cudaFuncSetAttribute(mma_gemm<128,0>, cudaFuncAttributeMaxDynamicSharedMemorySize, SMF);
    cudaFuncSetAttribute(expert_mma,      cudaFuncAttributeMaxDynamicSharedMemorySize, SMF);

    zero_cnt_kernel<<<1, 32>>>();

    // QKV projections (3xTF32)
    dim3 pg(En / 128, NTOK / 128, 1);
    mma_gemm<128,1><<<pg, 256, SMQ>>>(x, q_w, q_b, nullptr, lin,
                                      NTOK, En, En, 0, 0, 0, 1.f, 0);
    mma_gemm<128,1><<<pg, 256, SMQ>>>(x, k_w, k_b, nullptr, lin + (size_t)NTOK * En,
                                      NTOK, En, En, 0, 0, 0, 1.f, 0);
    mma_gemm<128,1><<<pg, 256, SMQ>>>(x, v_w, v_b, nullptr, lin + (size_t)2 * NTOK * En,
                                      NTOK, En, En, 0, 0, 0, 1.f, 0);

    rope_transpose_kernel<<<(Bn * Sn * Hn * 32) / 256, 256>>>();
    vtrans_kernel<<<dim3(Sn/32, Dn/32, BHn), 256>>>();

    // scores = Q K^T / 8  (3xTF32)
    mma_gemm<128,1><<<dim3(Sn/128, Sn/128, BHn), 256, SMQ>>>(
        rot, rot + ROTSTRIDE, nullptr, nullptr, probs,
        Sn, Sn, Dn, (long long)Sn * Dn, (long long)Sn * Dn, (long long)Sn * Sn,
        0.125f, 0);

    softmax_kernel<<<BHn * Sn, 256>>>(probs);

    // attn_out = P V  (3xTF32), B = V^T (TN), scatter into head layout
    mma_gemm<64,1><<<dim3(1, Sn/128, BHn), 256, SMP>>>(
        probs, vt, nullptr, nullptr, attn,
        Sn, Dn, Sn, (long long)Sn * Sn, (long long)Dn * Sn, 0,
        1.f, 1);

    gate_topk_kernel<<<NTOK / 4, 128>>>(gatew, gateb);

    expert_mma<<<dim3(En/128, NTOK/128, NEXP), 256, SMF>>>(ew, eb);

    combine_kernel<<<(NTOK * (En / 4)) / 256, 256>>>();

    // final FFN + bias + residual (plain tf32)
    mma_gemm<128,0><<<dim3(En/128, NTOK/128, 1), 256, SMF>>>(
        moe, ffn_w, ffn_b, x, out,
        NTOK, En, En, 0, 0, 0, 1.f, 0);
}

// round 9
// speedup vs baseline: 1.5198x; 1.3354x over previous
#include <cuda_runtime.h>
#include <math.h>

#define Bn   2
#define Sn   2048
#define En   1024
#define Hn   16
#define Dn   64
#define NEXP 8
#define NTOK (Bn*Sn)          // 4096
#define BHn  (Bn*Hn)          // 32
#define ROTSTRIDE ((size_t)BHn*Sn*Dn)

// ---------------- scratch ----------------
__device__ float g_lin [(size_t)3*NTOK*En];
__device__ float g_rot [(size_t)3*BHn*Sn*Dn];
__device__ float g_vt  [(size_t)BHn*Dn*Sn];        // V transposed (bh, d, s)
__device__ float g_probs[(size_t)BHn*Sn*Sn];       // 512 MB
__device__ float g_attn[(size_t)NTOK*En];
__device__ float g_sel [(size_t)2*NTOK*En];
__device__ float g_moe [(size_t)NTOK*En];
__device__ float g_gateflat[2*NTOK];
__device__ int   g_list[NEXP*NTOK];
__device__ int   g_cnt [NEXP];

__global__ void zero_cnt_kernel() {
    if (threadIdx.x < NEXP) g_cnt[threadIdx.x] = 0;
}

// ---------------- tf32 helpers ----------------
__device__ __forceinline__ unsigned f2tf(float x) {
    unsigned r;
    asm("cvt.rna.tf32.f32 %0, %1;" : "=r"(r) : "f"(x));
    return r;
}
__device__ __forceinline__ void mma8(float* c, const unsigned* a, const unsigned* b) {
    asm volatile(
        "mma.sync.aligned.m16n8k8.row.col.f32.tf32.tf32.f32 "
        "{%0,%1,%2,%3}, {%4,%5,%6,%7}, {%8,%9}, {%0,%1,%2,%3};\n"
        : "+f"(c[0]), "+f"(c[1]), "+f"(c[2]), "+f"(c[3])
        : "r"(a[0]), "r"(a[1]), "r"(a[2]), "r"(a[3]), "r"(b[0]), "r"(b[1]));
}
__device__ __forceinline__ void cpa16(float* s, const float* g) {
    unsigned sa = (unsigned)__cvta_generic_to_shared(s);
    asm volatile("cp.async.cg.shared.global [%0], [%1], 16;" :: "r"(sa), "l"(g));
}
#define CP_COMMIT()  asm volatile("cp.async.commit_group;" ::: "memory")
#define CP_WAIT1()   asm volatile("cp.async.wait_group 1;" ::: "memory")
#define CP_WAIT0()   asm volatile("cp.async.wait_group 0;" ::: "memory")

// ---------------- cp.async double-buffered tf32 GEMM (round-5 inner loop) ----------------
// C[z] = alpha * A[z][M][K] * B[z][N][K]^T (+bias) (+resid)
// c_attn=1: scatter C into per-head layout of Cg.
template<int BN, int SPLIT>
__global__ void __launch_bounds__(256)
mma_gemm(const float* __restrict__ Ag, const float* __restrict__ Bg,
         const float* __restrict__ bias, const float* __restrict__ resid,
         float* __restrict__ Cg, int M, int N, int K,
         long long sAz, long long sBz, long long sCz,
         float alpha, int c_attn)
{
    constexpr int WC    = (BN == 128) ? 4 : 2;
    constexpr int MT    = (BN == 128) ? 4 : 2;
    constexpr int BL    = (BN == 128) ? 4 : 2;
    constexpr int A_ELE = 128 * 36;
    constexpr int B_ELE = BN * 36;

    extern __shared__ float smf[];
    // layout: As[2][A_ELE], Bs[2][B_ELE]

    const int z = blockIdx.z;
    const float* A = Ag + (size_t)z * sAz;
    const float* B = Bg + (size_t)z * sBz;

    const int tid  = threadIdx.x;
    const int lane = tid & 31;
    const int warp = tid >> 5;
    const int grp  = lane >> 2;
    const int qd   = lane & 3;
    const int m0   = blockIdx.y * 128;
    const int n0   = blockIdx.x * BN;
    const int m0w  = (warp / WC) * (16 * MT);
    const int n0w  = (warp % WC) * 32;

    // per-thread copy slots
    int aS[4]; const float* aG[4];
    #pragma unroll
    for (int l = 0; l < 4; l++) {
        int idx = l * 256 + tid;
        int r = idx >> 3, c = (idx & 7) << 2;
        aS[l] = r * 36 + c;
        aG[l] = A + (size_t)(m0 + r) * K + c;
    }
    int bS[BL]; const float* bG[BL];
    #pragma unroll
    for (int l = 0; l < BL; l++) {
        int idx = l * 256 + tid;
        int r = idx >> 3, c = (idx & 7) << 2;
        bS[l] = r * 36 + c;
        bG[l] = B + (size_t)(n0 + r) * K + c;
    }

    float acc[MT][4][4];
    #pragma unroll
    for (int i = 0; i < MT; i++)
        #pragma unroll
        for (int j = 0; j < 4; j++)
            #pragma unroll
            for (int c = 0; c < 4; c++) acc[i][j][c] = 0.f;

    // prologue: stage 0
    {
        float* As_ = smf;
        float* Bs_ = smf + 2 * A_ELE;
        #pragma unroll
        for (int l = 0; l < 4;  l++) cpa16(As_ + aS[l], aG[l]);
        #pragma unroll
        for (int l = 0; l < BL; l++) cpa16(Bs_ + bS[l], bG[l]);
        CP_COMMIT();
    }

    const int NT = K >> 5;
    for (int t = 0; t < NT; t++) {
        if (t + 1 < NT) {
            int kt = (t + 1) << 5;
            int stg = (t + 1) & 1;
            float* As_ = smf + stg * A_ELE;
            float* Bs_ = smf + 2 * A_ELE + stg * B_ELE;
            #pragma unroll
            for (int l = 0; l < 4;  l++) cpa16(As_ + aS[l], aG[l] + kt);
            #pragma unroll
            for (int l = 0; l < BL; l++) cpa16(Bs_ + bS[l], bG[l] + kt);
            CP_COMMIT();
            CP_WAIT1();
        } else {
            CP_WAIT0();
        }
        __syncthreads();

        const float* Asb = smf + (t & 1) * A_ELE;
        const float* Bsb = smf + 2 * A_ELE + (t & 1) * B_ELE;

        #pragma unroll
        for (int kk = 0; kk < 32; kk += 8) {
            const int c0 = kk + qd, c1 = c0 + 4;
            unsigned bh[4][2], bl[4][2];
            #pragma unroll
            for (int nt = 0; nt < 4; nt++) {
                const float* Bb = Bsb + (n0w + nt * 8 + grp) * 36;
                float v0 = Bb[c0], v1 = Bb[c1];
                bh[nt][0] = f2tf(v0); bh[nt][1] = f2tf(v1);
                if (SPLIT) {
                    bl[nt][0] = f2tf(v0 - __uint_as_float(bh[nt][0]));
                    bl[nt][1] = f2tf(v1 - __uint_as_float(bh[nt][1]));
                }
            }
            #pragma unroll
            for (int mt = 0; mt < MT; mt++) {
                const float* Ar = Asb + (m0w + mt * 16 + grp) * 36;
                float x0 = Ar[c0],       x1 = Ar[8 * 36 + c0];
                float x2 = Ar[c1],       x3 = Ar[8 * 36 + c1];
                unsigned ah[4] = { f2tf(x0), f2tf(x1), f2tf(x2), f2tf(x3) };
                unsigned al[4];
                if (SPLIT) {
                    al[0] = f2tf(x0 - __uint_as_float(ah[0]));
                    al[1] = f2tf(x1 - __uint_as_float(ah[1]));
                    al[2] = f2tf(x2 - __uint_as_float(ah[2]));
                    al[3] = f2tf(x3 - __uint_as_float(ah[3]));
                }
                #pragma unroll
                for (int nt = 0; nt < 4; nt++) {
                    mma8(acc[mt][nt], ah, bh[nt]);
                    if (SPLIT) {
                        mma8(acc[mt][nt], al, bh[nt]);
                        mma8(acc[mt][nt], ah, bl[nt]);
                    }
                }
            }
        }
        __syncthreads();
    }

    #pragma unroll
    for (int mt = 0; mt < MT; mt++) {
        #pragma unroll
        for (int h = 0; h < 2; h++) {
            int r = m0 + m0w + mt * 16 + grp + h * 8;
            #pragma unroll
            for (int nt = 0; nt < 4; nt++) {
                int col = n0w + nt * 8 + 2 * qd;
                int gc  = n0 + col;
                float v0 = acc[mt][nt][2 * h + 0] * alpha;
                float v1 = acc[mt][nt][2 * h + 1] * alpha;
                if (bias)  { v0 += bias[gc]; v1 += bias[gc + 1]; }
                if (resid) {
                    const float* rr = resid + (size_t)r * N + gc;
                    v0 += rr[0]; v1 += rr[1];
                }
                float2* dst;
                if (c_attn) {
                    int bb = z >> 4, hh = z & 15;
                    dst = (float2*)(Cg + ((size_t)(bb * Sn + r)) * En + hh * 64 + gc);
                } else {
                    dst = (float2*)(Cg + (size_t)z * sCz + (size_t)r * N + gc);
                }
                *dst = make_float2(v0, v1);
            }
        }
    }
}

// ---------------- grouped expert GEMM (gathered rows, plain tf32, cp.async) ----------------
__global__ void __launch_bounds__(256)
expert_mma(const float* __restrict__ ew, const float* __restrict__ eb)
{
    constexpr int A_ELE = 128 * 36;
    constexpr int B_ELE = 128 * 36;

    const int e   = blockIdx.z;
    const int cnt = g_cnt[e];
    const int m0  = blockIdx.y * 128;
    if (m0 >= cnt) return;
    const int n0  = blockIdx.x * 128;

    extern __shared__ float smf[];
    __shared__ int   rowflat[128];
    __shared__ float rowgate[128];

    const int tid = threadIdx.x;
    if (tid < 128) {
        int m = m0 + tid;
        int fl = (m < cnt) ? g_list[e * NTOK + m] : 0;
        rowflat[tid] = fl;
        rowgate[tid] = (m < cnt) ? g_gateflat[fl] : 0.f;
    }
    __syncthreads();

    const float* W = ew + (size_t)e * En * En;
    const int lane = tid & 31, warp = tid >> 5;
    const int grp  = lane >> 2, qd = lane & 3;
    const int m0w  = (warp / 4) * 64;
    const int n0w  = (warp % 4) * 32;

    int aS[4]; const float* aG[4];
    #pragma unroll
    for (int l = 0; l < 4; l++) {
        int idx = l * 256 + tid;
        int r = idx >> 3, c = (idx & 7) << 2;
        aS[l] = r * 36 + c;
        aG[l] = g_attn + (size_t)(rowflat[r] >> 1) * En + c;
    }
    int bS[4]; const float* bG[4];
    #pragma unroll
    for (int l = 0; l < 4; l++) {
        int idx = l * 256 + tid;
        int r = idx >> 3, c = (idx & 7) << 2;
        bS[l] = r * 36 + c;
        bG[l] = W + (size_t)(n0 + r) * En + c;
    }

    float acc[4][4][4];
    #pragma unroll
    for (int i = 0; i < 4; i++)
        #pragma unroll
        for (int j = 0; j < 4; j++)
            #pragma unroll
            for (int c = 0; c < 4; c++) acc[i][j][c] = 0.f;

    {
        float* As_ = smf;
        float* Bs_ = smf + 2 * A_ELE;
        #pragma unroll
        for (int l = 0; l < 4; l++) cpa16(As_ + aS[l], aG[l]);
        #pragma unroll
        for (int l = 0; l < 4; l++) cpa16(Bs_ + bS[l], bG[l]);
        CP_COMMIT();
    }

    const int NT = En >> 5;
    for (int t = 0; t < NT; t++) {
        if (t + 1 < NT) {
            int kt = (t + 1) << 5;
            int stg = (t + 1) & 1;
            float* As_ = smf + stg * A_ELE;
            float* Bs_ = smf + 2 * A_ELE + stg * B_ELE;
            #pragma unroll
            for (int l = 0; l < 4; l++) cpa16(As_ + aS[l], aG[l] + kt);
            #pragma unroll
            for (int l = 0; l < 4; l++) cpa16(Bs_ + bS[l], bG[l] + kt);
            CP_COMMIT();
            CP_WAIT1();
        } else {
            CP_WAIT0();
        }
        __syncthreads();

        const float* Asb = smf + (t & 1) * A_ELE;
        const float* Bsb = smf + 2 * A_ELE + (t & 1) * B_ELE;

        #pragma unroll
        for (int kk = 0; kk < 32; kk += 8) {
            const int c0 = kk + qd, c1 = c0 + 4;
            unsigned bf0[4], bf1[4];
            #pragma unroll
            for (int nt = 0; nt < 4; nt++) {
                const float* Bb = Bsb + (n0w + nt * 8 + grp) * 36;
                bf0[nt] = f2tf(Bb[c0]); bf1[nt] = f2tf(Bb[c1]);
            }
            #pragma unroll
            for (int mt = 0; mt < 4; mt++) {
                const float* Ar = Asb + (m0w + mt * 16 + grp) * 36;
                unsigned ah[4] = { f2tf(Ar[c0]), f2tf(Ar[8 * 36 + c0]),
                                   f2tf(Ar[c1]), f2tf(Ar[8 * 36 + c1]) };
                #pragma unroll
                for (int nt = 0; nt < 4; nt++) {
                    unsigned bh2[2] = { bf0[nt], bf1[nt] };
                    mma8(acc[mt][nt], ah, bh2);
                }
            }
        }
        __syncthreads();
    }

    #pragma unroll
    for (int mt = 0; mt < 4; mt++) {
        #pragma unroll
        for (int h = 0; h < 2; h++) {
            int mloc = m0w + mt * 16 + grp + h * 8;
            if (m0 + mloc >= cnt) continue;
            int fl = rowflat[mloc];
            float gtv = rowgate[mloc];
            #pragma unroll
            for (int nt = 0; nt < 4; nt++) {
                int gc = n0 + n0w + nt * 8 + 2 * qd;
                float v0 = gtv * (acc[mt][nt][2 * h + 0] + eb[(size_t)e * En + gc]);
                float v1 = gtv * (acc[mt][nt][2 * h + 1] + eb[(size_t)e * En + gc + 1]);
                *(float2*)(g_sel + (size_t)fl * En + gc) = make_float2(v0, v1);
            }
        }
    }
}

// ---------------- RoPE + transpose ----------------
__global__ void rope_transpose_kernel()
{
    int idx = blockIdx.x * blockDim.x + threadIdx.x;
    int i = idx & 31;
    int h = (idx >> 5) & 15;
    int s = (idx >> 9) & (Sn - 1);
    int b = idx >> 20;

    float inv = powf(10000.0f, -(float)(2 * i) / 64.0f);
    float sn, cs;
    sincosf((float)s * inv, &sn, &cs);

    size_t in_base  = ((size_t)(b * Sn + s)) * En + h * 64;
    size_t out_base = ((size_t)((b * Hn + h) * Sn + s)) * 64;
    const size_t lin_stride = (size_t)NTOK * En;

    {
        const float* src = g_lin + in_base;
        float x1 = src[i], x2 = src[i + 32];
        g_rot[out_base + i]      = x1 * cs - x2 * sn;
        g_rot[out_base + i + 32] = x2 * cs + x1 * sn;
    }
    {
        const float* src = g_lin + lin_stride + in_base;
        float x1 = src[i], x2 = src[i + 32];
        g_rot[ROTSTRIDE + out_base + i]      = x1 * cs - x2 * sn;
        g_rot[ROTSTRIDE + out_base + i + 32] = x2 * cs + x1 * sn;
    }
    {
        const float* src = g_lin + 2 * lin_stride + in_base;
        g_rot[2 * ROTSTRIDE + out_base + i]      = src[i];
        g_rot[2 * ROTSTRIDE + out_base + i + 32] = src[i + 32];
    }
}

// ---------------- V transpose: (bh, s, d) -> (bh, d, s) ----------------
__global__ void __launch_bounds__(256)
vtrans_kernel()
{
    __shared__ float t[32][33];
    const int bh = blockIdx.z;
    const int s0 = blockIdx.x * 32;
    const int d0 = blockIdx.y * 32;
    const float* src = g_rot + 2 * ROTSTRIDE + (size_t)bh * Sn * Dn;
    float* dst = g_vt + (size_t)bh * Dn * Sn;
    const int tx = threadIdx.x & 31, ty = threadIdx.x >> 5;
    #pragma unroll
    for (int i = ty; i < 32; i += 8)
        t[i][tx] = src[(size_t)(s0 + i) * Dn + d0 + tx];
    __syncthreads();
    #pragma unroll
    for (int i = ty; i < 32; i += 8)
        dst[(size_t)(d0 + i) * Sn + s0 + tx] = t[tx][i];
}

// ---------------- row softmax (in place) ----------------
__global__ void __launch_bounds__(256)
softmax_kernel(float* __restrict__ probs)
{
    __shared__ float redm[8], reds[8];
    float4* p4 = (float4*)(probs + (size_t)blockIdx.x * Sn);
    const int tid = threadIdx.x;
    const int lane = tid & 31, warp = tid >> 5;

    float4 a = p4[tid], b = p4[tid + 256];
    float m = fmaxf(fmaxf(fmaxf(a.x, a.y), fmaxf(a.z, a.w)),
                    fmaxf(fmaxf(b.x, b.y), fmaxf(b.z, b.w)));
    #pragma unroll
    for (int o = 16; o; o >>= 1) m = fmaxf(m, __shfl_xor_sync(0xffffffffu, m, o));
    if (lane == 0) redm[warp] = m;
    __syncthreads();
    float mm = redm[0];
    #pragma unroll
    for (int w = 1; w < 8; w++) mm = fmaxf(mm, redm[w]);

    a.x = __expf(a.x - mm); a.y = __expf(a.y - mm);
    a.z = __expf(a.z - mm); a.w = __expf(a.w - mm);
    b.x = __expf(b.x - mm); b.y = __expf(b.y - mm);
    b.z = __expf(b.z - mm); b.w = __expf(b.w - mm);
    float s = (a.x + a.y + a.z + a.w) + (b.x + b.y + b.z + b.w);
    #pragma unroll
    for (int o = 16; o; o >>= 1) s += __shfl_xor_sync(0xffffffffu, s, o);
    if (lane == 0) reds[warp] = s;
    __syncthreads();
    float ss = 0.f;
    #pragma unroll
    for (int w = 0; w < 8; w++) ss += reds[w];
    float invs = 1.f / ss;

    a.x *= invs; a.y *= invs; a.z *= invs; a.w *= invs;
    b.x *= invs; b.y *= invs; b.z *= invs; b.w *= invs;
    p4[tid] = a; p4[tid + 256] = b;
}

// ---------------- gate + top-2 + dispatch ----------------
__global__ void __launch_bounds__(128)
gate_topk_kernel(const float* __restrict__ gw, const float* __restrict__ gb)
{
    const int warp = threadIdx.x >> 5;
    const int lane = threadIdx.x & 31;
    const int t = blockIdx.x * 4 + warp;

    float acc[NEXP];
    #pragma unroll
    for (int e = 0; e < NEXP; e++) acc[e] = 0.f;
    const float* xr = g_attn + (size_t)t * En;
    for (int i = lane; i < En; i += 32) {
        float xv = xr[i];
        #pragma unroll
        for (int e = 0; e < NEXP; e++) acc[e] += xv * gw[e * En + i];
    }
    #pragma unroll
    for (int e = 0; e < NEXP; e++) {
        #pragma unroll
        for (int off = 16; off; off >>= 1)
            acc[e] += __shfl_xor_sync(0xffffffffu, acc[e], off);
    }
    if (lane == 0) {
        float lg[NEXP];
        float m = -1e30f;
        #pragma unroll
        for (int e = 0; e < NEXP; e++) { lg[e] = acc[e] + gb[e]; m = fmaxf(m, lg[e]); }
        float sum = 0.f;
        #pragma unroll
        for (int e = 0; e < NEXP; e++) { lg[e] = __expf(lg[e] - m); sum += lg[e]; }
        float invs = 1.f / sum;
        int i0 = 0;
        #pragma unroll
        for (int e = 1; e < NEXP; e++) if (lg[e] > lg[i0]) i0 = e;
        int i1 = (i0 == 0) ? 1 : 0;
        #pragma unroll
        for (int e = 0; e < NEXP; e++) if (e != i0 && lg[e] > lg[i1]) i1 = e;

        int p0 = atomicAdd(&g_cnt[i0], 1);
        g_list[i0 * NTOK + p0] = t * 2;
        g_gateflat[t * 2] = lg[i0] * invs;
        int p1 = atomicAdd(&g_cnt[i1], 1);
        g_list[i1 * NTOK + p1] = t * 2 + 1;
        g_gateflat[t * 2 + 1] = lg[i1] * invs;
    }
}

// ---------------- combine expert slots ----------------
__global__ void combine_kernel()
{
    size_t i = (size_t)blockIdx.x * blockDim.x + threadIdx.x;
    size_t row = i >> 8;
    size_t col = i & 255;
    const float4* s4 = (const float4*)g_sel;
    float4 a = s4[(2 * row) * 256 + col];
    float4 b = s4[(2 * row + 1) * 256 + col];
    ((float4*)g_moe)[i] = make_float4(a.x + b.x, a.y + b.y, a.z + b.z, a.w + b.w);
}

// ---------------- launch ----------------
extern "C" void kernel_launch(void* const* d_in, const int* in_sizes, int n_in,
                              void* d_out, int out_size)
{
    const float* x     = (const float*)d_in[0];
    const float* q_w   = (const float*)d_in[1];
    const float* q_b   = (const float*)d_in[2];
    const float* k_w   = (const float*)d_in[3];
    const float* k_b   = (const float*)d_in[4];
    const float* v_w   = (const float*)d_in[5];
    const float* v_b   = (const float*)d_in[6];
    const float* gatew = (const float*)d_in[7];
    const float* gateb = (const float*)d_in[8];
    const float* ew    = (const float*)d_in[9];
    const float* eb    = (const float*)d_in[10];
    const float* ffn_w = (const float*)d_in[11];
    const float* ffn_b = (const float*)d_in[12];
    float* out = (float*)d_out;

    float *lin, *rot, *vt, *probs, *attn, *moe;
    cudaGetSymbolAddress((void**)&lin,   g_lin);
    cudaGetSymbolAddress((void**)&rot,   g_rot);
    cudaGetSymbolAddress((void**)&vt,    g_vt);
    cudaGetSymbolAddress((void**)&probs, g_probs);
    cudaGetSymbolAddress((void**)&attn,  g_attn);
    cudaGetSymbolAddress((void**)&moe,   g_moe);

    const int SM128 = (2 * 128 * 36 + 2 * 128 * 36) * 4;   // 73728
    const int SM64  = (2 * 128 * 36 + 2 *  64 * 36) * 4;   // 55296
    cudaFuncSetAttribute(mma_gemm<128,1>, cudaFuncAttributeMaxDynamicSharedMemorySize, SM128);
    cudaFuncSetAttribute(mma_gemm< 64,1>, cudaFuncAttributeMaxDynamicSharedMemorySize, SM64);
    cudaFuncSetAttribute(mma_gemm<128,0>, cudaFuncAttributeMaxDynamicSharedMemorySize, SM128);
    cudaFuncSetAttribute(expert_mma,      cudaFuncAttributeMaxDynamicSharedMemorySize, SM128);

    zero_cnt_kernel<<<1, 32>>>();

    // QKV projections (3xTF32)
    dim3 pg(En / 128, NTOK / 128, 1);
    mma_gemm<128,1><<<pg, 256, SM128>>>(x, q_w, q_b, nullptr, lin,
                                        NTOK, En, En, 0, 0, 0, 1.f, 0);
    mma_gemm<128,1><<<pg, 256, SM128>>>(x, k_w, k_b, nullptr, lin + (size_t)NTOK * En,
                                        NTOK, En, En, 0, 0, 0, 1.f, 0);
    mma_gemm<128,1><<<pg, 256, SM128>>>(x, v_w, v_b, nullptr, lin + (size_t)2 * NTOK * En,
                                        NTOK, En, En, 0, 0, 0, 1.f, 0);

    rope_transpose_kernel<<<(Bn * Sn * Hn * 32) / 256, 256>>>();
    vtrans_kernel<<<dim3(Sn/32, Dn/32, BHn), 256>>>();

    // scores = Q K^T / 8  (3xTF32)
    mma_gemm<128,1><<<dim3(Sn/128, Sn/128, BHn), 256, SM128>>>(
        rot, rot + ROTSTRIDE, nullptr, nullptr, probs,
        Sn, Sn, Dn, (long long)Sn * Dn, (long long)Sn * Dn, (long long)Sn * Sn,
        0.125f, 0);

    softmax_kernel<<<BHn * Sn, 256>>>(probs);

    // attn_out = P V  (3xTF32), B = V^T (TN), scatter into head layout
    mma_gemm<64,1><<<dim3(1, Sn/128, BHn), 256, SM64>>>(
        probs, vt, nullptr, nullptr, attn,
        Sn, Dn, Sn, (long long)Sn * Sn, (long long)Dn * Sn, 0,
        1.f, 1);

    gate_topk_kernel<<<NTOK / 4, 128>>>(gatew, gateb);

    expert_mma<<<dim3(En/128, NTOK/128, NEXP), 256, SM128>>>(ew, eb);

    combine_kernel<<<(NTOK * (En / 4)) / 256, 256>>>();

    // final FFN + bias + residual (plain tf32)
    mma_gemm<128,0><<<dim3(En/128, NTOK/128, 1), 256, SM128>>>(
        moe, ffn_w, ffn_b, x, out,
        NTOK, En, En, 0, 0, 0, 1.f, 0);
}

// round 10
// speedup vs baseline: 1.5264x; 1.0044x over previous
#include <cuda_runtime.h>
#include <math.h>

#define Bn   2
#define Sn   2048
#define En   1024
#define Hn   16
#define Dn   64
#define NEXP 8
#define NTOK (Bn*Sn)          // 4096
#define BHn  (Bn*Hn)          // 32
#define PLANE ((size_t)BHn*Sn*Dn)

// ---------------- scratch ----------------
__device__ float g_lin [(size_t)3*NTOK*En];
__device__ float g_xhi [(size_t)NTOK*En];
__device__ float g_xlo [(size_t)NTOK*En];
__device__ float g_whi [(size_t)3*En*En];
__device__ float g_wlo [(size_t)3*En*En];
__device__ float g_qhi [PLANE];
__device__ float g_qlo [PLANE];
__device__ float g_khi [PLANE];
__device__ float g_klo [PLANE];
__device__ float g_v   [PLANE];
__device__ float g_vt  [(size_t)BHn*Dn*Sn];        // V transposed (bh, d, s)
__device__ float g_probs[(size_t)BHn*Sn*Sn];       // 512 MB
__device__ float g_attn[(size_t)NTOK*En];
__device__ float g_sel [(size_t)2*NTOK*En];
__device__ float g_moe [(size_t)NTOK*En];
__device__ float g_gateflat[2*NTOK];
__device__ int   g_list[NEXP*NTOK];
__device__ int   g_cnt [NEXP];

__global__ void zero_cnt_kernel() {
    if (threadIdx.x < NEXP) g_cnt[threadIdx.x] = 0;
}

// ---------------- tf32 helpers ----------------
__device__ __forceinline__ unsigned f2tf(float x) {
    unsigned r;
    asm("cvt.rna.tf32.f32 %0, %1;" : "=r"(r) : "f"(x));
    return r;
}
__device__ __forceinline__ void mma8(float* c, const unsigned* a, const unsigned* b) {
    asm volatile(
        "mma.sync.aligned.m16n8k8.row.col.f32.tf32.tf32.f32 "
        "{%0,%1,%2,%3}, {%4,%5,%6,%7}, {%8,%9}, {%0,%1,%2,%3};\n"
        : "+f"(c[0]), "+f"(c[1]), "+f"(c[2]), "+f"(c[3])
        : "r"(a[0]), "r"(a[1]), "r"(a[2]), "r"(a[3]), "r"(b[0]), "r"(b[1]));
}
__device__ __forceinline__ void cpa16(float* s, const float* g) {
    unsigned sa = (unsigned)__cvta_generic_to_shared(s);
    asm volatile("cp.async.cg.shared.global [%0], [%1], 16;" :: "r"(sa), "l"(g));
}
#define CP_COMMIT()  asm volatile("cp.async.commit_group;" ::: "memory")
#define CP_WAIT1()   asm volatile("cp.async.wait_group 1;" ::: "memory")
#define CP_WAIT0()   asm volatile("cp.async.wait_group 0;" ::: "memory")

__device__ __forceinline__ void split2(float v, float& hi, float& lo) {
    unsigned h = f2tf(v);
    hi = __uint_as_float(h);
    lo = __uint_as_float(f2tf(v - hi));
}

// ---------------- elementwise hi/lo split ----------------
__global__ void split_kernel(const float* __restrict__ in,
                             float* __restrict__ oh, float* __restrict__ ol, int n4)
{
    int i = blockIdx.x * blockDim.x + threadIdx.x;
    if (i >= n4) return;
    float4 v = ((const float4*)in)[i];
    float4 h, l;
    split2(v.x, h.x, l.x); split2(v.y, h.y, l.y);
    split2(v.z, h.z, l.z); split2(v.w, h.w, l.w);
    ((float4*)oh)[i] = h;
    ((float4*)ol)[i] = l;
}

// ---------------- pre-split tf32 GEMM, no cvt in inner loop ----------------
// C[z] = alpha * A[z]*B[z]^T (+bias). A,B given as hi/lo plane pairs.
// if b1 != null, bias selected per z from {b0,b1,b2}.
template<int BN>
__global__ void __launch_bounds__(256)
gemm_ps(const float* __restrict__ Ah, const float* __restrict__ Al,
        const float* __restrict__ Bh, const float* __restrict__ Bl,
        const float* __restrict__ b0, const float* __restrict__ b1,
        const float* __restrict__ b2,
        float* __restrict__ Cg, int N, int K,
        long long sAz, long long sBz, long long sCz, float alpha)
{
    constexpr int WC    = (BN == 128) ? 4 : 2;
    constexpr int MT    = (BN == 128) ? 4 : 2;
    constexpr int BL    = (BN == 128) ? 4 : 2;
    constexpr int A_ELE = 128 * 36;
    constexpr int B_ELE = BN * 36;

    extern __shared__ float smf[];
    float* Ah_s = smf;                    // [2][A_ELE]
    float* Al_s = smf + 2 * A_ELE;        // [2][A_ELE]
    float* Bh_s = smf + 4 * A_ELE;        // [2][B_ELE]
    float* Bl_s = smf + 4 * A_ELE + 2 * B_ELE;

    const int z = blockIdx.z;
    const float* AH = Ah + (size_t)z * sAz;
    const float* AL = Al + (size_t)z * sAz;
    const float* BH = Bh + (size_t)z * sBz;
    const float* BLp= Bl + (size_t)z * sBz;
    const float* bias = (b1 == nullptr) ? b0 : (z == 0 ? b0 : (z == 1 ? b1 : b2));

    const int tid  = threadIdx.x;
    const int lane = tid & 31;
    const int warp = tid >> 5;
    const int grp  = lane >> 2;
    const int qd   = lane & 3;
    const int m0   = blockIdx.y * 128;
    const int n0   = blockIdx.x * BN;
    const int m0w  = (warp / WC) * (16 * MT);
    const int n0w  = (warp % WC) * 32;

    int aS[4]; long long aO[4];
    #pragma unroll
    for (int l = 0; l < 4; l++) {
        int idx = l * 256 + tid;
        int r = idx >> 3, c = (idx & 7) << 2;
        aS[l] = r * 36 + c;
        aO[l] = (long long)(m0 + r) * K + c;
    }
    int bS[BL]; long long bO[BL];
    #pragma unroll
    for (int l = 0; l < BL; l++) {
        int idx = l * 256 + tid;
        int r = idx >> 3, c = (idx & 7) << 2;
        bS[l] = r * 36 + c;
        bO[l] = (long long)(n0 + r) * K + c;
    }

    float acc[MT][4][4];
    #pragma unroll
    for (int i = 0; i < MT; i++)
        #pragma unroll
        for (int j = 0; j < 4; j++)
            #pragma unroll
            for (int c = 0; c < 4; c++) acc[i][j][c] = 0.f;

    {   // prologue
        #pragma unroll
        for (int l = 0; l < 4; l++) {
            cpa16(Ah_s + aS[l], AH + aO[l]);
            cpa16(Al_s + aS[l], AL + aO[l]);
        }
        #pragma unroll
        for (int l = 0; l < BL; l++) {
            cpa16(Bh_s + bS[l], BH + bO[l]);
            cpa16(Bl_s + bS[l], BLp + bO[l]);
        }
        CP_COMMIT();
    }

    const int NT = K >> 5;
    for (int t = 0; t < NT; t++) {
        if (t + 1 < NT) {
            int kt = (t + 1) << 5;
            int stg = (t + 1) & 1;
            #pragma unroll
            for (int l = 0; l < 4; l++) {
                cpa16(Ah_s + stg * A_ELE + aS[l], AH + aO[l] + kt);
                cpa16(Al_s + stg * A_ELE + aS[l], AL + aO[l] + kt);
            }
            #pragma unroll
            for (int l = 0; l < BL; l++) {
                cpa16(Bh_s + stg * B_ELE + bS[l], BH + bO[l] + kt);
                cpa16(Bl_s + stg * B_ELE + bS[l], BLp + bO[l] + kt);
            }
            CP_COMMIT();
            CP_WAIT1();
        } else {
            CP_WAIT0();
        }
        __syncthreads();

        const float* AH_b = Ah_s + (t & 1) * A_ELE;
        const float* AL_b = Al_s + (t & 1) * A_ELE;
        const float* BH_b = Bh_s + (t & 1) * B_ELE;
        const float* BL_b = Bl_s + (t & 1) * B_ELE;

        #pragma unroll
        for (int kk = 0; kk < 32; kk += 8) {
            const int c0 = kk + qd, c1 = c0 + 4;
            unsigned bh[4][2], bl[4][2];
            #pragma unroll
            for (int nt = 0; nt < 4; nt++) {
                int roff = (n0w + nt * 8 + grp) * 36;
                bh[nt][0] = __float_as_uint(BH_b[roff + c0]);
                bh[nt][1] = __float_as_uint(BH_b[roff + c1]);
                bl[nt][0] = __float_as_uint(BL_b[roff + c0]);
                bl[nt][1] = __float_as_uint(BL_b[roff + c1]);
            }
            #pragma unroll
            for (int mt = 0; mt < MT; mt++) {
                int roff = (m0w + mt * 16 + grp) * 36;
                unsigned ah[4] = { __float_as_uint(AH_b[roff + c0]),
                                   __float_as_uint(AH_b[roff + 8 * 36 + c0]),
                                   __float_as_uint(AH_b[roff + c1]),
                                   __float_as_uint(AH_b[roff + 8 * 36 + c1]) };
                unsigned al[4] = { __float_as_uint(AL_b[roff + c0]),
                                   __float_as_uint(AL_b[roff + 8 * 36 + c0]),
                                   __float_as_uint(AL_b[roff + c1]),
                                   __float_as_uint(AL_b[roff + 8 * 36 + c1]) };
                #pragma unroll
                for (int nt = 0; nt < 4; nt++) {
                    mma8(acc[mt][nt], ah, bh[nt]);
                    mma8(acc[mt][nt], al, bh[nt]);
                    mma8(acc[mt][nt], ah, bl[nt]);
                }
            }
        }
        __syncthreads();
    }

    #pragma unroll
    for (int mt = 0; mt < MT; mt++) {
        #pragma unroll
        for (int h = 0; h < 2; h++) {
            int r = m0 + m0w + mt * 16 + grp + h * 8;
            #pragma unroll
            for (int nt = 0; nt < 4; nt++) {
                int gc = n0 + n0w + nt * 8 + 2 * qd;
                float v0 = acc[mt][nt][2 * h + 0] * alpha;
                float v1 = acc[mt][nt][2 * h + 1] * alpha;
                if (bias) { v0 += bias[gc]; v1 += bias[gc + 1]; }
                *(float2*)(Cg + (size_t)z * sCz + (size_t)r * N + gc) =
                    make_float2(v0, v1);
            }
        }
    }
}

// ---------------- cp.async double-buffered tf32 GEMM (round-9, kept for PV/FFN) ----------------
template<int BN, int SPLIT>
__global__ void __launch_bounds__(256)
mma_gemm(const float* __restrict__ Ag, const float* __restrict__ Bg,
         const float* __restrict__ bias, const float* __restrict__ resid,
         float* __restrict__ Cg, int M, int N, int K,
         long long sAz, long long sBz, long long sCz,
         float alpha, int c_attn)
{
    constexpr int WC    = (BN == 128) ? 4 : 2;
    constexpr int MT    = (BN == 128) ? 4 : 2;
    constexpr int BL    = (BN == 128) ? 4 : 2;
    constexpr int A_ELE = 128 * 36;
    constexpr int B_ELE = BN * 36;

    extern __shared__ float smf[];

    const int z = blockIdx.z;
    const float* A = Ag + (size_t)z * sAz;
    const float* B = Bg + (size_t)z * sBz;

    const int tid  = threadIdx.x;
    const int lane = tid & 31;
    const int warp = tid >> 5;
    const int grp  = lane >> 2;
    const int qd   = lane & 3;
    const int m0   = blockIdx.y * 128;
    const int n0   = blockIdx.x * BN;
    const int m0w  = (warp / WC) * (16 * MT);
    const int n0w  = (warp % WC) * 32;

    int aS[4]; const float* aG[4];
    #pragma unroll
    for (int l = 0; l < 4; l++) {
        int idx = l * 256 + tid;
        int r = idx >> 3, c = (idx & 7) << 2;
        aS[l] = r * 36 + c;
        aG[l] = A + (size_t)(m0 + r) * K + c;
    }
    int bS[BL]; const float* bG[BL];
    #pragma unroll
    for (int l = 0; l < BL; l++) {
        int idx = l * 256 + tid;
        int r = idx >> 3, c = (idx & 7) << 2;
        bS[l] = r * 36 + c;
        bG[l] = B + (size_t)(n0 + r) * K + c;
    }

    float acc[MT][4][4];
    #pragma unroll
    for (int i = 0; i < MT; i++)
        #pragma unroll
        for (int j = 0; j < 4; j++)
            #pragma unroll
            for (int c = 0; c < 4; c++) acc[i][j][c] = 0.f;

    {
        float* As_ = smf;
        float* Bs_ = smf + 2 * A_ELE;
        #pragma unroll
        for (int l = 0; l < 4;  l++) cpa16(As_ + aS[l], aG[l]);
        #pragma unroll
        for (int l = 0; l < BL; l++) cpa16(Bs_ + bS[l], bG[l]);
        CP_COMMIT();
    }

    const int NT = K >> 5;
    for (int t = 0; t < NT; t++) {
        if (t + 1 < NT) {
            int kt = (t + 1) << 5;
            int stg = (t + 1) & 1;
            float* As_ = smf + stg * A_ELE;
            float* Bs_ = smf + 2 * A_ELE + stg * B_ELE;
            #pragma unroll
            for (int l = 0; l < 4;  l++) cpa16(As_ + aS[l], aG[l] + kt);
            #pragma unroll
            for (int l = 0; l < BL; l++) cpa16(Bs_ + bS[l], bG[l] + kt);
            CP_COMMIT();
            CP_WAIT1();
        } else {
            CP_WAIT0();
        }
        __syncthreads();

        const float* Asb = smf + (t & 1) * A_ELE;
        const float* Bsb = smf + 2 * A_ELE + (t & 1) * B_ELE;

        #pragma unroll
        for (int kk = 0; kk < 32; kk += 8) {
            const int c0 = kk + qd, c1 = c0 + 4;
            unsigned bh[4][2], bl[4][2];
            #pragma unroll
            for (int nt = 0; nt < 4; nt++) {
                const float* Bb = Bsb + (n0w + nt * 8 + grp) * 36;
                float v0 = Bb[c0], v1 = Bb[c1];
                bh[nt][0] = f2tf(v0); bh[nt][1] = f2tf(v1);
                if (SPLIT) {
                    bl[nt][0] = f2tf(v0 - __uint_as_float(bh[nt][0]));
                    bl[nt][1] = f2tf(v1 - __uint_as_float(bh[nt][1]));
                }
            }
            #pragma unroll
            for (int mt = 0; mt < MT; mt++) {
                const float* Ar = Asb + (m0w + mt * 16 + grp) * 36;
                float x0 = Ar[c0],       x1 = Ar[8 * 36 + c0];
                float x2 = Ar[c1],       x3 = Ar[8 * 36 + c1];
                unsigned ah[4] = { f2tf(x0), f2tf(x1), f2tf(x2), f2tf(x3) };
                unsigned al[4];
                if (SPLIT) {
                    al[0] = f2tf(x0 - __uint_as_float(ah[0]));
                    al[1] = f2tf(x1 - __uint_as_float(ah[1]));
                    al[2] = f2tf(x2 - __uint_as_float(ah[2]));
                    al[3] = f2tf(x3 - __uint_as_float(ah[3]));
                }
                #pragma unroll
                for (int nt = 0; nt < 4; nt++) {
                    mma8(acc[mt][nt], ah, bh[nt]);
                    if (SPLIT) {
                        mma8(acc[mt][nt], al, bh[nt]);
                        mma8(acc[mt][nt], ah, bl[nt]);
                    }
                }
            }
        }
        __syncthreads();
    }

    #pragma unroll
    for (int mt = 0; mt < MT; mt++) {
        #pragma unroll
        for (int h = 0; h < 2; h++) {
            int r = m0 + m0w + mt * 16 + grp + h * 8;
            #pragma unroll
            for (int nt = 0; nt < 4; nt++) {
                int col = n0w + nt * 8 + 2 * qd;
                int gc  = n0 + col;
                float v0 = acc[mt][nt][2 * h + 0] * alpha;
                float v1 = acc[mt][nt][2 * h + 1] * alpha;
                if (bias)  { v0 += bias[gc]; v1 += bias[gc + 1]; }
                if (resid) {
                    const float* rr = resid + (size_t)r * N + gc;
                    v0 += rr[0]; v1 += rr[1];
                }
                float2* dst;
                if (c_attn) {
                    int bb = z >> 4, hh = z & 15;
                    dst = (float2*)(Cg + ((size_t)(bb * Sn + r)) * En + hh * 64 + gc);
                } else {
                    dst = (float2*)(Cg + (size_t)z * sCz + (size_t)r * N + gc);
                }
                *dst = make_float2(v0, v1);
            }
        }
    }
}

// ---------------- grouped expert GEMM (round-9) ----------------
__global__ void __launch_bounds__(256)
expert_mma(const float* __restrict__ ew, const float* __restrict__ eb)
{
    constexpr int A_ELE = 128 * 36;
    constexpr int B_ELE = 128 * 36;

    const int e   = blockIdx.z;
    const int cnt = g_cnt[e];
    const int m0  = blockIdx.y * 128;
    if (m0 >= cnt) return;
    const int n0  = blockIdx.x * 128;

    extern __shared__ float smf[];
    __shared__ int   rowflat[128];
    __shared__ float rowgate[128];

    const int tid = threadIdx.x;
    if (tid < 128) {
        int m = m0 + tid;
        int fl = (m < cnt) ? g_list[e * NTOK + m] : 0;
        rowflat[tid] = fl;
        rowgate[tid] = (m < cnt) ? g_gateflat[fl] : 0.f;
    }
    __syncthreads();

    const float* W = ew + (size_t)e * En * En;
    const int lane = tid & 31, warp = tid >> 5;
    const int grp  = lane >> 2, qd = lane & 3;
    const int m0w  = (warp / 4) * 64;
    const int n0w  = (warp % 4) * 32;

    int aS[4]; const float* aG[4];
    #pragma unroll
    for (int l = 0; l < 4; l++) {
        int idx = l * 256 + tid;
        int r = idx >> 3, c = (idx & 7) << 2;
        aS[l] = r * 36 + c;
        aG[l] = g_attn + (size_t)(rowflat[r] >> 1) * En + c;
    }
    int bS[4]; const float* bG[4];
    #pragma unroll
    for (int l = 0; l < 4; l++) {
        int idx = l * 256 + tid;
        int r = idx >> 3, c = (idx & 7) << 2;
        bS[l] = r * 36 + c;
        bG[l] = W + (size_t)(n0 + r) * En + c;
    }

    float acc[4][4][4];
    #pragma unroll
    for (int i = 0; i < 4; i++)
        #pragma unroll
        for (int j = 0; j < 4; j++)
            #pragma unroll
            for (int c = 0; c < 4; c++) acc[i][j][c] = 0.f;

    {
        float* As_ = smf;
        float* Bs_ = smf + 2 * A_ELE;
        #pragma unroll
        for (int l = 0; l < 4; l++) cpa16(As_ + aS[l], aG[l]);
        #pragma unroll
        for (int l = 0; l < 4; l++) cpa16(Bs_ + bS[l], bG[l]);
        CP_COMMIT();
    }

    const int NT = En >> 5;
    for (int t = 0; t < NT; t++) {
        if (t + 1 < NT) {
            int kt = (t + 1) << 5;
            int stg = (t + 1) & 1;
            float* As_ = smf + stg * A_ELE;
            float* Bs_ = smf + 2 * A_ELE + stg * B_ELE;
            #pragma unroll
            for (int l = 0; l < 4; l++) cpa16(As_ + aS[l], aG[l] + kt);
            #pragma unroll
            for (int l = 0; l < 4; l++) cpa16(Bs_ + bS[l], bG[l] + kt);
            CP_COMMIT();
            CP_WAIT1();
        } else {
            CP_WAIT0();
        }
        __syncthreads();

        const float* Asb = smf + (t & 1) * A_ELE;
        const float* Bsb = smf + 2 * A_ELE + (t & 1) * B_ELE;

        #pragma unroll
        for (int kk = 0; kk < 32; kk += 8) {
            const int c0 = kk + qd, c1 = c0 + 4;
            unsigned bf0[4], bf1[4];
            #pragma unroll
            for (int nt = 0; nt < 4; nt++) {
                const float* Bb = Bsb + (n0w + nt * 8 + grp) * 36;
                bf0[nt] = f2tf(Bb[c0]); bf1[nt] = f2tf(Bb[c1]);
            }
            #pragma unroll
            for (int mt = 0; mt < 4; mt++) {
                const float* Ar = Asb + (m0w + mt * 16 + grp) * 36;
                unsigned ah[4] = { f2tf(Ar[c0]), f2tf(Ar[8 * 36 + c0]),
                                   f2tf(Ar[c1]), f2tf(Ar[8 * 36 + c1]) };
                #pragma unroll
                for (int nt = 0; nt < 4; nt++) {
                    unsigned bh2[2] = { bf0[nt], bf1[nt] };
                    mma8(acc[mt][nt], ah, bh2);
                }
            }
        }
        __syncthreads();
    }

    #pragma unroll
    for (int mt = 0; mt < 4; mt++) {
        #pragma unroll
        for (int h = 0; h < 2; h++) {
            int mloc = m0w + mt * 16 + grp + h * 8;
            if (m0 + mloc >= cnt) continue;
            int fl = rowflat[mloc];
            float gtv = rowgate[mloc];
            #pragma unroll
            for (int nt = 0; nt < 4; nt++) {
                int gc = n0 + n0w + nt * 8 + 2 * qd;
                float v0 = gtv * (acc[mt][nt][2 * h + 0] + eb[(size_t)e * En + gc]);
                float v1 = gtv * (acc[mt][nt][2 * h + 1] + eb[(size_t)e * En + gc + 1]);
                *(float2*)(g_sel + (size_t)fl * En + gc) = make_float2(v0, v1);
            }
        }
    }
}

// ---------------- RoPE + transpose, writes pre-split q/k planes + plain v ----------------
__global__ void rope_transpose_kernel()
{
    int idx = blockIdx.x * blockDim.x + threadIdx.x;
    int i = idx & 31;
    int h = (idx >> 5) & 15;
    int s = (idx >> 9) & (Sn - 1);
    int b = idx >> 20;

    float inv = powf(10000.0f, -(float)(2 * i) / 64.0f);
    float sn, cs;
    sincosf((float)s * inv, &sn, &cs);

    size_t in_base  = ((size_t)(b * Sn + s)) * En + h * 64;
    size_t out_base = ((size_t)((b * Hn + h) * Sn + s)) * 64;
    const size_t lin_stride = (size_t)NTOK * En;

    {
        const float* src = g_lin + in_base;
        float x1 = src[i], x2 = src[i + 32];
        float r1 = x1 * cs - x2 * sn;
        float r2 = x2 * cs + x1 * sn;
        float h1, l1, h2, l2;
        split2(r1, h1, l1); split2(r2, h2, l2);
        g_qhi[out_base + i] = h1;      g_qlo[out_base + i] = l1;
        g_qhi[out_base + i + 32] = h2; g_qlo[out_base + i + 32] = l2;
    }
    {
        const float* src = g_lin + lin_stride + in_base;
        float x1 = src[i], x2 = src[i + 32];
        float r1 = x1 * cs - x2 * sn;
        float r2 = x2 * cs + x1 * sn;
        float h1, l1, h2, l2;
        split2(r1, h1, l1); split2(r2, h2, l2);
        g_khi[out_base + i] = h1;      g_klo[out_base + i] = l1;
        g_khi[out_base + i + 32] = h2; g_klo[out_base + i + 32] = l2;
    }
    {
        const float* src = g_lin + 2 * lin_stride + in_base;
        g_v[out_base + i]      = src[i];
        g_v[out_base + i + 32] = src[i + 32];
    }
}

// ---------------- V transpose: (bh, s, d) -> (bh, d, s) ----------------
__global__ void __launch_bounds__(256)
vtrans_kernel()
{
    __shared__ float t[32][33];
    const int bh = blockIdx.z;
    const int s0 = blockIdx.x * 32;
    const int d0 = blockIdx.y * 32;
    const float* src = g_v + (size_t)bh * Sn * Dn;
    float* dst = g_vt + (size_t)bh * Dn * Sn;
    const int tx = threadIdx.x & 31, ty = threadIdx.x >> 5;
    #pragma unroll
    for (int i = ty; i < 32; i += 8)
        t[i][tx] = src[(size_t)(s0 + i) * Dn + d0 + tx];
    __syncthreads();
    #pragma unroll
    for (int i = ty; i < 32; i += 8)
        dst[(size_t)(d0 + i) * Sn + s0 + tx] = t[tx][i];
}

// ---------------- row softmax (in place) ----------------
__global__ void __launch_bounds__(256)
softmax_kernel(float* __restrict__ probs)
{
    __shared__ float redm[8], reds[8];
    float4* p4 = (float4*)(probs + (size_t)blockIdx.x * Sn);
    const int tid = threadIdx.x;
    const int lane = tid & 31, warp = tid >> 5;

    float4 a = p4[tid], b = p4[tid + 256];
    float m = fmaxf(fmaxf(fmaxf(a.x, a.y), fmaxf(a.z, a.w)),
                    fmaxf(fmaxf(b.x, b.y), fmaxf(b.z, b.w)));
    #pragma unroll
    for (int o = 16; o; o >>= 1) m = fmaxf(m, __shfl_xor_sync(0xffffffffu, m, o));
    if (lane == 0) redm[warp] = m;
    __syncthreads();
    float mm = redm[0];
    #pragma unroll
    for (int w = 1; w < 8; w++) mm = fmaxf(mm, redm[w]);

    a.x = __expf(a.x - mm); a.y = __expf(a.y - mm);
    a.z = __expf(a.z - mm); a.w = __expf(a.w - mm);
    b.x = __expf(b.x - mm); b.y = __expf(b.y - mm);
    b.z = __expf(b.z - mm); b.w = __expf(b.w - mm);
    float s = (a.x + a.y + a.z + a.w) + (b.x + b.y + b.z + b.w);
    #pragma unroll
    for (int o = 16; o; o >>= 1) s += __shfl_xor_sync(0xffffffffu, s, o);
    if (lane == 0) reds[warp] = s;
    __syncthreads();
    float ss = 0.f;
    #pragma unroll
    for (int w = 0; w < 8; w++) ss += reds[w];
    float invs = 1.f / ss;

    a.x *= invs; a.y *= invs; a.z *= invs; a.w *= invs;
    b.x *= invs; b.y *= invs; b.z *= invs; b.w *= invs;
    p4[tid] = a; p4[tid + 256] = b;
}

// ---------------- gate + top-2 + dispatch ----------------
__global__ void __launch_bounds__(128)
gate_topk_kernel(const float* __restrict__ gw, const float* __restrict__ gb)
{
    const int warp = threadIdx.x >> 5;
    const int lane = threadIdx.x & 31;
    const int t = blockIdx.x * 4 + warp;

    float acc[NEXP];
    #pragma unroll
    for (int e = 0; e < NEXP; e++) acc[e] = 0.f;
    const float* xr = g_attn + (size_t)t * En;
    for (int i = lane; i < En; i += 32) {
        float xv = xr[i];
        #pragma unroll
        for (int e = 0; e < NEXP; e++) acc[e] += xv * gw[e * En + i];
    }
    #pragma unroll
    for (int e = 0; e < NEXP; e++) {
        #pragma unroll
        for (int off = 16; off; off >>= 1)
            acc[e] += __shfl_xor_sync(0xffffffffu, acc[e], off);
    }
    if (lane == 0) {
        float lg[NEXP];
        float m = -1e30f;
        #pragma unroll
        for (int e = 0; e < NEXP; e++) { lg[e] = acc[e] + gb[e]; m = fmaxf(m, lg[e]); }
        float sum = 0.f;
        #pragma unroll
        for (int e = 0; e < NEXP; e++) { lg[e] = __expf(lg[e] - m); sum += lg[e]; }
        float invs = 1.f / sum;
        int i0 = 0;
        #pragma unroll
        for (int e = 1; e < NEXP; e++) if (lg[e] > lg[i0]) i0 = e;
        int i1 = (i0 == 0) ? 1 : 0;
        #pragma unroll
        for (int e = 0; e < NEXP; e++) if (e != i0 && lg[e] > lg[i1]) i1 = e;

        int p0 = atomicAdd(&g_cnt[i0], 1);
        g_list[i0 * NTOK + p0] = t * 2;
        g_gateflat[t * 2] = lg[i0] * invs;
        int p1 = atomicAdd(&g_cnt[i1], 1);
        g_list[i1 * NTOK + p1] = t * 2 + 1;
        g_gateflat[t * 2 + 1] = lg[i1] * invs;
    }
}

// ---------------- combine expert slots ----------------
__global__ void combine_kernel()
{
    size_t i = (size_t)blockIdx.x * blockDim.x + threadIdx.x;
    size_t row = i >> 8;
    size_t col = i & 255;
    const float4* s4 = (const float4*)g_sel;
    float4 a = s4[(2 * row) * 256 + col];
    float4 b = s4[(2 * row + 1) * 256 + col];
    ((float4*)g_moe)[i] = make_float4(a.x + b.x, a.y + b.y, a.z + b.z, a.w + b.w);
}

// ---------------- launch ----------------
extern "C" void kernel_launch(void* const* d_in, const int* in_sizes, int n_in,
                              void* d_out, int out_size)
{
    const float* x     = (const float*)d_in[0];
    const float* q_w   = (const float*)d_in[1];
    const float* q_b   = (const float*)d_in[2];
    const float* k_w   = (const float*)d_in[3];
    const float* k_b   = (const float*)d_in[4];
    const float* v_w   = (const float*)d_in[5];
    const float* v_b   = (const float*)d_in[6];
    const float* gatew = (const float*)d_in[7];
    const float* gateb = (const float*)d_in[8];
    const float* ew    = (const float*)d_in[9];
    const float* eb    = (const float*)d_in[10];
    const float* ffn_w = (const float*)d_in[11];
    const float* ffn_b = (const float*)d_in[12];
    float* out = (float*)d_out;

    float *lin, *xhi, *xlo, *whi, *wlo, *qhi, *qlo, *khi, *klo, *vt, *probs, *attn, *moe;
    cudaGetSymbolAddress((void**)&lin,   g_lin);
    cudaGetSymbolAddress((void**)&xhi,   g_xhi);
    cudaGetSymbolAddress((void**)&xlo,   g_xlo);
    cudaGetSymbolAddress((void**)&whi,   g_whi);
    cudaGetSymbolAddress((void**)&wlo,   g_wlo);
    cudaGetSymbolAddress((void**)&qhi,   g_qhi);
    cudaGetSymbolAddress((void**)&qlo,   g_qlo);
    cudaGetSymbolAddress((void**)&khi,   g_khi);
    cudaGetSymbolAddress((void**)&klo,   g_klo);
    cudaGetSymbolAddress((void**)&vt,    g_vt);
    cudaGetSymbolAddress((void**)&probs, g_probs);
    cudaGetSymbolAddress((void**)&attn,  g_attn);
    cudaGetSymbolAddress((void**)&moe,   g_moe);

    const int SMPS  = (4 * 128 * 36 + 4 * 128 * 36) * 4;   // 147456 presplit BN=128
    const int SM128 = (2 * 128 * 36 + 2 * 128 * 36) * 4;   // 73728
    const int SM64  = (2 * 128 * 36 + 2 *  64 * 36) * 4;   // 55296
    cudaFuncSetAttribute(gemm_ps<128>,    cudaFuncAttributeMaxDynamicSharedMemorySize, SMPS);
    cudaFuncSetAttribute(mma_gemm< 64,1>, cudaFuncAttributeMaxDynamicSharedMemorySize, SM64);
    cudaFuncSetAttribute(mma_gemm<128,0>, cudaFuncAttributeMaxDynamicSharedMemorySize, SM128);
    cudaFuncSetAttribute(expert_mma,      cudaFuncAttributeMaxDynamicSharedMemorySize, SM128);

    zero_cnt_kernel<<<1, 32>>>();

    // pre-split x and qkv weights
    split_kernel<<<(NTOK * En / 4 + 255) / 256, 256>>>(x, xhi, xlo, NTOK * En / 4);
    split_kernel<<<(En * En / 4 + 255) / 256, 256>>>(q_w, whi, wlo, En * En / 4);
    split_kernel<<<(En * En / 4 + 255) / 256, 256>>>(k_w, whi + (size_t)En * En,
                                                     wlo + (size_t)En * En, En * En / 4);
    split_kernel<<<(En * En / 4 + 255) / 256, 256>>>(v_w, whi + (size_t)2 * En * En,
                                                     wlo + (size_t)2 * En * En, En * En / 4);

    // fused QKV projections (pre-split, no cvt), z picks weight plane + bias
    gemm_ps<128><<<dim3(En / 128, NTOK / 128, 3), 256, SMPS>>>(
        xhi, xlo, whi, wlo, q_b, k_b, v_b, lin,
        En, En, 0, (long long)En * En, (long long)NTOK * En, 1.f);

    rope_transpose_kernel<<<(Bn * Sn * Hn * 32) / 256, 256>>>();
    vtrans_kernel<<<dim3(Sn / 32, Dn / 32, BHn), 256>>>();

    // scores = Q K^T / 8 (pre-split planes)
    gemm_ps<128><<<dim3(Sn / 128, Sn / 128, BHn), 256, SMPS>>>(
        qhi, qlo, khi, klo, nullptr, nullptr, nullptr, probs,
        Sn, Dn, (long long)Sn * Dn, (long long)Sn * Dn, (long long)Sn * Sn, 0.125f);

    softmax_kernel<<<BHn * Sn, 256>>>(probs);

    // attn_out = P V (3xTF32 with in-kernel cvt), B = V^T, scatter into head layout
    mma_gemm<64,1><<<dim3(1, Sn / 128, BHn), 256, SM64>>>(
        probs, vt, nullptr, nullptr, attn,
        Sn, Dn, Sn, (long long)Sn * Sn, (long long)Dn * Sn, 0,
        1.f, 1);

    gate_topk_kernel<<<NTOK / 4, 128>>>(gatew, gateb);

    expert_mma<<<dim3(En / 128, NTOK / 128, NEXP), 256, SM128>>>(ew, eb);

    combine_kernel<<<(NTOK * (En / 4)) / 256, 256>>>();

    // final FFN + bias + residual (plain tf32)
    mma_gemm<128,0><<<dim3(En / 128, NTOK / 128, 1), 256, SM128>>>(
        moe, ffn_w, ffn_b, x, out,
        NTOK, En, En, 0, 0, 0, 1.f, 0);
}

// round 11
// speedup vs baseline: 1.7190x; 1.1261x over previous
#include <cuda_runtime.h>
#include <math.h>

#define Bn   2
#define Sn   2048
#define En   1024
#define Hn   16
#define Dn   64
#define NEXP 8
#define NTOK (Bn*Sn)          // 4096
#define BHn  (Bn*Hn)          // 32
#define PLANE ((size_t)BHn*Sn*Dn)
#define FSTR 68

// ---------------- scratch ----------------
__device__ float g_lin [(size_t)3*NTOK*En];
__device__ float g_xhi [(size_t)NTOK*En];
__device__ float g_xlo [(size_t)NTOK*En];
__device__ float g_whi [(size_t)3*En*En];
__device__ float g_wlo [(size_t)3*En*En];
__device__ float g_qhi [PLANE];
__device__ float g_qlo [PLANE];
__device__ float g_khi [PLANE];
__device__ float g_klo [PLANE];
__device__ float g_v   [PLANE];
__device__ float g_vthi[(size_t)BHn*Dn*Sn];        // V^T hi (bh, d, s)
__device__ float g_vtlo[(size_t)BHn*Dn*Sn];        // V^T lo
__device__ float g_attn[(size_t)NTOK*En];
__device__ float g_sel [(size_t)2*NTOK*En];
__device__ float g_moe [(size_t)NTOK*En];
__device__ float g_gateflat[2*NTOK];
__device__ int   g_list[NEXP*NTOK];
__device__ int   g_cnt [NEXP];

__global__ void zero_cnt_kernel() {
    if (threadIdx.x < NEXP) g_cnt[threadIdx.x] = 0;
}

// ---------------- tf32 helpers ----------------
__device__ __forceinline__ unsigned f2tf(float x) {
    unsigned r;
    asm("cvt.rna.tf32.f32 %0, %1;" : "=r"(r) : "f"(x));
    return r;
}
__device__ __forceinline__ void mma8(float* c, const unsigned* a, const unsigned* b) {
    asm volatile(
        "mma.sync.aligned.m16n8k8.row.col.f32.tf32.tf32.f32 "
        "{%0,%1,%2,%3}, {%4,%5,%6,%7}, {%8,%9}, {%0,%1,%2,%3};\n"
        : "+f"(c[0]), "+f"(c[1]), "+f"(c[2]), "+f"(c[3])
        : "r"(a[0]), "r"(a[1]), "r"(a[2]), "r"(a[3]), "r"(b[0]), "r"(b[1]));
}
__device__ __forceinline__ void cpa16(float* s, const float* g) {
    unsigned sa = (unsigned)__cvta_generic_to_shared(s);
    asm volatile("cp.async.cg.shared.global [%0], [%1], 16;" :: "r"(sa), "l"(g));
}
#define CP_COMMIT()  asm volatile("cp.async.commit_group;" ::: "memory")
#define CP_WAIT1()   asm volatile("cp.async.wait_group 1;" ::: "memory")
#define CP_WAIT0()   asm volatile("cp.async.wait_group 0;" ::: "memory")

__device__ __forceinline__ void split2(float v, float& hi, float& lo) {
    unsigned h = f2tf(v);
    hi = __uint_as_float(h);
    lo = __uint_as_float(f2tf(v - hi));
}

// ---------------- elementwise hi/lo split ----------------
__global__ void split_kernel(const float* __restrict__ in,
                             float* __restrict__ oh, float* __restrict__ ol, int n4)
{
    int i = blockIdx.x * blockDim.x + threadIdx.x;
    if (i >= n4) return;
    float4 v = ((const float4*)in)[i];
    float4 h, l;
    split2(v.x, h.x, l.x); split2(v.y, h.y, l.y);
    split2(v.z, h.z, l.z); split2(v.w, h.w, l.w);
    ((float4*)oh)[i] = h;
    ((float4*)ol)[i] = l;
}

// ---------------- pre-split tf32 GEMM (QKV) ----------------
template<int BN>
__global__ void __launch_bounds__(256)
gemm_ps(const float* __restrict__ Ah, const float* __restrict__ Al,
        const float* __restrict__ Bh, const float* __restrict__ Bl,
        const float* __restrict__ b0, const float* __restrict__ b1,
        const float* __restrict__ b2,
        float* __restrict__ Cg, int N, int K,
        long long sAz, long long sBz, long long sCz, float alpha)
{
    constexpr int WC    = (BN == 128) ? 4 : 2;
    constexpr int MT    = (BN == 128) ? 4 : 2;
    constexpr int BL    = (BN == 128) ? 4 : 2;
    constexpr int A_ELE = 128 * 36;
    constexpr int B_ELE = BN * 36;

    extern __shared__ float smf[];
    float* Ah_s = smf;
    float* Al_s = smf + 2 * A_ELE;
    float* Bh_s = smf + 4 * A_ELE;
    float* Bl_s = smf + 4 * A_ELE + 2 * B_ELE;

    const int z = blockIdx.z;
    const float* AH = Ah + (size_t)z * sAz;
    const float* AL = Al + (size_t)z * sAz;
    const float* BH = Bh + (size_t)z * sBz;
    const float* BLp= Bl + (size_t)z * sBz;
    const float* bias = (b1 == nullptr) ? b0 : (z == 0 ? b0 : (z == 1 ? b1 : b2));

    const int tid  = threadIdx.x;
    const int lane = tid & 31;
    const int warp = tid >> 5;
    const int grp  = lane >> 2;
    const int qd   = lane & 3;
    const int m0   = blockIdx.y * 128;
    const int n0   = blockIdx.x * BN;
    const int m0w  = (warp / WC) * (16 * MT);
    const int n0w  = (warp % WC) * 32;

    int aS[4]; long long aO[4];
    #pragma unroll
    for (int l = 0; l < 4; l++) {
        int idx = l * 256 + tid;
        int r = idx >> 3, c = (idx & 7) << 2;
        aS[l] = r * 36 + c;
        aO[l] = (long long)(m0 + r) * K + c;
    }
    int bS[BL]; long long bO[BL];
    #pragma unroll
    for (int l = 0; l < BL; l++) {
        int idx = l * 256 + tid;
        int r = idx >> 3, c = (idx & 7) << 2;
        bS[l] = r * 36 + c;
        bO[l] = (long long)(n0 + r) * K + c;
    }

    float acc[MT][4][4];
    #pragma unroll
    for (int i = 0; i < MT; i++)
        #pragma unroll
        for (int j = 0; j < 4; j++)
            #pragma unroll
            for (int c = 0; c < 4; c++) acc[i][j][c] = 0.f;

    {
        #pragma unroll
        for (int l = 0; l < 4; l++) {
            cpa16(Ah_s + aS[l], AH + aO[l]);
            cpa16(Al_s + aS[l], AL + aO[l]);
        }
        #pragma unroll
        for (int l = 0; l < BL; l++) {
            cpa16(Bh_s + bS[l], BH + bO[l]);
            cpa16(Bl_s + bS[l], BLp + bO[l]);
        }
        CP_COMMIT();
    }

    const int NT = K >> 5;
    for (int t = 0; t < NT; t++) {
        if (t + 1 < NT) {
            int kt = (t + 1) << 5;
            int stg = (t + 1) & 1;
            #pragma unroll
            for (int l = 0; l < 4; l++) {
                cpa16(Ah_s + stg * A_ELE + aS[l], AH + aO[l] + kt);
                cpa16(Al_s + stg * A_ELE + aS[l], AL + aO[l] + kt);
            }
            #pragma unroll
            for (int l = 0; l < BL; l++) {
                cpa16(Bh_s + stg * B_ELE + bS[l], BH + bO[l] + kt);
                cpa16(Bl_s + stg * B_ELE + bS[l], BLp + bO[l] + kt);
            }
            CP_COMMIT();
            CP_WAIT1();
        } else {
            CP_WAIT0();
        }
        __syncthreads();

        const float* AH_b = Ah_s + (t & 1) * A_ELE;
        const float* AL_b = Al_s + (t & 1) * A_ELE;
        const float* BH_b = Bh_s + (t & 1) * B_ELE;
        const float* BL_b = Bl_s + (t & 1) * B_ELE;

        #pragma unroll
        for (int kk = 0; kk < 32; kk += 8) {
            const int c0 = kk + qd, c1 = c0 + 4;
            unsigned bh[4][2], bl[4][2];
            #pragma unroll
            for (int nt = 0; nt < 4; nt++) {
                int roff = (n0w + nt * 8 + grp) * 36;
                bh[nt][0] = __float_as_uint(BH_b[roff + c0]);
                bh[nt][1] = __float_as_uint(BH_b[roff + c1]);
                bl[nt][0] = __float_as_uint(BL_b[roff + c0]);
                bl[nt][1] = __float_as_uint(BL_b[roff + c1]);
            }
            #pragma unroll
            for (int mt = 0; mt < MT; mt++) {
                int roff = (m0w + mt * 16 + grp) * 36;
                unsigned ah[4] = { __float_as_uint(AH_b[roff + c0]),
                                   __float_as_uint(AH_b[roff + 8 * 36 + c0]),
                                   __float_as_uint(AH_b[roff + c1]),
                                   __float_as_uint(AH_b[roff + 8 * 36 + c1]) };
                unsigned al[4] = { __float_as_uint(AL_b[roff + c0]),
                                   __float_as_uint(AL_b[roff + 8 * 36 + c0]),
                                   __float_as_uint(AL_b[roff + c1]),
                                   __float_as_uint(AL_b[roff + 8 * 36 + c1]) };
                #pragma unroll
                for (int nt = 0; nt < 4; nt++) {
                    mma8(acc[mt][nt], ah, bh[nt]);
                    mma8(acc[mt][nt], al, bh[nt]);
                    mma8(acc[mt][nt], ah, bl[nt]);
                }
            }
        }
        __syncthreads();
    }

    #pragma unroll
    for (int mt = 0; mt < MT; mt++) {
        #pragma unroll
        for (int h = 0; h < 2; h++) {
            int r = m0 + m0w + mt * 16 + grp + h * 8;
            #pragma unroll
            for (int nt = 0; nt < 4; nt++) {
                int gc = n0 + n0w + nt * 8 + 2 * qd;
                float v0 = acc[mt][nt][2 * h + 0] * alpha;
                float v1 = acc[mt][nt][2 * h + 1] * alpha;
                if (bias) { v0 += bias[gc]; v1 += bias[gc + 1]; }
                *(float2*)(Cg + (size_t)z * sCz + (size_t)r * N + gc) =
                    make_float2(v0, v1);
            }
        }
    }
}

// ---------------- fused flash attention (3xTF32 S and PV) ----------------
// grid (Sn/128, BHn), 256 threads. Q/K from pre-split planes, V^T pre-split.
__global__ void __launch_bounds__(256)
flash_attn()
{
    extern __shared__ float sm[];
    float* qh = sm;                         // 128*FSTR
    float* ql = qh + 128 * FSTR;
    float* kh = ql + 128 * FSTR;            // 64*FSTR
    float* kl = kh + 64 * FSTR;
    float* vh = kl + 64 * FSTR;             // V^T tile: row d, col key
    float* vl = vh + 64 * FSTR;
    float* ph = vl + 64 * FSTR;             // 128*FSTR
    float* pl = ph + 128 * FSTR;
    __shared__ float redmx[2 * 128];
    __shared__ float redsm[2 * 128];

    const int bh  = blockIdx.y;
    const int q0  = blockIdx.x * 128;
    const int tid = threadIdx.x;
    const int lane = tid & 31, warp = tid >> 5;
    const int grp  = lane >> 2, qd = lane & 3;
    const int mw   = (warp >> 1) * 32;
    const int nw   = (warp & 1) * 32;

    const size_t sbase = (size_t)bh * Sn * Dn;   // (bh, s, d)
    const size_t vbase = (size_t)bh * Dn * Sn;   // (bh, d, s)

    // Q load (group 1)
    #pragma unroll
    for (int l = 0; l < 8; l++) {
        int idx = l * 256 + tid;
        int r = idx >> 4, c = (idx & 15) << 2;
        cpa16(qh + r * FSTR + c, g_qhi + sbase + (size_t)(q0 + r) * 64 + c);
        cpa16(ql + r * FSTR + c, g_qlo + sbase + (size_t)(q0 + r) * 64 + c);
    }
    CP_COMMIT();

    // K0 (group 2), V0 (group 3)
    int kvr[4], kvc[4];
    #pragma unroll
    for (int l = 0; l < 4; l++) {
        int idx = l * 256 + tid;
        kvr[l] = idx >> 4; kvc[l] = (idx & 15) << 2;
    }
    #pragma unroll
    for (int l = 0; l < 4; l++) {
        cpa16(kh + kvr[l] * FSTR + kvc[l], g_khi + sbase + (size_t)kvr[l] * 64 + kvc[l]);
        cpa16(kl + kvr[l] * FSTR + kvc[l], g_klo + sbase + (size_t)kvr[l] * 64 + kvc[l]);
    }
    CP_COMMIT();
    #pragma unroll
    for (int l = 0; l < 4; l++) {
        cpa16(vh + kvr[l] * FSTR + kvc[l], g_vthi + vbase + (size_t)kvr[l] * Sn + kvc[l]);
        cpa16(vl + kvr[l] * FSTR + kvc[l], g_vtlo + vbase + (size_t)kvr[l] * Sn + kvc[l]);
    }
    CP_COMMIT();

    float acco[2][4][4];
    #pragma unroll
    for (int i = 0; i < 2; i++)
        #pragma unroll
        for (int j = 0; j < 4; j++)
            #pragma unroll
            for (int c = 0; c < 4; c++) acco[i][j][c] = 0.f;
    float mI[2][2] = { {-1e30f, -1e30f}, {-1e30f, -1e30f} };
    float lI[2][2] = { {0.f, 0.f}, {0.f, 0.f} };

    for (int kt = 0; kt < Sn; kt += 64) {
        CP_WAIT1();            // K tile ready (V of this tile may be pending)
        __syncthreads();

        // ---- S = Q K^T (3xTF32) ----
        float accs[2][4][4];
        #pragma unroll
        for (int i = 0; i < 2; i++)
            #pragma unroll
            for (int j = 0; j < 4; j++)
                #pragma unroll
                for (int c = 0; c < 4; c++) accs[i][j][c] = 0.f;

        #pragma unroll
        for (int kk = 0; kk < 64; kk += 8) {
            const int c0 = kk + qd, c1 = c0 + 4;
            unsigned bhf[4][2], blf[4][2];
            #pragma unroll
            for (int nt = 0; nt < 4; nt++) {
                int ro = (nw + nt * 8 + grp) * FSTR;
                bhf[nt][0] = __float_as_uint(kh[ro + c0]);
                bhf[nt][1] = __float_as_uint(kh[ro + c1]);
                blf[nt][0] = __float_as_uint(kl[ro + c0]);
                blf[nt][1] = __float_as_uint(kl[ro + c1]);
            }
            #pragma unroll
            for (int mt = 0; mt < 2; mt++) {
                int ro = (mw + mt * 16 + grp) * FSTR;
                unsigned ah[4] = { __float_as_uint(qh[ro + c0]),
                                   __float_as_uint(qh[ro + 8 * FSTR + c0]),
                                   __float_as_uint(qh[ro + c1]),
                                   __float_as_uint(qh[ro + 8 * FSTR + c1]) };
                unsigned al[4] = { __float_as_uint(ql[ro + c0]),
                                   __float_as_uint(ql[ro + 8 * FSTR + c0]),
                                   __float_as_uint(ql[ro + c1]),
                                   __float_as_uint(ql[ro + 8 * FSTR + c1]) };
                #pragma unroll
                for (int nt = 0; nt < 4; nt++) {
                    mma8(accs[mt][nt], ah, bhf[nt]);
                    mma8(accs[mt][nt], al, bhf[nt]);
                    mma8(accs[mt][nt], ah, blf[nt]);
                }
            }
        }

        // scale + tile row-max (warp-local 32 cols)
        #pragma unroll
        for (int mt = 0; mt < 2; mt++)
            #pragma unroll
            for (int nt = 0; nt < 4; nt++)
                #pragma unroll
                for (int c = 0; c < 4; c++) accs[mt][nt][c] *= 0.125f;

        #pragma unroll
        for (int mt = 0; mt < 2; mt++)
            #pragma unroll
            for (int h = 0; h < 2; h++) {
                float tm = -1e30f;
                #pragma unroll
                for (int nt = 0; nt < 4; nt++)
                    tm = fmaxf(tm, fmaxf(accs[mt][nt][2 * h], accs[mt][nt][2 * h + 1]));
                tm = fmaxf(tm, __shfl_xor_sync(0xffffffffu, tm, 1));
                tm = fmaxf(tm, __shfl_xor_sync(0xffffffffu, tm, 2));
                if (qd == 0)
                    redmx[(warp & 1) * 128 + mw + mt * 16 + grp + h * 8] = tm;
            }
        __syncthreads();       // sync1: maxes ready, kh/kl free

        // prefetch next K (empty commit on last tile keeps group order)
        if (kt + 64 < Sn) {
            #pragma unroll
            for (int l = 0; l < 4; l++) {
                cpa16(kh + kvr[l] * FSTR + kvc[l],
                      g_khi + sbase + (size_t)(kt + 64 + kvr[l]) * 64 + kvc[l]);
                cpa16(kl + kvr[l] * FSTR + kvc[l],
                      g_klo + sbase + (size_t)(kt + 64 + kvr[l]) * 64 + kvc[l]);
            }
        }
        CP_COMMIT();

        // p = exp(s - m_new), write P hi/lo, partial sums
        float cfac[2][2];
        #pragma unroll
        for (int mt = 0; mt < 2; mt++)
            #pragma unroll
            for (int h = 0; h < 2; h++) {
                int row = mw + mt * 16 + grp + h * 8;
                float mx = fmaxf(redmx[row], redmx[128 + row]);
                float mnew = fmaxf(mI[mt][h], mx);
                cfac[mt][h] = __expf(mI[mt][h] - mnew);
                mI[mt][h] = mnew;
                float sum = 0.f;
                #pragma unroll
                for (int nt = 0; nt < 4; nt++) {
                    float p0 = __expf(accs[mt][nt][2 * h]     - mnew);
                    float p1 = __expf(accs[mt][nt][2 * h + 1] - mnew);
                    sum += p0 + p1;
                    float h0, l0, h1, l1;
                    split2(p0, h0, l0); split2(p1, h1, l1);
                    int off = row * FSTR + nw + nt * 8 + 2 * qd;
                    *(float2*)(ph + off) = make_float2(h0, h1);
                    *(float2*)(pl + off) = make_float2(l0, l1);
                }
                sum += __shfl_xor_sync(0xffffffffu, sum, 1);
                sum += __shfl_xor_sync(0xffffffffu, sum, 2);
                if (qd == 0) redsm[(warp & 1) * 128 + row] = sum;
            }

        CP_WAIT1();            // V tile ready (next-K pending)
        __syncthreads();       // sync2: P, sums, V all visible

        // stats update + rescale O
        #pragma unroll
        for (int mt = 0; mt < 2; mt++)
            #pragma unroll
            for (int h = 0; h < 2; h++) {
                int row = mw + mt * 16 + grp + h * 8;
                float s2 = redsm[row] + redsm[128 + row];
                lI[mt][h] = lI[mt][h] * cfac[mt][h] + s2;
                #pragma unroll
                for (int nt = 0; nt < 4; nt++) {
                    acco[mt][nt][2 * h]     *= cfac[mt][h];
                    acco[mt][nt][2 * h + 1] *= cfac[mt][h];
                }
            }

        // ---- O += P V (3xTF32): A=P rows q, B=V^T rows d ----
        #pragma unroll
        for (int kk = 0; kk < 64; kk += 8) {
            const int c0 = kk + qd, c1 = c0 + 4;
            unsigned bhf[4][2], blf[4][2];
            #pragma unroll
            for (int nt = 0; nt < 4; nt++) {
                int ro = (nw + nt * 8 + grp) * FSTR;
                bhf[nt][0] = __float_as_uint(vh[ro + c0]);
                bhf[nt][1] = __float_as_uint(vh[ro + c1]);
                blf[nt][0] = __float_as_uint(vl[ro + c0]);
                blf[nt][1] = __float_as_uint(vl[ro + c1]);
            }
            #pragma unroll
            for (int mt = 0; mt < 2; mt++) {
                int ro = (mw + mt * 16 + grp) * FSTR;
                unsigned ah[4] = { __float_as_uint(ph[ro + c0]),
                                   __float_as_uint(ph[ro + 8 * FSTR + c0]),
                                   __float_as_uint(ph[ro + c1]),
                                   __float_as_uint(ph[ro + 8 * FSTR + c1]) };
                unsigned al[4] = { __float_as_uint(pl[ro + c0]),
                                   __float_as_uint(pl[ro + 8 * FSTR + c0]),
                                   __float_as_uint(pl[ro + c1]),
                                   __float_as_uint(pl[ro + 8 * FSTR + c1]) };
                #pragma unroll
                for (int nt = 0; nt < 4; nt++) {
                    mma8(acco[mt][nt], ah, bhf[nt]);
                    mma8(acco[mt][nt], al, bhf[nt]);
                    mma8(acco[mt][nt], ah, blf[nt]);
                }
            }
        }
        __syncthreads();       // sync3: vh/vl + red arrays free

        // prefetch next V
        if (kt + 64 < Sn) {
            #pragma unroll
            for (int l = 0; l < 4; l++) {
                cpa16(vh + kvr[l] * FSTR + kvc[l],
                      g_vthi + vbase + (size_t)kvr[l] * Sn + kt + 64 + kvc[l]);
                cpa16(vl + kvr[l] * FSTR + kvc[l],
                      g_vtlo + vbase + (size_t)kvr[l] * Sn + kt + 64 + kvc[l]);
            }
        }
        CP_COMMIT();
    }

    // epilogue: normalize, scatter to (tok, E) head layout
    const int bb = bh >> 4, hh = bh & 15;
    #pragma unroll
    for (int mt = 0; mt < 2; mt++)
        #pragma unroll
        for (int h = 0; h < 2; h++) {
            int row = mw + mt * 16 + grp + h * 8;
            float inv = 1.f / lI[mt][h];
            #pragma unroll
            for (int nt = 0; nt < 4; nt++) {
                int dcol = nw + nt * 8 + 2 * qd;
                *(float2*)(g_attn + ((size_t)(bb * Sn + q0 + row)) * En + hh * 64 + dcol) =
                    make_float2(acco[mt][nt][2 * h] * inv, acco[mt][nt][2 * h + 1] * inv);
            }
        }
}

// ---------------- FFN GEMM (plain tf32, cp.async) ----------------
template<int BN, int SPLIT>
__global__ void __launch_bounds__(256)
mma_gemm(const float* __restrict__ Ag, const float* __restrict__ Bg,
         const float* __restrict__ bias, const float* __restrict__ resid,
         float* __restrict__ Cg, int M, int N, int K,
         long long sAz, long long sBz, long long sCz,
         float alpha, int c_attn)
{
    constexpr int WC    = (BN == 128) ? 4 : 2;
    constexpr int MT    = (BN == 128) ? 4 : 2;
    constexpr int BL    = (BN == 128) ? 4 : 2;
    constexpr int A_ELE = 128 * 36;
    constexpr int B_ELE = BN * 36;

    extern __shared__ float smf[];

    const int z = blockIdx.z;
    const float* A = Ag + (size_t)z * sAz;
    const float* B = Bg + (size_t)z * sBz;

    const int tid  = threadIdx.x;
    const int lane = tid & 31;
    const int warp = tid >> 5;
    const int grp  = lane >> 2;
    const int qd   = lane & 3;
    const int m0   = blockIdx.y * 128;
    const int n0   = blockIdx.x * BN;
    const int m0w  = (warp / WC) * (16 * MT);
    const int n0w  = (warp % WC) * 32;

    int aS[4]; const float* aG[4];
    #pragma unroll
    for (int l = 0; l < 4; l++) {
        int idx = l * 256 + tid;
        int r = idx >> 3, c = (idx & 7) << 2;
        aS[l] = r * 36 + c;
        aG[l] = A + (size_t)(m0 + r) * K + c;
    }
    int bS[BL]; const float* bG[BL];
    #pragma unroll
    for (int l = 0; l < BL; l++) {
        int idx = l * 256 + tid;
        int r = idx >> 3, c = (idx & 7) << 2;
        bS[l] = r * 36 + c;
        bG[l] = B + (size_t)(n0 + r) * K + c;
    }

    float acc[MT][4][4];
    #pragma unroll
    for (int i = 0; i < MT; i++)
        #pragma unroll
        for (int j = 0; j < 4; j++)
            #pragma unroll
            for (int c = 0; c < 4; c++) acc[i][j][c] = 0.f;

    {
        float* As_ = smf;
        float* Bs_ = smf + 2 * A_ELE;
        #pragma unroll
        for (int l = 0; l < 4;  l++) cpa16(As_ + aS[l], aG[l]);
        #pragma unroll
        for (int l = 0; l < BL; l++) cpa16(Bs_ + bS[l], bG[l]);
        CP_COMMIT();
    }

    const int NT = K >> 5;
    for (int t = 0; t < NT; t++) {
        if (t + 1 < NT) {
            int kt = (t + 1) << 5;
            int stg = (t + 1) & 1;
            float* As_ = smf + stg * A_ELE;
            float* Bs_ = smf + 2 * A_ELE + stg * B_ELE;
            #pragma unroll
            for (int l = 0; l < 4;  l++) cpa16(As_ + aS[l], aG[l] + kt);
            #pragma unroll
            for (int l = 0; l < BL; l++) cpa16(Bs_ + bS[l], bG[l] + kt);
            CP_COMMIT();
            CP_WAIT1();
        } else {
            CP_WAIT0();
        }
        __syncthreads();

        const float* Asb = smf + (t & 1) * A_ELE;
        const float* Bsb = smf + 2 * A_ELE + (t & 1) * B_ELE;

        #pragma unroll
        for (int kk = 0; kk < 32; kk += 8) {
            const int c0 = kk + qd, c1 = c0 + 4;
            unsigned bh[4][2], bl[4][2];
            #pragma unroll
            for (int nt = 0; nt < 4; nt++) {
                const float* Bb = Bsb + (n0w + nt * 8 + grp) * 36;
                float v0 = Bb[c0], v1 = Bb[c1];
                bh[nt][0] = f2tf(v0); bh[nt][1] = f2tf(v1);
                if (SPLIT) {
                    bl[nt][0] = f2tf(v0 - __uint_as_float(bh[nt][0]));
                    bl[nt][1] = f2tf(v1 - __uint_as_float(bh[nt][1]));
                }
            }
            #pragma unroll
            for (int mt = 0; mt < MT; mt++) {
                const float* Ar = Asb + (m0w + mt * 16 + grp) * 36;
                float x0 = Ar[c0],       x1 = Ar[8 * 36 + c0];
                float x2 = Ar[c1],       x3 = Ar[8 * 36 + c1];
                unsigned ah[4] = { f2tf(x0), f2tf(x1), f2tf(x2), f2tf(x3) };
                unsigned al[4];
                if (SPLIT) {
                    al[0] = f2tf(x0 - __uint_as_float(ah[0]));
                    al[1] = f2tf(x1 - __uint_as_float(ah[1]));
                    al[2] = f2tf(x2 - __uint_as_float(ah[2]));
                    al[3] = f2tf(x3 - __uint_as_float(ah[3]));
                }
                #pragma unroll
                for (int nt = 0; nt < 4; nt++) {
                    mma8(acc[mt][nt], ah, bh[nt]);
                    if (SPLIT) {
                        mma8(acc[mt][nt], al, bh[nt]);
                        mma8(acc[mt][nt], ah, bl[nt]);
                    }
                }
            }
        }
        __syncthreads();
    }

    #pragma unroll
    for (int mt = 0; mt < MT; mt++) {
        #pragma unroll
        for (int h = 0; h < 2; h++) {
            int r = m0 + m0w + mt * 16 + grp + h * 8;
            #pragma unroll
            for (int nt = 0; nt < 4; nt++) {
                int col = n0w + nt * 8 + 2 * qd;
                int gc  = n0 + col;
                float v0 = acc[mt][nt][2 * h + 0] * alpha;
                float v1 = acc[mt][nt][2 * h + 1] * alpha;
                if (bias)  { v0 += bias[gc]; v1 += bias[gc + 1]; }
                if (resid) {
                    const float* rr = resid + (size_t)r * N + gc;
                    v0 += rr[0]; v1 += rr[1];
                }
                *(float2*)(Cg + (size_t)z * sCz + (size_t)r * N + gc) =
                    make_float2(v0, v1);
            }
        }
    }
}

// ---------------- grouped expert GEMM ----------------
__global__ void __launch_bounds__(256)
expert_mma(const float* __restrict__ ew, const float* __restrict__ eb)
{
    constexpr int A_ELE = 128 * 36;
    constexpr int B_ELE = 128 * 36;

    const int e   = blockIdx.z;
    const int cnt = g_cnt[e];
    const int m0  = blockIdx.y * 128;
    if (m0 >= cnt) return;
    const int n0  = blockIdx.x * 128;

    extern __shared__ float smf[];
    __shared__ int   rowflat[128];
    __shared__ float rowgate[128];

    const int tid = threadIdx.x;
    if (tid < 128) {
        int m = m0 + tid;
        int fl = (m < cnt) ? g_list[e * NTOK + m] : 0;
        rowflat[tid] = fl;
        rowgate[tid] = (m < cnt) ? g_gateflat[fl] : 0.f;
    }
    __syncthreads();

    const float* W = ew + (size_t)e * En * En;
    const int lane = tid & 31, warp = tid >> 5;
    const int grp  = lane >> 2, qd = lane & 3;
    const int m0w  = (warp / 4) * 64;
    const int n0w  = (warp % 4) * 32;

    int aS[4]; const float* aG[4];
    #pragma unroll
    for (int l = 0; l < 4; l++) {
        int idx = l * 256 + tid;
        int r = idx >> 3, c = (idx & 7) << 2;
        aS[l] = r * 36 + c;
        aG[l] = g_attn + (size_t)(rowflat[r] >> 1) * En + c;
    }
    int bS[4]; const float* bG[4];
    #pragma unroll
    for (int l = 0; l < 4; l++) {
        int idx = l * 256 + tid;
        int r = idx >> 3, c = (idx & 7) << 2;
        bS[l] = r * 36 + c;
        bG[l] = W + (size_t)(n0 + r) * En + c;
    }

    float acc[4][4][4];
    #pragma unroll
    for (int i = 0; i < 4; i++)
        #pragma unroll
        for (int j = 0; j < 4; j++)
            #pragma unroll
            for (int c = 0; c < 4; c++) acc[i][j][c] = 0.f;

    {
        float* As_ = smf;
        float* Bs_ = smf + 2 * A_ELE;
        #pragma unroll
        for (int l = 0; l < 4; l++) cpa16(As_ + aS[l], aG[l]);
        #pragma unroll
        for (int l = 0; l < 4; l++) cpa16(Bs_ + bS[l], bG[l]);
        CP_COMMIT();
    }

    const int NT = En >> 5;
    for (int t = 0; t < NT; t++) {
        if (t + 1 < NT) {
            int kt = (t + 1) << 5;
            int stg = (t + 1) & 1;
            float* As_ = smf + stg * A_ELE;
            float* Bs_ = smf + 2 * A_ELE + stg * B_ELE;
            #pragma unroll
            for (int l = 0; l < 4; l++) cpa16(As_ + aS[l], aG[l] + kt);
            #pragma unroll
            for (int l = 0; l < 4; l++) cpa16(Bs_ + bS[l], bG[l] + kt);
            CP_COMMIT();
            CP_WAIT1();
        } else {
            CP_WAIT0();
        }
        __syncthreads();

        const float* Asb = smf + (t & 1) * A_ELE;
        const float* Bsb = smf + 2 * A_ELE + (t & 1) * B_ELE;

        #pragma unroll
        for (int kk = 0; kk < 32; kk += 8) {
            const int c0 = kk + qd, c1 = c0 + 4;
            unsigned bf0[4], bf1[4];
            #pragma unroll
            for (int nt = 0; nt < 4; nt++) {
                const float* Bb = Bsb + (n0w + nt * 8 + grp) * 36;
                bf0[nt] = f2tf(Bb[c0]); bf1[nt] = f2tf(Bb[c1]);
            }
            #pragma unroll
            for (int mt = 0; mt < 4; mt++) {
                const float* Ar = Asb + (m0w + mt * 16 + grp) * 36;
                unsigned ah[4] = { f2tf(Ar[c0]), f2tf(Ar[8 * 36 + c0]),
                                   f2tf(Ar[c1]), f2tf(Ar[8 * 36 + c1]) };
                #pragma unroll
                for (int nt = 0; nt < 4; nt++) {
                    unsigned bh2[2] = { bf0[nt], bf1[nt] };
                    mma8(acc[mt][nt], ah, bh2);
                }
            }
        }
        __syncthreads();
    }

    #pragma unroll
    for (int mt = 0; mt < 4; mt++) {
        #pragma unroll
        for (int h = 0; h < 2; h++) {
            int mloc = m0w + mt * 16 + grp + h * 8;
            if (m0 + mloc >= cnt) continue;
            int fl = rowflat[mloc];
            float gtv = rowgate[mloc];
            #pragma unroll
            for (int nt = 0; nt < 4; nt++) {
                int gc = n0 + n0w + nt * 8 + 2 * qd;
                float v0 = gtv * (acc[mt][nt][2 * h + 0] + eb[(size_t)e * En + gc]);
                float v1 = gtv * (acc[mt][nt][2 * h + 1] + eb[(size_t)e * En + gc + 1]);
                *(float2*)(g_sel + (size_t)fl * En + gc) = make_float2(v0, v1);
            }
        }
    }
}

// ---------------- RoPE + transpose, pre-split q/k planes + plain v ----------------
__global__ void rope_transpose_kernel()
{
    int idx = blockIdx.x * blockDim.x + threadIdx.x;
    int i = idx & 31;
    int h = (idx >> 5) & 15;
    int s = (idx >> 9) & (Sn - 1);
    int b = idx >> 20;

    float inv = powf(10000.0f, -(float)(2 * i) / 64.0f);
    float sn, cs;
    sincosf((float)s * inv, &sn, &cs);

    size_t in_base  = ((size_t)(b * Sn + s)) * En + h * 64;
    size_t out_base = ((size_t)((b * Hn + h) * Sn + s)) * 64;
    const size_t lin_stride = (size_t)NTOK * En;

    {
        const float* src = g_lin + in_base;
        float x1 = src[i], x2 = src[i + 32];
        float r1 = x1 * cs - x2 * sn;
        float r2 = x2 * cs + x1 * sn;
        float h1, l1, h2, l2;
        split2(r1, h1, l1); split2(r2, h2, l2);
        g_qhi[out_base + i] = h1;      g_qlo[out_base + i] = l1;
        g_qhi[out_base + i + 32] = h2; g_qlo[out_base + i + 32] = l2;
    }
    {
        const float* src = g_lin + lin_stride + in_base;
        float x1 = src[i], x2 = src[i + 32];
        float r1 = x1 * cs - x2 * sn;
        float r2 = x2 * cs + x1 * sn;
        float h1, l1, h2, l2;
        split2(r1, h1, l1); split2(r2, h2, l2);
        g_khi[out_base + i] = h1;      g_klo[out_base + i] = l1;
        g_khi[out_base + i + 32] = h2; g_klo[out_base + i + 32] = l2;
    }
    {
        const float* src = g_lin + 2 * lin_stride + in_base;
        g_v[out_base + i]      = src[i];
        g_v[out_base + i + 32] = src[i + 32];
    }
}

// ---------------- V transpose + split: (bh, s, d) -> hi/lo (bh, d, s) ----------------
__global__ void __launch_bounds__(256)
vtrans_kernel()
{
    __shared__ float t[32][33];
    const int bh = blockIdx.z;
    const int s0 = blockIdx.x * 32;
    const int d0 = blockIdx.y * 32;
    const float* src = g_v + (size_t)bh * Sn * Dn;
    const size_t dstb = (size_t)bh * Dn * Sn;
    const int tx = threadIdx.x & 31, ty = threadIdx.x >> 5;
    #pragma unroll
    for (int i = ty; i < 32; i += 8)
        t[i][tx] = src[(size_t)(s0 + i) * Dn + d0 + tx];
    __syncthreads();
    #pragma unroll
    for (int i = ty; i < 32; i += 8) {
        float v = t[tx][i];
        float h, l;
        split2(v, h, l);
        g_vthi[dstb + (size_t)(d0 + i) * Sn + s0 + tx] = h;
        g_vtlo[dstb + (size_t)(d0 + i) * Sn + s0 + tx] = l;
    }
}

// ---------------- gate + top-2 + dispatch ----------------
__global__ void __launch_bounds__(128)
gate_topk_kernel(const float* __restrict__ gw, const float* __restrict__ gb)
{
    const int warp = threadIdx.x >> 5;
    const int lane = threadIdx.x & 31;
    const int t = blockIdx.x * 4 + warp;

    float acc[NEXP];
    #pragma unroll
    for (int e = 0; e < NEXP; e++) acc[e] = 0.f;
    const float* xr = g_attn + (size_t)t * En;
    for (int i = lane; i < En; i += 32) {
        float xv = xr[i];
        #pragma unroll
        for (int e = 0; e < NEXP; e++) acc[e] += xv * gw[e * En + i];
    }
    #pragma unroll
    for (int e = 0; e < NEXP; e++) {
        #pragma unroll
        for (int off = 16; off; off >>= 1)
            acc[e] += __shfl_xor_sync(0xffffffffu, acc[e], off);
    }
    if (lane == 0) {
        float lg[NEXP];
        float m = -1e30f;
        #pragma unroll
        for (int e = 0; e < NEXP; e++) { lg[e] = acc[e] + gb[e]; m = fmaxf(m, lg[e]); }
        float sum = 0.f;
        #pragma unroll
        for (int e = 0; e < NEXP; e++) { lg[e] = __expf(lg[e] - m); sum += lg[e]; }
        float invs = 1.f / sum;
        int i0 = 0;
        #pragma unroll
        for (int e = 1; e < NEXP; e++) if (lg[e] > lg[i0]) i0 = e;
        int i1 = (i0 == 0) ? 1 : 0;
        #pragma unroll
        for (int e = 0; e < NEXP; e++) if (e != i0 && lg[e] > lg[i1]) i1 = e;

        int p0 = atomicAdd(&g_cnt[i0], 1);
        g_list[i0 * NTOK + p0] = t * 2;
        g_gateflat[t * 2] = lg[i0] * invs;
        int p1 = atomicAdd(&g_cnt[i1], 1);
        g_list[i1 * NTOK + p1] = t * 2 + 1;
        g_gateflat[t * 2 + 1] = lg[i1] * invs;
    }
}

// ---------------- combine expert slots ----------------
__global__ void combine_kernel()
{
    size_t i = (size_t)blockIdx.x * blockDim.x + threadIdx.x;
    size_t row = i >> 8;
    size_t col = i & 255;
    const float4* s4 = (const float4*)g_sel;
    float4 a = s4[(2 * row) * 256 + col];
    float4 b = s4[(2 * row + 1) * 256 + col];
    ((float4*)g_moe)[i] = make_float4(a.x + b.x, a.y + b.y, a.z + b.z, a.w + b.w);
}

// ---------------- launch ----------------
extern "C" void kernel_launch(void* const* d_in, const int* in_sizes, int n_in,
                              void* d_out, int out_size)
{
    const float* x     = (const float*)d_in[0];
    const float* q_w   = (const float*)d_in[1];
    const float* q_b   = (const float*)d_in[2];
    const float* k_w   = (const float*)d_in[3];
    const float* k_b   = (const float*)d_in[4];
    const float* v_w   = (const float*)d_in[5];
    const float* v_b   = (const float*)d_in[6];
    const float* gatew = (const float*)d_in[7];
    const float* gateb = (const float*)d_in[8];
    const float* ew    = (const float*)d_in[9];
    const float* eb    = (const float*)d_in[10];
    const float* ffn_w = (const float*)d_in[11];
    const float* ffn_b = (const float*)d_in[12];
    float* out = (float*)d_out;

    float *lin, *xhi, *xlo, *whi, *wlo, *moe;
    cudaGetSymbolAddress((void**)&lin,   g_lin);
    cudaGetSymbolAddress((void**)&xhi,   g_xhi);
    cudaGetSymbolAddress((void**)&xlo,   g_xlo);
    cudaGetSymbolAddress((void**)&whi,   g_whi);
    cudaGetSymbolAddress((void**)&wlo,   g_wlo);
    cudaGetSymbolAddress((void**)&moe,   g_moe);

    const int SMPS  = (4 * 128 * 36 + 4 * 128 * 36) * 4;   // 147456
    const int SM128 = (2 * 128 * 36 + 2 * 128 * 36) * 4;   // 73728
    const int SMFL  = (2 * 128 * FSTR + 2 * 64 * FSTR + 2 * 64 * FSTR
                       + 2 * 128 * FSTR) * 4;              // 208896
    cudaFuncSetAttribute(gemm_ps<128>,    cudaFuncAttributeMaxDynamicSharedMemorySize, SMPS);
    cudaFuncSetAttribute(flash_attn,      cudaFuncAttributeMaxDynamicSharedMemorySize, SMFL);
    cudaFuncSetAttribute(mma_gemm<128,0>, cudaFuncAttributeMaxDynamicSharedMemorySize, SM128);
    cudaFuncSetAttribute(expert_mma,      cudaFuncAttributeMaxDynamicSharedMemorySize, SM128);

    zero_cnt_kernel<<<1, 32>>>();

    // pre-split x and qkv weights
    split_kernel<<<(NTOK * En / 4 + 255) / 256, 256>>>(x, xhi, xlo, NTOK * En / 4);
    split_kernel<<<(En * En / 4 + 255) / 256, 256>>>(q_w, whi, wlo, En * En / 4);
    split_kernel<<<(En * En / 4 + 255) / 256, 256>>>(k_w, whi + (size_t)En * En,
                                                     wlo + (size_t)En * En, En * En / 4);
    split_kernel<<<(En * En / 4 + 255) / 256, 256>>>(v_w, whi + (size_t)2 * En * En,
                                                     wlo + (size_t)2 * En * En, En * En / 4);

    // fused QKV projections (pre-split planes)
    gemm_ps<128><<<dim3(En / 128, NTOK / 128, 3), 256, SMPS>>>(
        xhi, xlo, whi, wlo, q_b, k_b, v_b, lin,
        En, En, 0, (long long)En * En, (long long)NTOK * En, 1.f);

    rope_transpose_kernel<<<(Bn * Sn * Hn * 32) / 256, 256>>>();
    vtrans_kernel<<<dim3(Sn / 32, Dn / 32, BHn), 256>>>();

    // fused attention: scores + softmax + PV in one kernel
    flash_attn<<<dim3(Sn / 128, BHn), 256, SMFL>>>();

    gate_topk_kernel<<<NTOK / 4, 128>>>(gatew, gateb);

    expert_mma<<<dim3(En / 128, NTOK / 128, NEXP), 256, SM128>>>(ew, eb);

    combine_kernel<<<(NTOK * (En / 4)) / 256, 256>>>();

    // final FFN + bias + residual (plain tf32)
    mma_gemm<128,0><<<dim3(En / 128, NTOK / 128, 1), 256, SM128>>>(
        moe, ffn_w, ffn_b, x, out,
        NTOK, En, En, 0, 0, 0, 1.f, 0);
}

// round 12
// speedup vs baseline: 1.7206x; 1.0010x over previous
#include <cuda_runtime.h>
#include <math.h>

#define Bn   2
#define Sn   2048
#define En   1024
#define Hn   16
#define Dn   64
#define NEXP 8
#define NTOK (Bn*Sn)          // 4096
#define BHn  (Bn*Hn)          // 32
#define PLANE ((size_t)BHn*Sn*Dn)
#define FSTR 68

// ---------------- scratch ----------------
__device__ float g_lin [(size_t)3*NTOK*En];
__device__ float g_xhi [(size_t)NTOK*En];
__device__ float g_xlo [(size_t)NTOK*En];
__device__ float g_whi [(size_t)3*En*En];
__device__ float g_wlo [(size_t)3*En*En];
__device__ float g_qhi [PLANE];
__device__ float g_qlo [PLANE];
__device__ float g_khi [PLANE];
__device__ float g_klo [PLANE];
__device__ float g_v   [PLANE];
__device__ float g_vthi[(size_t)BHn*Dn*Sn];        // V^T hi (bh, d, s)
__device__ float g_vtlo[(size_t)BHn*Dn*Sn];        // V^T lo
__device__ float g_attn[(size_t)NTOK*En];
__device__ float g_sel [(size_t)2*NTOK*En];
__device__ float g_moe [(size_t)NTOK*En];
__device__ float g_gateflat[2*NTOK];
__device__ int   g_list[NEXP*NTOK];
__device__ int   g_cnt [NEXP];

__global__ void zero_cnt_kernel() {
    if (threadIdx.x < NEXP) g_cnt[threadIdx.x] = 0;
}

// ---------------- tf32 helpers ----------------
__device__ __forceinline__ unsigned f2tf(float x) {
    unsigned r;
    asm("cvt.rna.tf32.f32 %0, %1;" : "=r"(r) : "f"(x));
    return r;
}
__device__ __forceinline__ void mma8(float* c, const unsigned* a, const unsigned* b) {
    asm volatile(
        "mma.sync.aligned.m16n8k8.row.col.f32.tf32.tf32.f32 "
        "{%0,%1,%2,%3}, {%4,%5,%6,%7}, {%8,%9}, {%0,%1,%2,%3};\n"
        : "+f"(c[0]), "+f"(c[1]), "+f"(c[2]), "+f"(c[3])
        : "r"(a[0]), "r"(a[1]), "r"(a[2]), "r"(a[3]), "r"(b[0]), "r"(b[1]));
}
__device__ __forceinline__ void cpa16(float* s, const float* g) {
    unsigned sa = (unsigned)__cvta_generic_to_shared(s);
    asm volatile("cp.async.cg.shared.global [%0], [%1], 16;" :: "r"(sa), "l"(g));
}
#define CP_COMMIT()  asm volatile("cp.async.commit_group;" ::: "memory")
#define CP_WAIT1()   asm volatile("cp.async.wait_group 1;" ::: "memory")
#define CP_WAIT0()   asm volatile("cp.async.wait_group 0;" ::: "memory")

__device__ __forceinline__ void split2(float v, float& hi, float& lo) {
    unsigned h = f2tf(v);
    hi = __uint_as_float(h);
    lo = __uint_as_float(f2tf(v - hi));
}

// ---------------- elementwise hi/lo split ----------------
__global__ void split_kernel(const float* __restrict__ in,
                             float* __restrict__ oh, float* __restrict__ ol, int n4)
{
    int i = blockIdx.x * blockDim.x + threadIdx.x;
    if (i >= n4) return;
    float4 v = ((const float4*)in)[i];
    float4 h, l;
    split2(v.x, h.x, l.x); split2(v.y, h.y, l.y);
    split2(v.z, h.z, l.z); split2(v.w, h.w, l.w);
    ((float4*)oh)[i] = h;
    ((float4*)ol)[i] = l;
}

// ---------------- pre-split tf32 GEMM (QKV) ----------------
template<int BN>
__global__ void __launch_bounds__(256)
gemm_ps(const float* __restrict__ Ah, const float* __restrict__ Al,
        const float* __restrict__ Bh, const float* __restrict__ Bl,
        const float* __restrict__ b0, const float* __restrict__ b1,
        const float* __restrict__ b2,
        float* __restrict__ Cg, int N, int K,
        long long sAz, long long sBz, long long sCz, float alpha)
{
    constexpr int WC    = (BN == 128) ? 4 : 2;
    constexpr int MT    = (BN == 128) ? 4 : 2;
    constexpr int BL    = (BN == 128) ? 4 : 2;
    constexpr int A_ELE = 128 * 36;
    constexpr int B_ELE = BN * 36;

    extern __shared__ float smf[];
    float* Ah_s = smf;
    float* Al_s = smf + 2 * A_ELE;
    float* Bh_s = smf + 4 * A_ELE;
    float* Bl_s = smf + 4 * A_ELE + 2 * B_ELE;

    const int z = blockIdx.z;
    const float* AH = Ah + (size_t)z * sAz;
    const float* AL = Al + (size_t)z * sAz;
    const float* BH = Bh + (size_t)z * sBz;
    const float* BLp= Bl + (size_t)z * sBz;
    const float* bias = (b1 == nullptr) ? b0 : (z == 0 ? b0 : (z == 1 ? b1 : b2));

    const int tid  = threadIdx.x;
    const int lane = tid & 31;
    const int warp = tid >> 5;
    const int grp  = lane >> 2;
    const int qd   = lane & 3;
    const int m0   = blockIdx.y * 128;
    const int n0   = blockIdx.x * BN;
    const int m0w  = (warp / WC) * (16 * MT);
    const int n0w  = (warp % WC) * 32;

    int aS[4]; long long aO[4];
    #pragma unroll
    for (int l = 0; l < 4; l++) {
        int idx = l * 256 + tid;
        int r = idx >> 3, c = (idx & 7) << 2;
        aS[l] = r * 36 + c;
        aO[l] = (long long)(m0 + r) * K + c;
    }
    int bS[BL]; long long bO[BL];
    #pragma unroll
    for (int l = 0; l < BL; l++) {
        int idx = l * 256 + tid;
        int r = idx >> 3, c = (idx & 7) << 2;
        bS[l] = r * 36 + c;
        bO[l] = (long long)(n0 + r) * K + c;
    }

    float acc[MT][4][4];
    #pragma unroll
    for (int i = 0; i < MT; i++)
        #pragma unroll
        for (int j = 0; j < 4; j++)
            #pragma unroll
            for (int c = 0; c < 4; c++) acc[i][j][c] = 0.f;

    {
        #pragma unroll
        for (int l = 0; l < 4; l++) {
            cpa16(Ah_s + aS[l], AH + aO[l]);
            cpa16(Al_s + aS[l], AL + aO[l]);
        }
        #pragma unroll
        for (int l = 0; l < BL; l++) {
            cpa16(Bh_s + bS[l], BH + bO[l]);
            cpa16(Bl_s + bS[l], BLp + bO[l]);
        }
        CP_COMMIT();
    }

    const int NT = K >> 5;
    for (int t = 0; t < NT; t++) {
        if (t + 1 < NT) {
            int kt = (t + 1) << 5;
            int stg = (t + 1) & 1;
            #pragma unroll
            for (int l = 0; l < 4; l++) {
                cpa16(Ah_s + stg * A_ELE + aS[l], AH + aO[l] + kt);
                cpa16(Al_s + stg * A_ELE + aS[l], AL + aO[l] + kt);
            }
            #pragma unroll
            for (int l = 0; l < BL; l++) {
                cpa16(Bh_s + stg * B_ELE + bS[l], BH + bO[l] + kt);
                cpa16(Bl_s + stg * B_ELE + bS[l], BLp + bO[l] + kt);
            }
            CP_COMMIT();
            CP_WAIT1();
        } else {
            CP_WAIT0();
        }
        __syncthreads();

        const float* AH_b = Ah_s + (t & 1) * A_ELE;
        const float* AL_b = Al_s + (t & 1) * A_ELE;
        const float* BH_b = Bh_s + (t & 1) * B_ELE;
        const float* BL_b = Bl_s + (t & 1) * B_ELE;

        #pragma unroll
        for (int kk = 0; kk < 32; kk += 8) {
            const int c0 = kk + qd, c1 = c0 + 4;
            unsigned bh[4][2], bl[4][2];
            #pragma unroll
            for (int nt = 0; nt < 4; nt++) {
                int roff = (n0w + nt * 8 + grp) * 36;
                bh[nt][0] = __float_as_uint(BH_b[roff + c0]);
                bh[nt][1] = __float_as_uint(BH_b[roff + c1]);
                bl[nt][0] = __float_as_uint(BL_b[roff + c0]);
                bl[nt][1] = __float_as_uint(BL_b[roff + c1]);
            }
            #pragma unroll
            for (int mt = 0; mt < MT; mt++) {
                int roff = (m0w + mt * 16 + grp) * 36;
                unsigned ah[4] = { __float_as_uint(AH_b[roff + c0]),
                                   __float_as_uint(AH_b[roff + 8 * 36 + c0]),
                                   __float_as_uint(AH_b[roff + c1]),
                                   __float_as_uint(AH_b[roff + 8 * 36 + c1]) };
                unsigned al[4] = { __float_as_uint(AL_b[roff + c0]),
                                   __float_as_uint(AL_b[roff + 8 * 36 + c0]),
                                   __float_as_uint(AL_b[roff + c1]),
                                   __float_as_uint(AL_b[roff + 8 * 36 + c1]) };
                #pragma unroll
                for (int nt = 0; nt < 4; nt++) {
                    mma8(acc[mt][nt], ah, bh[nt]);
                    mma8(acc[mt][nt], al, bh[nt]);
                    mma8(acc[mt][nt], ah, bl[nt]);
                }
            }
        }
        __syncthreads();
    }

    #pragma unroll
    for (int mt = 0; mt < MT; mt++) {
        #pragma unroll
        for (int h = 0; h < 2; h++) {
            int r = m0 + m0w + mt * 16 + grp + h * 8;
            #pragma unroll
            for (int nt = 0; nt < 4; nt++) {
                int gc = n0 + n0w + nt * 8 + 2 * qd;
                float v0 = acc[mt][nt][2 * h + 0] * alpha;
                float v1 = acc[mt][nt][2 * h + 1] * alpha;
                if (bias) { v0 += bias[gc]; v1 += bias[gc + 1]; }
                *(float2*)(Cg + (size_t)z * sCz + (size_t)r * N + gc) =
                    make_float2(v0, v1);
            }
        }
    }
}

// ---------------- fused flash attention (3xTF32 S and PV) ----------------
// grid (Sn/128, BHn), 256 threads. Q/K from pre-split planes, V^T pre-split.
__global__ void __launch_bounds__(256)
flash_attn()
{
    extern __shared__ float sm[];
    float* qh = sm;                         // 128*FSTR
    float* ql = qh + 128 * FSTR;
    float* kh = ql + 128 * FSTR;            // 64*FSTR
    float* kl = kh + 64 * FSTR;
    float* vh = kl + 64 * FSTR;             // V^T tile: row d, col key
    float* vl = vh + 64 * FSTR;
    float* ph = vl + 64 * FSTR;             // 128*FSTR
    float* pl = ph + 128 * FSTR;
    __shared__ float redmx[2 * 128];
    __shared__ float redsm[2 * 128];

    const int bh  = blockIdx.y;
    const int q0  = blockIdx.x * 128;
    const int tid = threadIdx.x;
    const int lane = tid & 31, warp = tid >> 5;
    const int grp  = lane >> 2, qd = lane & 3;
    const int mw   = (warp >> 1) * 32;
    const int nw   = (warp & 1) * 32;

    const size_t sbase = (size_t)bh * Sn * Dn;   // (bh, s, d)
    const size_t vbase = (size_t)bh * Dn * Sn;   // (bh, d, s)

    // Q load (group 1)
    #pragma unroll
    for (int l = 0; l < 8; l++) {
        int idx = l * 256 + tid;
        int r = idx >> 4, c = (idx & 15) << 2;
        cpa16(qh + r * FSTR + c, g_qhi + sbase + (size_t)(q0 + r) * 64 + c);
        cpa16(ql + r * FSTR + c, g_qlo + sbase + (size_t)(q0 + r) * 64 + c);
    }
    CP_COMMIT();

    // K0 (group 2), V0 (group 3)
    int kvr[4], kvc[4];
    #pragma unroll
    for (int l = 0; l < 4; l++) {
        int idx = l * 256 + tid;
        kvr[l] = idx >> 4; kvc[l] = (idx & 15) << 2;
    }
    #pragma unroll
    for (int l = 0; l < 4; l++) {
        cpa16(kh + kvr[l] * FSTR + kvc[l], g_khi + sbase + (size_t)kvr[l] * 64 + kvc[l]);
        cpa16(kl + kvr[l] * FSTR + kvc[l], g_klo + sbase + (size_t)kvr[l] * 64 + kvc[l]);
    }
    CP_COMMIT();
    #pragma unroll
    for (int l = 0; l < 4; l++) {
        cpa16(vh + kvr[l] * FSTR + kvc[l], g_vthi + vbase + (size_t)kvr[l] * Sn + kvc[l]);
        cpa16(vl + kvr[l] * FSTR + kvc[l], g_vtlo + vbase + (size_t)kvr[l] * Sn + kvc[l]);
    }
    CP_COMMIT();

    float acco[2][4][4];
    #pragma unroll
    for (int i = 0; i < 2; i++)
        #pragma unroll
        for (int j = 0; j < 4; j++)
            #pragma unroll
            for (int c = 0; c < 4; c++) acco[i][j][c] = 0.f;
    float mI[2][2] = { {-1e30f, -1e30f}, {-1e30f, -1e30f} };
    float lI[2][2] = { {0.f, 0.f}, {0.f, 0.f} };

    for (int kt = 0; kt < Sn; kt += 64) {
        CP_WAIT1();            // K tile ready (V of this tile may be pending)
        __syncthreads();

        // ---- S = Q K^T (3xTF32) ----
        float accs[2][4][4];
        #pragma unroll
        for (int i = 0; i < 2; i++)
            #pragma unroll
            for (int j = 0; j < 4; j++)
                #pragma unroll
                for (int c = 0; c < 4; c++) accs[i][j][c] = 0.f;

        #pragma unroll
        for (int kk = 0; kk < 64; kk += 8) {
            const int c0 = kk + qd, c1 = c0 + 4;
            unsigned bhf[4][2], blf[4][2];
            #pragma unroll
            for (int nt = 0; nt < 4; nt++) {
                int ro = (nw + nt * 8 + grp) * FSTR;
                bhf[nt][0] = __float_as_uint(kh[ro + c0]);
                bhf[nt][1] = __float_as_uint(kh[ro + c1]);
                blf[nt][0] = __float_as_uint(kl[ro + c0]);
                blf[nt][1] = __float_as_uint(kl[ro + c1]);
            }
            #pragma unroll
            for (int mt = 0; mt < 2; mt++) {
                int ro = (mw + mt * 16 + grp) * FSTR;
                unsigned ah[4] = { __float_as_uint(qh[ro + c0]),
                                   __float_as_uint(qh[ro + 8 * FSTR + c0]),
                                   __float_as_uint(qh[ro + c1]),
                                   __float_as_uint(qh[ro + 8 * FSTR + c1]) };
                unsigned al[4] = { __float_as_uint(ql[ro + c0]),
                                   __float_as_uint(ql[ro + 8 * FSTR + c0]),
                                   __float_as_uint(ql[ro + c1]),
                                   __float_as_uint(ql[ro + 8 * FSTR + c1]) };
                #pragma unroll
                for (int nt = 0; nt < 4; nt++) {
                    mma8(accs[mt][nt], ah, bhf[nt]);
                    mma8(accs[mt][nt], al, bhf[nt]);
                    mma8(accs[mt][nt], ah, blf[nt]);
                }
            }
        }

        // scale + tile row-max (warp-local 32 cols)
        #pragma unroll
        for (int mt = 0; mt < 2; mt++)
            #pragma unroll
            for (int nt = 0; nt < 4; nt++)
                #pragma unroll
                for (int c = 0; c < 4; c++) accs[mt][nt][c] *= 0.125f;

        #pragma unroll
        for (int mt = 0; mt < 2; mt++)
            #pragma unroll
            for (int h = 0; h < 2; h++) {
                float tm = -1e30f;
                #pragma unroll
                for (int nt = 0; nt < 4; nt++)
                    tm = fmaxf(tm, fmaxf(accs[mt][nt][2 * h], accs[mt][nt][2 * h + 1]));
                tm = fmaxf(tm, __shfl_xor_sync(0xffffffffu, tm, 1));
                tm = fmaxf(tm, __shfl_xor_sync(0xffffffffu, tm, 2));
                if (qd == 0)
                    redmx[(warp & 1) * 128 + mw + mt * 16 + grp + h * 8] = tm;
            }
        __syncthreads();       // sync1: maxes ready, kh/kl free

        // prefetch next K (empty commit on last tile keeps group order)
        if (kt + 64 < Sn) {
            #pragma unroll
            for (int l = 0; l < 4; l++) {
                cpa16(kh + kvr[l] * FSTR + kvc[l],
                      g_khi + sbase + (size_t)(kt + 64 + kvr[l]) * 64 + kvc[l]);
                cpa16(kl + kvr[l] * FSTR + kvc[l],
                      g_klo + sbase + (size_t)(kt + 64 + kvr[l]) * 64 + kvc[l]);
            }
        }
        CP_COMMIT();

        // p = exp(s - m_new), write P hi/lo, partial sums
        float cfac[2][2];
        #pragma unroll
        for (int mt = 0; mt < 2; mt++)
            #pragma unroll
            for (int h = 0; h < 2; h++) {
                int row = mw + mt * 16 + grp + h * 8;
                float mx = fmaxf(redmx[row], redmx[128 + row]);
                float mnew = fmaxf(mI[mt][h], mx);
                cfac[mt][h] = __expf(mI[mt][h] - mnew);
                mI[mt][h] = mnew;
                float sum = 0.f;
                #pragma unroll
                for (int nt = 0; nt < 4; nt++) {
                    float p0 = __expf(accs[mt][nt][2 * h]     - mnew);
                    float p1 = __expf(accs[mt][nt][2 * h + 1] - mnew);
                    sum += p0 + p1;
                    float h0, l0, h1, l1;
                    split2(p0, h0, l0); split2(p1, h1, l1);
                    int off = row * FSTR + nw + nt * 8 + 2 * qd;
                    *(float2*)(ph + off) = make_float2(h0, h1);
                    *(float2*)(pl + off) = make_float2(l0, l1);
                }
                sum += __shfl_xor_sync(0xffffffffu, sum, 1);
                sum += __shfl_xor_sync(0xffffffffu, sum, 2);
                if (qd == 0) redsm[(warp & 1) * 128 + row] = sum;
            }

        CP_WAIT1();            // V tile ready (next-K pending)
        __syncthreads();       // sync2: P, sums, V all visible

        // stats update + rescale O
        #pragma unroll
        for (int mt = 0; mt < 2; mt++)
            #pragma unroll
            for (int h = 0; h < 2; h++) {
                int row = mw + mt * 16 + grp + h * 8;
                float s2 = redsm[row] + redsm[128 + row];
                lI[mt][h] = lI[mt][h] * cfac[mt][h] + s2;
                #pragma unroll
                for (int nt = 0; nt < 4; nt++) {
                    acco[mt][nt][2 * h]     *= cfac[mt][h];
                    acco[mt][nt][2 * h + 1] *= cfac[mt][h];
                }
            }

        // ---- O += P V (3xTF32): A=P rows q, B=V^T rows d ----
        #pragma unroll
        for (int kk = 0; kk < 64; kk += 8) {
            const int c0 = kk + qd, c1 = c0 + 4;
            unsigned bhf[4][2], blf[4][2];
            #pragma unroll
            for (int nt = 0; nt < 4; nt++) {
                int ro = (nw + nt * 8 + grp) * FSTR;
                bhf[nt][0] = __float_as_uint(vh[ro + c0]);
                bhf[nt][1] = __float_as_uint(vh[ro + c1]);
                blf[nt][0] = __float_as_uint(vl[ro + c0]);
                blf[nt][1] = __float_as_uint(vl[ro + c1]);
            }
            #pragma unroll
            for (int mt = 0; mt < 2; mt++) {
                int ro = (mw + mt * 16 + grp) * FSTR;
                unsigned ah[4] = { __float_as_uint(ph[ro + c0]),
                                   __float_as_uint(ph[ro + 8 * FSTR + c0]),
                                   __float_as_uint(ph[ro + c1]),
                                   __float_as_uint(ph[ro + 8 * FSTR + c1]) };
                unsigned al[4] = { __float_as_uint(pl[ro + c0]),
                                   __float_as_uint(pl[ro + 8 * FSTR + c0]),
                                   __float_as_uint(pl[ro + c1]),
                                   __float_as_uint(pl[ro + 8 * FSTR + c1]) };
                #pragma unroll
                for (int nt = 0; nt < 4; nt++) {
                    mma8(acco[mt][nt], ah, bhf[nt]);
                    mma8(acco[mt][nt], al, bhf[nt]);
                    mma8(acco[mt][nt], ah, blf[nt]);
                }
            }
        }
        __syncthreads();       // sync3: vh/vl + red arrays free

        // prefetch next V
        if (kt + 64 < Sn) {
            #pragma unroll
            for (int l = 0; l < 4; l++) {
                cpa16(vh + kvr[l] * FSTR + kvc[l],
                      g_vthi + vbase + (size_t)kvr[l] * Sn + kt + 64 + kvc[l]);
                cpa16(vl + kvr[l] * FSTR + kvc[l],
                      g_vtlo + vbase + (size_t)kvr[l] * Sn + kt + 64 + kvc[l]);
            }
        }
        CP_COMMIT();
    }

    // epilogue: normalize, scatter to (tok, E) head layout
    const int bb = bh >> 4, hh = bh & 15;
    #pragma unroll
    for (int mt = 0; mt < 2; mt++)
        #pragma unroll
        for (int h = 0; h < 2; h++) {
            int row = mw + mt * 16 + grp + h * 8;
            float inv = 1.f / lI[mt][h];
            #pragma unroll
            for (int nt = 0; nt < 4; nt++) {
                int dcol = nw + nt * 8 + 2 * qd;
                *(float2*)(g_attn + ((size_t)(bb * Sn + q0 + row)) * En + hh * 64 + dcol) =
                    make_float2(acco[mt][nt][2 * h] * inv, acco[mt][nt][2 * h + 1] * inv);
            }
        }
}

// ---------------- FFN GEMM (plain tf32, cp.async) ----------------
template<int BN, int SPLIT>
__global__ void __launch_bounds__(256)
mma_gemm(const float* __restrict__ Ag, const float* __restrict__ Bg,
         const float* __restrict__ bias, const float* __restrict__ resid,
         float* __restrict__ Cg, int M, int N, int K,
         long long sAz, long long sBz, long long sCz,
         float alpha, int c_attn)
{
    constexpr int WC    = (BN == 128) ? 4 : 2;
    constexpr int MT    = (BN == 128) ? 4 : 2;
    constexpr int BL    = (BN == 128) ? 4 : 2;
    constexpr int A_ELE = 128 * 36;
    constexpr int B_ELE = BN * 36;

    extern __shared__ float smf[];

    const int z = blockIdx.z;
    const float* A = Ag + (size_t)z * sAz;
    const float* B = Bg + (size_t)z * sBz;

    const int tid  = threadIdx.x;
    const int lane = tid & 31;
    const int warp = tid >> 5;
    const int grp  = lane >> 2;
    const int qd   = lane & 3;
    const int m0   = blockIdx.y * 128;
    const int n0   = blockIdx.x * BN;
    const int m0w  = (warp / WC) * (16 * MT);
    const int n0w  = (warp % WC) * 32;

    int aS[4]; const float* aG[4];
    #pragma unroll
    for (int l = 0; l < 4; l++) {
        int idx = l * 256 + tid;
        int r = idx >> 3, c = (idx & 7) << 2;
        aS[l] = r * 36 + c;
        aG[l] = A + (size_t)(m0 + r) * K + c;
    }
    int bS[BL]; const float* bG[BL];
    #pragma unroll
    for (int l = 0; l < BL; l++) {
        int idx = l * 256 + tid;
        int r = idx >> 3, c = (idx & 7) << 2;
        bS[l] = r * 36 + c;
        bG[l] = B + (size_t)(n0 + r) * K + c;
    }

    float acc[MT][4][4];
    #pragma unroll
    for (int i = 0; i < MT; i++)
        #pragma unroll
        for (int j = 0; j < 4; j++)
            #pragma unroll
            for (int c = 0; c < 4; c++) acc[i][j][c] = 0.f;

    {
        float* As_ = smf;
        float* Bs_ = smf + 2 * A_ELE;
        #pragma unroll
        for (int l = 0; l < 4;  l++) cpa16(As_ + aS[l], aG[l]);
        #pragma unroll
        for (int l = 0; l < BL; l++) cpa16(Bs_ + bS[l], bG[l]);
        CP_COMMIT();
    }

    const int NT = K >> 5;
    for (int t = 0; t < NT; t++) {
        if (t + 1 < NT) {
            int kt = (t + 1) << 5;
            int stg = (t + 1) & 1;
            float* As_ = smf + stg * A_ELE;
            float* Bs_ = smf + 2 * A_ELE + stg * B_ELE;
            #pragma unroll
            for (int l = 0; l < 4;  l++) cpa16(As_ + aS[l], aG[l] + kt);
            #pragma unroll
            for (int l = 0; l < BL; l++) cpa16(Bs_ + bS[l], bG[l] + kt);
            CP_COMMIT();
            CP_WAIT1();
        } else {
            CP_WAIT0();
        }
        __syncthreads();

        const float* Asb = smf + (t & 1) * A_ELE;
        const float* Bsb = smf + 2 * A_ELE + (t & 1) * B_ELE;

        #pragma unroll
        for (int kk = 0; kk < 32; kk += 8) {
            const int c0 = kk + qd, c1 = c0 + 4;
            unsigned bh[4][2], bl[4][2];
            #pragma unroll
            for (int nt = 0; nt < 4; nt++) {
                const float* Bb = Bsb + (n0w + nt * 8 + grp) * 36;
                float v0 = Bb[c0], v1 = Bb[c1];
                bh[nt][0] = f2tf(v0); bh[nt][1] = f2tf(v1);
                if (SPLIT) {
                    bl[nt][0] = f2tf(v0 - __uint_as_float(bh[nt][0]));
                    bl[nt][1] = f2tf(v1 - __uint_as_float(bh[nt][1]));
                }
            }
            #pragma unroll
            for (int mt = 0; mt < MT; mt++) {
                const float* Ar = Asb + (m0w + mt * 16 + grp) * 36;
                float x0 = Ar[c0],       x1 = Ar[8 * 36 + c0];
                float x2 = Ar[c1],       x3 = Ar[8 * 36 + c1];
                unsigned ah[4] = { f2tf(x0), f2tf(x1), f2tf(x2), f2tf(x3) };
                unsigned al[4];
                if (SPLIT) {
                    al[0] = f2tf(x0 - __uint_as_float(ah[0]));
                    al[1] = f2tf(x1 - __uint_as_float(ah[1]));
                    al[2] = f2tf(x2 - __uint_as_float(ah[2]));
                    al[3] = f2tf(x3 - __uint_as_float(ah[3]));
                }
                #pragma unroll
                for (int nt = 0; nt < 4; nt++) {
                    mma8(acc[mt][nt], ah, bh[nt]);
                    if (SPLIT) {
                        mma8(acc[mt][nt], al, bh[nt]);
                        mma8(acc[mt][nt], ah, bl[nt]);
                    }
                }
            }
        }
        __syncthreads();
    }

    #pragma unroll
    for (int mt = 0; mt < MT; mt++) {
        #pragma unroll
        for (int h = 0; h < 2; h++) {
            int r = m0 + m0w + mt * 16 + grp + h * 8;
            #pragma unroll
            for (int nt = 0; nt < 4; nt++) {
                int col = n0w + nt * 8 + 2 * qd;
                int gc  = n0 + col;
                float v0 = acc[mt][nt][2 * h + 0] * alpha;
                float v1 = acc[mt][nt][2 * h + 1] * alpha;
                if (bias)  { v0 += bias[gc]; v1 += bias[gc + 1]; }
                if (resid) {
                    const float* rr = resid + (size_t)r * N + gc;
                    v0 += rr[0]; v1 += rr[1];
                }
                *(float2*)(Cg + (size_t)z * sCz + (size_t)r * N + gc) =
                    make_float2(v0, v1);
            }
        }
    }
}

// ---------------- grouped expert GEMM ----------------
__global__ void __launch_bounds__(256)
expert_mma(const float* __restrict__ ew, const float* __restrict__ eb)
{
    constexpr int A_ELE = 128 * 36;
    constexpr int B_ELE = 128 * 36;

    const int e   = blockIdx.z;
    const int cnt = g_cnt[e];
    const int m0  = blockIdx.y * 128;
    if (m0 >= cnt) return;
    const int n0  = blockIdx.x * 128;

    extern __shared__ float smf[];
    __shared__ int   rowflat[128];
    __shared__ float rowgate[128];

    const int tid = threadIdx.x;
    if (tid < 128) {
        int m = m0 + tid;
        int fl = (m < cnt) ? g_list[e * NTOK + m] : 0;
        rowflat[tid] = fl;
        rowgate[tid] = (m < cnt) ? g_gateflat[fl] : 0.f;
    }
    __syncthreads();

    const float* W = ew + (size_t)e * En * En;
    const int lane = tid & 31, warp = tid >> 5;
    const int grp  = lane >> 2, qd = lane & 3;
    const int m0w  = (warp / 4) * 64;
    const int n0w  = (warp % 4) * 32;

    int aS[4]; const float* aG[4];
    #pragma unroll
    for (int l = 0; l < 4; l++) {
        int idx = l * 256 + tid;
        int r = idx >> 3, c = (idx & 7) << 2;
        aS[l] = r * 36 + c;
        aG[l] = g_attn + (size_t)(rowflat[r] >> 1) * En + c;
    }
    int bS[4]; const float* bG[4];
    #pragma unroll
    for (int l = 0; l < 4; l++) {
        int idx = l * 256 + tid;
        int r = idx >> 3, c = (idx & 7) << 2;
        bS[l] = r * 36 + c;
        bG[l] = W + (size_t)(n0 + r) * En + c;
    }

    float acc[4][4][4];
    #pragma unroll
    for (int i = 0; i < 4; i++)
        #pragma unroll
        for (int j = 0; j < 4; j++)
            #pragma unroll
            for (int c = 0; c < 4; c++) acc[i][j][c] = 0.f;

    {
        float* As_ = smf;
        float* Bs_ = smf + 2 * A_ELE;
        #pragma unroll
        for (int l = 0; l < 4; l++) cpa16(As_ + aS[l], aG[l]);
        #pragma unroll
        for (int l = 0; l < 4; l++) cpa16(Bs_ + bS[l], bG[l]);
        CP_COMMIT();
    }

    const int NT = En >> 5;
    for (int t = 0; t < NT; t++) {
        if (t + 1 < NT) {
            int kt = (t + 1) << 5;
            int stg = (t + 1) & 1;
            float* As_ = smf + stg * A_ELE;
            float* Bs_ = smf + 2 * A_ELE + stg * B_ELE;
            #pragma unroll
            for (int l = 0; l < 4; l++) cpa16(As_ + aS[l], aG[l] + kt);
            #pragma unroll
            for (int l = 0; l < 4; l++) cpa16(Bs_ + bS[l], bG[l] + kt);
            CP_COMMIT();
            CP_WAIT1();
        } else {
            CP_WAIT0();
        }
        __syncthreads();

        const float* Asb = smf + (t & 1) * A_ELE;
        const float* Bsb = smf + 2 * A_ELE + (t & 1) * B_ELE;

        #pragma unroll
        for (int kk = 0; kk < 32; kk += 8) {
            const int c0 = kk + qd, c1 = c0 + 4;
            unsigned bf0[4], bf1[4];
            #pragma unroll
            for (int nt = 0; nt < 4; nt++) {
                const float* Bb = Bsb + (n0w + nt * 8 + grp) * 36;
                bf0[nt] = f2tf(Bb[c0]); bf1[nt] = f2tf(Bb[c1]);
            }
            #pragma unroll
            for (int mt = 0; mt < 4; mt++) {
                const float* Ar = Asb + (m0w + mt * 16 + grp) * 36;
                unsigned ah[4] = { f2tf(Ar[c0]), f2tf(Ar[8 * 36 + c0]),
                                   f2tf(Ar[c1]), f2tf(Ar[8 * 36 + c1]) };
                #pragma unroll
                for (int nt = 0; nt < 4; nt++) {
                    unsigned bh2[2] = { bf0[nt], bf1[nt] };
                    mma8(acc[mt][nt], ah, bh2);
                }
            }
        }
        __syncthreads();
    }

    #pragma unroll
    for (int mt = 0; mt < 4; mt++) {
        #pragma unroll
        for (int h = 0; h < 2; h++) {
            int mloc = m0w + mt * 16 + grp + h * 8;
            if (m0 + mloc >= cnt) continue;
            int fl = rowflat[mloc];
            float gtv = rowgate[mloc];
            #pragma unroll
            for (int nt = 0; nt < 4; nt++) {
                int gc = n0 + n0w + nt * 8 + 2 * qd;
                float v0 = gtv * (acc[mt][nt][2 * h + 0] + eb[(size_t)e * En + gc]);
                float v1 = gtv * (acc[mt][nt][2 * h + 1] + eb[(size_t)e * En + gc + 1]);
                *(float2*)(g_sel + (size_t)fl * En + gc) = make_float2(v0, v1);
            }
        }
    }
}

// ---------------- RoPE + transpose, pre-split q/k planes + plain v ----------------
__global__ void rope_transpose_kernel()
{
    int idx = blockIdx.x * blockDim.x + threadIdx.x;
    int i = idx & 31;
    int h = (idx >> 5) & 15;
    int s = (idx >> 9) & (Sn - 1);
    int b = idx >> 20;

    float inv = powf(10000.0f, -(float)(2 * i) / 64.0f);
    float sn, cs;
    sincosf((float)s * inv, &sn, &cs);

    size_t in_base  = ((size_t)(b * Sn + s)) * En + h * 64;
    size_t out_base = ((size_t)((b * Hn + h) * Sn + s)) * 64;
    const size_t lin_stride = (size_t)NTOK * En;

    {
        const float* src = g_lin + in_base;
        float x1 = src[i], x2 = src[i + 32];
        float r1 = x1 * cs - x2 * sn;
        float r2 = x2 * cs + x1 * sn;
        float h1, l1, h2, l2;
        split2(r1, h1, l1); split2(r2, h2, l2);
        g_qhi[out_base + i] = h1;      g_qlo[out_base + i] = l1;
        g_qhi[out_base + i + 32] = h2; g_qlo[out_base + i + 32] = l2;
    }
    {
        const float* src = g_lin + lin_stride + in_base;
        float x1 = src[i], x2 = src[i + 32];
        float r1 = x1 * cs - x2 * sn;
        float r2 = x2 * cs + x1 * sn;
        float h1, l1, h2, l2;
        split2(r1, h1, l1); split2(r2, h2, l2);
        g_khi[out_base + i] = h1;      g_klo[out_base + i] = l1;
        g_khi[out_base + i + 32] = h2; g_klo[out_base + i + 32] = l2;
    }
    {
        const float* src = g_lin + 2 * lin_stride + in_base;
        g_v[out_base + i]      = src[i];
        g_v[out_base + i + 32] = src[i + 32];
    }
}

// ---------------- V transpose + split: (bh, s, d) -> hi/lo (bh, d, s) ----------------
__global__ void __launch_bounds__(256)
vtrans_kernel()
{
    __shared__ float t[32][33];
    const int bh = blockIdx.z;
    const int s0 = blockIdx.x * 32;
    const int d0 = blockIdx.y * 32;
    const float* src = g_v + (size_t)bh * Sn * Dn;
    const size_t dstb = (size_t)bh * Dn * Sn;
    const int tx = threadIdx.x & 31, ty = threadIdx.x >> 5;
    #pragma unroll
    for (int i = ty; i < 32; i += 8)
        t[i][tx] = src[(size_t)(s0 + i) * Dn + d0 + tx];
    __syncthreads();
    #pragma unroll
    for (int i = ty; i < 32; i += 8) {
        float v = t[tx][i];
        float h, l;
        split2(v, h, l);
        g_vthi[dstb + (size_t)(d0 + i) * Sn + s0 + tx] = h;
        g_vtlo[dstb + (size_t)(d0 + i) * Sn + s0 + tx] = l;
    }
}

// ---------------- gate + top-2 + dispatch ----------------
__global__ void __launch_bounds__(128)
gate_topk_kernel(const float* __restrict__ gw, const float* __restrict__ gb)
{
    const int warp = threadIdx.x >> 5;
    const int lane = threadIdx.x & 31;
    const int t = blockIdx.x * 4 + warp;

    float acc[NEXP];
    #pragma unroll
    for (int e = 0; e < NEXP; e++) acc[e] = 0.f;
    const float* xr = g_attn + (size_t)t * En;
    for (int i = lane; i < En; i += 32) {
        float xv = xr[i];
        #pragma unroll
        for (int e = 0; e < NEXP; e++) acc[e] += xv * gw[e * En + i];
    }
    #pragma unroll
    for (int e = 0; e < NEXP; e++) {
        #pragma unroll
        for (int off = 16; off; off >>= 1)
            acc[e] += __shfl_xor_sync(0xffffffffu, acc[e], off);
    }
    if (lane == 0) {
        float lg[NEXP];
        float m = -1e30f;
        #pragma unroll
        for (int e = 0; e < NEXP; e++) { lg[e] = acc[e] + gb[e]; m = fmaxf(m, lg[e]); }
        float sum = 0.f;
        #pragma unroll
        for (int e = 0; e < NEXP; e++) { lg[e] = __expf(lg[e] - m); sum += lg[e]; }
        float invs = 1.f / sum;
        int i0 = 0;
        #pragma unroll
        for (int e = 1; e < NEXP; e++) if (lg[e] > lg[i0]) i0 = e;
        int i1 = (i0 == 0) ? 1 : 0;
        #pragma unroll
        for (int e = 0; e < NEXP; e++) if (e != i0 && lg[e] > lg[i1]) i1 = e;

        int p0 = atomicAdd(&g_cnt[i0], 1);
        g_list[i0 * NTOK + p0] = t * 2;
        g_gateflat[t * 2] = lg[i0] * invs;
        int p1 = atomicAdd(&g_cnt[i1], 1);
        g_list[i1 * NTOK + p1] = t * 2 + 1;
        g_gateflat[t * 2 + 1] = lg[i1] * invs;
    }
}

// ---------------- combine expert slots ----------------
__global__ void combine_kernel()
{
    size_t i = (size_t)blockIdx.x * blockDim.x + threadIdx.x;
    size_t row = i >> 8;
    size_t col = i & 255;
    const float4* s4 = (const float4*)g_sel;
    float4 a = s4[(2 * row) * 256 + col];
    float4 b = s4[(2 * row + 1) * 256 + col];
    ((float4*)g_moe)[i] = make_float4(a.x + b.x, a.y + b.y, a.z + b.z, a.w + b.w);
}

// ---------------- launch ----------------
extern "C" void kernel_launch(void* const* d_in, const int* in_sizes, int n_in,
                              void* d_out, int out_size)
{
    const float* x     = (const float*)d_in[0];
    const float* q_w   = (const float*)d_in[1];
    const float* q_b   = (const float*)d_in[2];
    const float* k_w   = (const float*)d_in[3];
    const float* k_b   = (const float*)d_in[4];
    const float* v_w   = (const float*)d_in[5];
    const float* v_b   = (const float*)d_in[6];
    const float* gatew = (const float*)d_in[7];
    const float* gateb = (const float*)d_in[8];
    const float* ew    = (const float*)d_in[9];
    const float* eb    = (const float*)d_in[10];
    const float* ffn_w = (const float*)d_in[11];
    const float* ffn_b = (const float*)d_in[12];
    float* out = (float*)d_out;

    float *lin, *xhi, *xlo, *whi, *wlo, *moe;
    cudaGetSymbolAddress((void**)&lin,   g_lin);
    cudaGetSymbolAddress((void**)&xhi,   g_xhi);
    cudaGetSymbolAddress((void**)&xlo,   g_xlo);
    cudaGetSymbolAddress((void**)&whi,   g_whi);
    cudaGetSymbolAddress((void**)&wlo,   g_wlo);
    cudaGetSymbolAddress((void**)&moe,   g_moe);

    const int SMPS  = (4 * 128 * 36 + 4 * 128 * 36) * 4;   // 147456
    const int SM128 = (2 * 128 * 36 + 2 * 128 * 36) * 4;   // 73728
    const int SMFL  = (2 * 128 * FSTR + 2 * 64 * FSTR + 2 * 64 * FSTR
                       + 2 * 128 * FSTR) * 4;              // 208896
    cudaFuncSetAttribute(gemm_ps<128>,    cudaFuncAttributeMaxDynamicSharedMemorySize, SMPS);
    cudaFuncSetAttribute(flash_attn,      cudaFuncAttributeMaxDynamicSharedMemorySize, SMFL);
    cudaFuncSetAttribute(mma_gemm<128,0>, cudaFuncAttributeMaxDynamicSharedMemorySize, SM128);
    cudaFuncSetAttribute(expert_mma,      cudaFuncAttributeMaxDynamicSharedMemorySize, SM128);

    zero_cnt_kernel<<<1, 32>>>();

    // pre-split x and qkv weights
    split_kernel<<<(NTOK * En / 4 + 255) / 256, 256>>>(x, xhi, xlo, NTOK * En / 4);
    split_kernel<<<(En * En / 4 + 255) / 256, 256>>>(q_w, whi, wlo, En * En / 4);
    split_kernel<<<(En * En / 4 + 255) / 256, 256>>>(k_w, whi + (size_t)En * En,
                                                     wlo + (size_t)En * En, En * En / 4);
    split_kernel<<<(En * En / 4 + 255) / 256, 256>>>(v_w, whi + (size_t)2 * En * En,
                                                     wlo + (size_t)2 * En * En, En * En / 4);

    // fused QKV projections (pre-split planes)
    gemm_ps<128><<<dim3(En / 128, NTOK / 128, 3), 256, SMPS>>>(
        xhi, xlo, whi, wlo, q_b, k_b, v_b, lin,
        En, En, 0, (long long)En * En, (long long)NTOK * En, 1.f);

    rope_transpose_kernel<<<(Bn * Sn * Hn * 32) / 256, 256>>>();
    vtrans_kernel<<<dim3(Sn / 32, Dn / 32, BHn), 256>>>();

    // fused attention: scores + softmax + PV in one kernel
    flash_attn<<<dim3(Sn / 128, BHn), 256, SMFL>>>();

    gate_topk_kernel<<<NTOK / 4, 128>>>(gatew, gateb);

    expert_mma<<<dim3(En / 128, NTOK / 128, NEXP), 256, SM128>>>(ew, eb);

    combine_kernel<<<(NTOK * (En / 4)) / 256, 256>>>();

    // final FFN + bias + residual (plain tf32)
    mma_gemm<128,0><<<dim3(En / 128, NTOK / 128, 1), 256, SM128>>>(
        moe, ffn_w, ffn_b, x, out,
        NTOK, En, En, 0, 0, 0, 1.f, 0);
}

// round 13
// speedup vs baseline: 1.7222x; 1.0009x over previous
#include <cuda_runtime.h>
#include <math.h>

#define Bn   2
#define Sn   2048
#define En   1024
#define Hn   16
#define Dn   64
#define NEXP 8
#define NTOK (Bn*Sn)          // 4096
#define BHn  (Bn*Hn)          // 32
#define PLANE ((size_t)BHn*Sn*Dn)
#define FSTR 68

// ---------------- scratch ----------------
__device__ float g_lin [(size_t)3*NTOK*En];
__device__ float g_xhi [(size_t)NTOK*En];
__device__ float g_xlo [(size_t)NTOK*En];
__device__ float g_whi [(size_t)3*En*En];
__device__ float g_wlo [(size_t)3*En*En];
__device__ float g_qhi [PLANE];
__device__ float g_qlo [PLANE];
__device__ float g_khi [PLANE];
__device__ float g_klo [PLANE];
__device__ float g_v   [PLANE];
__device__ float g_vthi[(size_t)BHn*Dn*Sn];        // V^T hi (bh, d, s)
__device__ float g_vtlo[(size_t)BHn*Dn*Sn];        // V^T lo
__device__ float g_attn[(size_t)NTOK*En];
__device__ float g_sel [(size_t)2*NTOK*En];
__device__ float g_moe [(size_t)NTOK*En];
__device__ float g_gateflat[2*NTOK];
__device__ int   g_list[NEXP*NTOK];
__device__ int   g_cnt [NEXP];

__global__ void zero_cnt_kernel() {
    if (threadIdx.x < NEXP) g_cnt[threadIdx.x] = 0;
}

// ---------------- tf32 helpers ----------------
__device__ __forceinline__ unsigned f2tf(float x) {
    unsigned r;
    asm("cvt.rna.tf32.f32 %0, %1;" : "=r"(r) : "f"(x));
    return r;
}
__device__ __forceinline__ void mma8(float* c, const unsigned* a, const unsigned* b) {
    asm volatile(
        "mma.sync.aligned.m16n8k8.row.col.f32.tf32.tf32.f32 "
        "{%0,%1,%2,%3}, {%4,%5,%6,%7}, {%8,%9}, {%0,%1,%2,%3};\n"
        : "+f"(c[0]), "+f"(c[1]), "+f"(c[2]), "+f"(c[3])
        : "r"(a[0]), "r"(a[1]), "r"(a[2]), "r"(a[3]), "r"(b[0]), "r"(b[1]));
}
__device__ __forceinline__ void cpa16(float* s, const float* g) {
    unsigned sa = (unsigned)__cvta_generic_to_shared(s);
    asm volatile("cp.async.cg.shared.global [%0], [%1], 16;" :: "r"(sa), "l"(g));
}
#define CP_COMMIT()  asm volatile("cp.async.commit_group;" ::: "memory")
#define CP_WAIT1()   asm volatile("cp.async.wait_group 1;" ::: "memory")
#define CP_WAIT0()   asm volatile("cp.async.wait_group 0;" ::: "memory")

__device__ __forceinline__ void split2(float v, float& hi, float& lo) {
    unsigned h = f2tf(v);
    hi = __uint_as_float(h);
    lo = __uint_as_float(f2tf(v - hi));
}

// ---------------- elementwise hi/lo split ----------------
__global__ void split_kernel(const float* __restrict__ in,
                             float* __restrict__ oh, float* __restrict__ ol, int n4)
{
    int i = blockIdx.x * blockDim.x + threadIdx.x;
    if (i >= n4) return;
    float4 v = ((const float4*)in)[i];
    float4 h, l;
    split2(v.x, h.x, l.x); split2(v.y, h.y, l.y);
    split2(v.z, h.z, l.z); split2(v.w, h.w, l.w);
    ((float4*)oh)[i] = h;
    ((float4*)ol)[i] = l;
}

// ---------------- pre-split tf32 GEMM (QKV) ----------------
template<int BN>
__global__ void __launch_bounds__(256)
gemm_ps(const float* __restrict__ Ah, const float* __restrict__ Al,
        const float* __restrict__ Bh, const float* __restrict__ Bl,
        const float* __restrict__ b0, const float* __restrict__ b1,
        const float* __restrict__ b2,
        float* __restrict__ Cg, int N, int K,
        long long sAz, long long sBz, long long sCz, float alpha)
{
    constexpr int WC    = (BN == 128) ? 4 : 2;
    constexpr int MT    = (BN == 128) ? 4 : 2;
    constexpr int BL    = (BN == 128) ? 4 : 2;
    constexpr int A_ELE = 128 * 36;
    constexpr int B_ELE = BN * 36;

    extern __shared__ float smf[];
    float* Ah_s = smf;
    float* Al_s = smf + 2 * A_ELE;
    float* Bh_s = smf + 4 * A_ELE;
    float* Bl_s = smf + 4 * A_ELE + 2 * B_ELE;

    const int z = blockIdx.z;
    const float* AH = Ah + (size_t)z * sAz;
    const float* AL = Al + (size_t)z * sAz;
    const float* BH = Bh + (size_t)z * sBz;
    const float* BLp= Bl + (size_t)z * sBz;
    const float* bias = (b1 == nullptr) ? b0 : (z == 0 ? b0 : (z == 1 ? b1 : b2));

    const int tid  = threadIdx.x;
    const int lane = tid & 31;
    const int warp = tid >> 5;
    const int grp  = lane >> 2;
    const int qd   = lane & 3;
    const int m0   = blockIdx.y * 128;
    const int n0   = blockIdx.x * BN;
    const int m0w  = (warp / WC) * (16 * MT);
    const int n0w  = (warp % WC) * 32;

    int aS[4]; long long aO[4];
    #pragma unroll
    for (int l = 0; l < 4; l++) {
        int idx = l * 256 + tid;
        int r = idx >> 3, c = (idx & 7) << 2;
        aS[l] = r * 36 + c;
        aO[l] = (long long)(m0 + r) * K + c;
    }
    int bS[BL]; long long bO[BL];
    #pragma unroll
    for (int l = 0; l < BL; l++) {
        int idx = l * 256 + tid;
        int r = idx >> 3, c = (idx & 7) << 2;
        bS[l] = r * 36 + c;
        bO[l] = (long long)(n0 + r) * K + c;
    }

    float acc[MT][4][4];
    #pragma unroll
    for (int i = 0; i < MT; i++)
        #pragma unroll
        for (int j = 0; j < 4; j++)
            #pragma unroll
            for (int c = 0; c < 4; c++) acc[i][j][c] = 0.f;

    {
        #pragma unroll
        for (int l = 0; l < 4; l++) {
            cpa16(Ah_s + aS[l], AH + aO[l]);
            cpa16(Al_s + aS[l], AL + aO[l]);
        }
        #pragma unroll
        for (int l = 0; l < BL; l++) {
            cpa16(Bh_s + bS[l], BH + bO[l]);
            cpa16(Bl_s + bS[l], BLp + bO[l]);
        }
        CP_COMMIT();
    }

    const int NT = K >> 5;
    for (int t = 0; t < NT; t++) {
        if (t + 1 < NT) {
            int kt = (t + 1) << 5;
            int stg = (t + 1) & 1;
            #pragma unroll
            for (int l = 0; l < 4; l++) {
                cpa16(Ah_s + stg * A_ELE + aS[l], AH + aO[l] + kt);
                cpa16(Al_s + stg * A_ELE + aS[l], AL + aO[l] + kt);
            }
            #pragma unroll
            for (int l = 0; l < BL; l++) {
                cpa16(Bh_s + stg * B_ELE + bS[l], BH + bO[l] + kt);
                cpa16(Bl_s + stg * B_ELE + bS[l], BLp + bO[l] + kt);
            }
            CP_COMMIT();
            CP_WAIT1();
        } else {
            CP_WAIT0();
        }
        __syncthreads();

        const float* AH_b = Ah_s + (t & 1) * A_ELE;
        const float* AL_b = Al_s + (t & 1) * A_ELE;
        const float* BH_b = Bh_s + (t & 1) * B_ELE;
        const float* BL_b = Bl_s + (t & 1) * B_ELE;

        #pragma unroll
        for (int kk = 0; kk < 32; kk += 8) {
            const int c0 = kk + qd, c1 = c0 + 4;
            unsigned bh[4][2], bl[4][2];
            #pragma unroll
            for (int nt = 0; nt < 4; nt++) {
                int roff = (n0w + nt * 8 + grp) * 36;
                bh[nt][0] = __float_as_uint(BH_b[roff + c0]);
                bh[nt][1] = __float_as_uint(BH_b[roff + c1]);
                bl[nt][0] = __float_as_uint(BL_b[roff + c0]);
                bl[nt][1] = __float_as_uint(BL_b[roff + c1]);
            }
            #pragma unroll
            for (int mt = 0; mt < MT; mt++) {
                int roff = (m0w + mt * 16 + grp) * 36;
                unsigned ah[4] = { __float_as_uint(AH_b[roff + c0]),
                                   __float_as_uint(AH_b[roff + 8 * 36 + c0]),
                                   __float_as_uint(AH_b[roff + c1]),
                                   __float_as_uint(AH_b[roff + 8 * 36 + c1]) };
                unsigned al[4] = { __float_as_uint(AL_b[roff + c0]),
                                   __float_as_uint(AL_b[roff + 8 * 36 + c0]),
                                   __float_as_uint(AL_b[roff + c1]),
                                   __float_as_uint(AL_b[roff + 8 * 36 + c1]) };
                #pragma unroll
                for (int nt = 0; nt < 4; nt++) {
                    mma8(acc[mt][nt], ah, bh[nt]);
                    mma8(acc[mt][nt], al, bh[nt]);
                    mma8(acc[mt][nt], ah, bl[nt]);
                }
            }
        }
        __syncthreads();
    }

    #pragma unroll
    for (int mt = 0; mt < MT; mt++) {
        #pragma unroll
        for (int h = 0; h < 2; h++) {
            int r = m0 + m0w + mt * 16 + grp + h * 8;
            #pragma unroll
            for (int nt = 0; nt < 4; nt++) {
                int gc = n0 + n0w + nt * 8 + 2 * qd;
                float v0 = acc[mt][nt][2 * h + 0] * alpha;
                float v1 = acc[mt][nt][2 * h + 1] * alpha;
                if (bias) { v0 += bias[gc]; v1 += bias[gc + 1]; }
                *(float2*)(Cg + (size_t)z * sCz + (size_t)r * N + gc) =
                    make_float2(v0, v1);
            }
        }
    }
}

// ---------------- fused flash attention (3xTF32 S and PV) ----------------
// grid (Sn/128, BHn), 256 threads. Q/K from pre-split planes, V^T pre-split.
__global__ void __launch_bounds__(256)
flash_attn()
{
    extern __shared__ float sm[];
    float* qh = sm;                         // 128*FSTR
    float* ql = qh + 128 * FSTR;
    float* kh = ql + 128 * FSTR;            // 64*FSTR
    float* kl = kh + 64 * FSTR;
    float* vh = kl + 64 * FSTR;             // V^T tile: row d, col key
    float* vl = vh + 64 * FSTR;
    float* ph = vl + 64 * FSTR;             // 128*FSTR
    float* pl = ph + 128 * FSTR;
    __shared__ float redmx[2 * 128];
    __shared__ float redsm[2 * 128];

    const int bh  = blockIdx.y;
    const int q0  = blockIdx.x * 128;
    const int tid = threadIdx.x;
    const int lane = tid & 31, warp = tid >> 5;
    const int grp  = lane >> 2, qd = lane & 3;
    const int mw   = (warp >> 1) * 32;
    const int nw   = (warp & 1) * 32;

    const size_t sbase = (size_t)bh * Sn * Dn;   // (bh, s, d)
    const size_t vbase = (size_t)bh * Dn * Sn;   // (bh, d, s)

    // Q load (group 1)
    #pragma unroll
    for (int l = 0; l < 8; l++) {
        int idx = l * 256 + tid;
        int r = idx >> 4, c = (idx & 15) << 2;
        cpa16(qh + r * FSTR + c, g_qhi + sbase + (size_t)(q0 + r) * 64 + c);
        cpa16(ql + r * FSTR + c, g_qlo + sbase + (size_t)(q0 + r) * 64 + c);
    }
    CP_COMMIT();

    // K0 (group 2), V0 (group 3)
    int kvr[4], kvc[4];
    #pragma unroll
    for (int l = 0; l < 4; l++) {
        int idx = l * 256 + tid;
        kvr[l] = idx >> 4; kvc[l] = (idx & 15) << 2;
    }
    #pragma unroll
    for (int l = 0; l < 4; l++) {
        cpa16(kh + kvr[l] * FSTR + kvc[l], g_khi + sbase + (size_t)kvr[l] * 64 + kvc[l]);
        cpa16(kl + kvr[l] * FSTR + kvc[l], g_klo + sbase + (size_t)kvr[l] * 64 + kvc[l]);
    }
    CP_COMMIT();
    #pragma unroll
    for (int l = 0; l < 4; l++) {
        cpa16(vh + kvr[l] * FSTR + kvc[l], g_vthi + vbase + (size_t)kvr[l] * Sn + kvc[l]);
        cpa16(vl + kvr[l] * FSTR + kvc[l], g_vtlo + vbase + (size_t)kvr[l] * Sn + kvc[l]);
    }
    CP_COMMIT();

    float acco[2][4][4];
    #pragma unroll
    for (int i = 0; i < 2; i++)
        #pragma unroll
        for (int j = 0; j < 4; j++)
            #pragma unroll
            for (int c = 0; c < 4; c++) acco[i][j][c] = 0.f;
    float mI[2][2] = { {-1e30f, -1e30f}, {-1e30f, -1e30f} };
    float lI[2][2] = { {0.f, 0.f}, {0.f, 0.f} };

    for (int kt = 0; kt < Sn; kt += 64) {
        CP_WAIT1();            // K tile ready (V of this tile may be pending)
        __syncthreads();

        // ---- S = Q K^T (3xTF32) ----
        float accs[2][4][4];
        #pragma unroll
        for (int i = 0; i < 2; i++)
            #pragma unroll
            for (int j = 0; j < 4; j++)
                #pragma unroll
                for (int c = 0; c < 4; c++) accs[i][j][c] = 0.f;

        #pragma unroll
        for (int kk = 0; kk < 64; kk += 8) {
            const int c0 = kk + qd, c1 = c0 + 4;
            unsigned bhf[4][2], blf[4][2];
            #pragma unroll
            for (int nt = 0; nt < 4; nt++) {
                int ro = (nw + nt * 8 + grp) * FSTR;
                bhf[nt][0] = __float_as_uint(kh[ro + c0]);
                bhf[nt][1] = __float_as_uint(kh[ro + c1]);
                blf[nt][0] = __float_as_uint(kl[ro + c0]);
                blf[nt][1] = __float_as_uint(kl[ro + c1]);
            }
            #pragma unroll
            for (int mt = 0; mt < 2; mt++) {
                int ro = (mw + mt * 16 + grp) * FSTR;
                unsigned ah[4] = { __float_as_uint(qh[ro + c0]),
                                   __float_as_uint(qh[ro + 8 * FSTR + c0]),
                                   __float_as_uint(qh[ro + c1]),
                                   __float_as_uint(qh[ro + 8 * FSTR + c1]) };
                unsigned al[4] = { __float_as_uint(ql[ro + c0]),
                                   __float_as_uint(ql[ro + 8 * FSTR + c0]),
                                   __float_as_uint(ql[ro + c1]),
                                   __float_as_uint(ql[ro + 8 * FSTR + c1]) };
                #pragma unroll
                for (int nt = 0; nt < 4; nt++) {
                    mma8(accs[mt][nt], ah, bhf[nt]);
                    mma8(accs[mt][nt], al, bhf[nt]);
                    mma8(accs[mt][nt], ah, blf[nt]);
                }
            }
        }

        // scale + tile row-max (warp-local 32 cols)
        #pragma unroll
        for (int mt = 0; mt < 2; mt++)
            #pragma unroll
            for (int nt = 0; nt < 4; nt++)
                #pragma unroll
                for (int c = 0; c < 4; c++) accs[mt][nt][c] *= 0.125f;

        #pragma unroll
        for (int mt = 0; mt < 2; mt++)
            #pragma unroll
            for (int h = 0; h < 2; h++) {
                float tm = -1e30f;
                #pragma unroll
                for (int nt = 0; nt < 4; nt++)
                    tm = fmaxf(tm, fmaxf(accs[mt][nt][2 * h], accs[mt][nt][2 * h + 1]));
                tm = fmaxf(tm, __shfl_xor_sync(0xffffffffu, tm, 1));
                tm = fmaxf(tm, __shfl_xor_sync(0xffffffffu, tm, 2));
                if (qd == 0)
                    redmx[(warp & 1) * 128 + mw + mt * 16 + grp + h * 8] = tm;
            }
        __syncthreads();       // sync1: maxes ready, kh/kl free

        // prefetch next K (empty commit on last tile keeps group order)
        if (kt + 64 < Sn) {
            #pragma unroll
            for (int l = 0; l < 4; l++) {
                cpa16(kh + kvr[l] * FSTR + kvc[l],
                      g_khi + sbase + (size_t)(kt + 64 + kvr[l]) * 64 + kvc[l]);
                cpa16(kl + kvr[l] * FSTR + kvc[l],
                      g_klo + sbase + (size_t)(kt + 64 + kvr[l]) * 64 + kvc[l]);
            }
        }
        CP_COMMIT();

        // p = exp(s - m_new), write P hi/lo, partial sums
        float cfac[2][2];
        #pragma unroll
        for (int mt = 0; mt < 2; mt++)
            #pragma unroll
            for (int h = 0; h < 2; h++) {
                int row = mw + mt * 16 + grp + h * 8;
                float mx = fmaxf(redmx[row], redmx[128 + row]);
                float mnew = fmaxf(mI[mt][h], mx);
                cfac[mt][h] = __expf(mI[mt][h] - mnew);
                mI[mt][h] = mnew;
                float sum = 0.f;
                #pragma unroll
                for (int nt = 0; nt < 4; nt++) {
                    float p0 = __expf(accs[mt][nt][2 * h]     - mnew);
                    float p1 = __expf(accs[mt][nt][2 * h + 1] - mnew);
                    sum += p0 + p1;
                    float h0, l0, h1, l1;
                    split2(p0, h0, l0); split2(p1, h1, l1);
                    int off = row * FSTR + nw + nt * 8 + 2 * qd;
                    *(float2*)(ph + off) = make_float2(h0, h1);
                    *(float2*)(pl + off) = make_float2(l0, l1);
                }
                sum += __shfl_xor_sync(0xffffffffu, sum, 1);
                sum += __shfl_xor_sync(0xffffffffu, sum, 2);
                if (qd == 0) redsm[(warp & 1) * 128 + row] = sum;
            }

        CP_WAIT1();            // V tile ready (next-K pending)
        __syncthreads();       // sync2: P, sums, V all visible

        // stats update + rescale O
        #pragma unroll
        for (int mt = 0; mt < 2; mt++)
            #pragma unroll
            for (int h = 0; h < 2; h++) {
                int row = mw + mt * 16 + grp + h * 8;
                float s2 = redsm[row] + redsm[128 + row];
                lI[mt][h] = lI[mt][h] * cfac[mt][h] + s2;
                #pragma unroll
                for (int nt = 0; nt < 4; nt++) {
                    acco[mt][nt][2 * h]     *= cfac[mt][h];
                    acco[mt][nt][2 * h + 1] *= cfac[mt][h];
                }
            }

        // ---- O += P V (3xTF32): A=P rows q, B=V^T rows d ----
        #pragma unroll
        for (int kk = 0; kk < 64; kk += 8) {
            const int c0 = kk + qd, c1 = c0 + 4;
            unsigned bhf[4][2], blf[4][2];
            #pragma unroll
            for (int nt = 0; nt < 4; nt++) {
                int ro = (nw + nt * 8 + grp) * FSTR;
                bhf[nt][0] = __float_as_uint(vh[ro + c0]);
                bhf[nt][1] = __float_as_uint(vh[ro + c1]);
                blf[nt][0] = __float_as_uint(vl[ro + c0]);
                blf[nt][1] = __float_as_uint(vl[ro + c1]);
            }
            #pragma unroll
            for (int mt = 0; mt < 2; mt++) {
                int ro = (mw + mt * 16 + grp) * FSTR;
                unsigned ah[4] = { __float_as_uint(ph[ro + c0]),
                                   __float_as_uint(ph[ro + 8 * FSTR + c0]),
                                   __float_as_uint(ph[ro + c1]),
                                   __float_as_uint(ph[ro + 8 * FSTR + c1]) };
                unsigned al[4] = { __float_as_uint(pl[ro + c0]),
                                   __float_as_uint(pl[ro + 8 * FSTR + c0]),
                                   __float_as_uint(pl[ro + c1]),
                                   __float_as_uint(pl[ro + 8 * FSTR + c1]) };
                #pragma unroll
                for (int nt = 0; nt < 4; nt++) {
                    mma8(acco[mt][nt], ah, bhf[nt]);
                    mma8(acco[mt][nt], al, bhf[nt]);
                    mma8(acco[mt][nt], ah, blf[nt]);
                }
            }
        }
        __syncthreads();       // sync3: vh/vl + red arrays free

        // prefetch next V
        if (kt + 64 < Sn) {
            #pragma unroll
            for (int l = 0; l < 4; l++) {
                cpa16(vh + kvr[l] * FSTR + kvc[l],
                      g_vthi + vbase + (size_t)kvr[l] * Sn + kt + 64 + kvc[l]);
                cpa16(vl + kvr[l] * FSTR + kvc[l],
                      g_vtlo + vbase + (size_t)kvr[l] * Sn + kt + 64 + kvc[l]);
            }
        }
        CP_COMMIT();
    }

    // epilogue: normalize, scatter to (tok, E) head layout
    const int bb = bh >> 4, hh = bh & 15;
    #pragma unroll
    for (int mt = 0; mt < 2; mt++)
        #pragma unroll
        for (int h = 0; h < 2; h++) {
            int row = mw + mt * 16 + grp + h * 8;
            float inv = 1.f / lI[mt][h];
            #pragma unroll
            for (int nt = 0; nt < 4; nt++) {
                int dcol = nw + nt * 8 + 2 * qd;
                *(float2*)(g_attn + ((size_t)(bb * Sn + q0 + row)) * En + hh * 64 + dcol) =
                    make_float2(acco[mt][nt][2 * h] * inv, acco[mt][nt][2 * h + 1] * inv);
            }
        }
}

// ---------------- FFN GEMM (plain tf32, cp.async) ----------------
template<int BN, int SPLIT>
__global__ void __launch_bounds__(256)
mma_gemm(const float* __restrict__ Ag, const float* __restrict__ Bg,
         const float* __restrict__ bias, const float* __restrict__ resid,
         float* __restrict__ Cg, int M, int N, int K,
         long long sAz, long long sBz, long long sCz,
         float alpha, int c_attn)
{
    constexpr int WC    = (BN == 128) ? 4 : 2;
    constexpr int MT    = (BN == 128) ? 4 : 2;
    constexpr int BL    = (BN == 128) ? 4 : 2;
    constexpr int A_ELE = 128 * 36;
    constexpr int B_ELE = BN * 36;

    extern __shared__ float smf[];

    const int z = blockIdx.z;
    const float* A = Ag + (size_t)z * sAz;
    const float* B = Bg + (size_t)z * sBz;

    const int tid  = threadIdx.x;
    const int lane = tid & 31;
    const int warp = tid >> 5;
    const int grp  = lane >> 2;
    const int qd   = lane & 3;
    const int m0   = blockIdx.y * 128;
    const int n0   = blockIdx.x * BN;
    const int m0w  = (warp / WC) * (16 * MT);
    const int n0w  = (warp % WC) * 32;

    int aS[4]; const float* aG[4];
    #pragma unroll
    for (int l = 0; l < 4; l++) {
        int idx = l * 256 + tid;
        int r = idx >> 3, c = (idx & 7) << 2;
        aS[l] = r * 36 + c;
        aG[l] = A + (size_t)(m0 + r) * K + c;
    }
    int bS[BL]; const float* bG[BL];
    #pragma unroll
    for (int l = 0; l < BL; l++) {
        int idx = l * 256 + tid;
        int r = idx >> 3, c = (idx & 7) << 2;
        bS[l] = r * 36 + c;
        bG[l] = B + (size_t)(n0 + r) * K + c;
    }

    float acc[MT][4][4];
    #pragma unroll
    for (int i = 0; i < MT; i++)
        #pragma unroll
        for (int j = 0; j < 4; j++)
            #pragma unroll
            for (int c = 0; c < 4; c++) acc[i][j][c] = 0.f;

    {
        float* As_ = smf;
        float* Bs_ = smf + 2 * A_ELE;
        #pragma unroll
        for (int l = 0; l < 4;  l++) cpa16(As_ + aS[l], aG[l]);
        #pragma unroll
        for (int l = 0; l < BL; l++) cpa16(Bs_ + bS[l], bG[l]);
        CP_COMMIT();
    }

    const int NT = K >> 5;
    for (int t = 0; t < NT; t++) {
        if (t + 1 < NT) {
            int kt = (t + 1) << 5;
            int stg = (t + 1) & 1;
            float* As_ = smf + stg * A_ELE;
            float* Bs_ = smf + 2 * A_ELE + stg * B_ELE;
            #pragma unroll
            for (int l = 0; l < 4;  l++) cpa16(As_ + aS[l], aG[l] + kt);
            #pragma unroll
            for (int l = 0; l < BL; l++) cpa16(Bs_ + bS[l], bG[l] + kt);
            CP_COMMIT();
            CP_WAIT1();
        } else {
            CP_WAIT0();
        }
        __syncthreads();

        const float* Asb = smf + (t & 1) * A_ELE;
        const float* Bsb = smf + 2 * A_ELE + (t & 1) * B_ELE;

        #pragma unroll
        for (int kk = 0; kk < 32; kk += 8) {
            const int c0 = kk + qd, c1 = c0 + 4;
            unsigned bh[4][2], bl[4][2];
            #pragma unroll
            for (int nt = 0; nt < 4; nt++) {
                const float* Bb = Bsb + (n0w + nt * 8 + grp) * 36;
                float v0 = Bb[c0], v1 = Bb[c1];
                bh[nt][0] = f2tf(v0); bh[nt][1] = f2tf(v1);
                if (SPLIT) {
                    bl[nt][0] = f2tf(v0 - __uint_as_float(bh[nt][0]));
                    bl[nt][1] = f2tf(v1 - __uint_as_float(bh[nt][1]));
                }
            }
            #pragma unroll
            for (int mt = 0; mt < MT; mt++) {
                const float* Ar = Asb + (m0w + mt * 16 + grp) * 36;
                float x0 = Ar[c0],       x1 = Ar[8 * 36 + c0];
                float x2 = Ar[c1],       x3 = Ar[8 * 36 + c1];
                unsigned ah[4] = { f2tf(x0), f2tf(x1), f2tf(x2), f2tf(x3) };
                unsigned al[4];
                if (SPLIT) {
                    al[0] = f2tf(x0 - __uint_as_float(ah[0]));
                    al[1] = f2tf(x1 - __uint_as_float(ah[1]));
                    al[2] = f2tf(x2 - __uint_as_float(ah[2]));
                    al[3] = f2tf(x3 - __uint_as_float(ah[3]));
                }
                #pragma unroll
                for (int nt = 0; nt < 4; nt++) {
                    mma8(acc[mt][nt], ah, bh[nt]);
                    if (SPLIT) {
                        mma8(acc[mt][nt], al, bh[nt]);
                        mma8(acc[mt][nt], ah, bl[nt]);
                    }
                }
            }
        }
        __syncthreads();
    }

    #pragma unroll
    for (int mt = 0; mt < MT; mt++) {
        #pragma unroll
        for (int h = 0; h < 2; h++) {
            int r = m0 + m0w + mt * 16 + grp + h * 8;
            #pragma unroll
            for (int nt = 0; nt < 4; nt++) {
                int col = n0w + nt * 8 + 2 * qd;
                int gc  = n0 + col;
                float v0 = acc[mt][nt][2 * h + 0] * alpha;
                float v1 = acc[mt][nt][2 * h + 1] * alpha;
                if (bias)  { v0 += bias[gc]; v1 += bias[gc + 1]; }
                if (resid) {
                    const float* rr = resid + (size_t)r * N + gc;
                    v0 += rr[0]; v1 += rr[1];
                }
                *(float2*)(Cg + (size_t)z * sCz + (size_t)r * N + gc) =
                    make_float2(v0, v1);
            }
        }
    }
}

// ---------------- grouped expert GEMM ----------------
__global__ void __launch_bounds__(256)
expert_mma(const float* __restrict__ ew, const float* __restrict__ eb)
{
    constexpr int A_ELE = 128 * 36;
    constexpr int B_ELE = 128 * 36;

    const int e   = blockIdx.z;
    const int cnt = g_cnt[e];
    const int m0  = blockIdx.y * 128;
    if (m0 >= cnt) return;
    const int n0  = blockIdx.x * 128;

    extern __shared__ float smf[];
    __shared__ int   rowflat[128];
    __shared__ float rowgate[128];

    const int tid = threadIdx.x;
    if (tid < 128) {
        int m = m0 + tid;
        int fl = (m < cnt) ? g_list[e * NTOK + m] : 0;
        rowflat[tid] = fl;
        rowgate[tid] = (m < cnt) ? g_gateflat[fl] : 0.f;
    }
    __syncthreads();

    const float* W = ew + (size_t)e * En * En;
    const int lane = tid & 31, warp = tid >> 5;
    const int grp  = lane >> 2, qd = lane & 3;
    const int m0w  = (warp / 4) * 64;
    const int n0w  = (warp % 4) * 32;

    int aS[4]; const float* aG[4];
    #pragma unroll
    for (int l = 0; l < 4; l++) {
        int idx = l * 256 + tid;
        int r = idx >> 3, c = (idx & 7) << 2;
        aS[l] = r * 36 + c;
        aG[l] = g_attn + (size_t)(rowflat[r] >> 1) * En + c;
    }
    int bS[4]; const float* bG[4];
    #pragma unroll
    for (int l = 0; l < 4; l++) {
        int idx = l * 256 + tid;
        int r = idx >> 3, c = (idx & 7) << 2;
        bS[l] = r * 36 + c;
        bG[l] = W + (size_t)(n0 + r) * En + c;
    }

    float acc[4][4][4];
    #pragma unroll
    for (int i = 0; i < 4; i++)
        #pragma unroll
        for (int j = 0; j < 4; j++)
            #pragma unroll
            for (int c = 0; c < 4; c++) acc[i][j][c] = 0.f;

    {
        float* As_ = smf;
        float* Bs_ = smf + 2 * A_ELE;
        #pragma unroll
        for (int l = 0; l < 4; l++) cpa16(As_ + aS[l], aG[l]);
        #pragma unroll
        for (int l = 0; l < 4; l++) cpa16(Bs_ + bS[l], bG[l]);
        CP_COMMIT();
    }

    const int NT = En >> 5;
    for (int t = 0; t < NT; t++) {
        if (t + 1 < NT) {
            int kt = (t + 1) << 5;
            int stg = (t + 1) & 1;
            float* As_ = smf + stg * A_ELE;
            float* Bs_ = smf + 2 * A_ELE + stg * B_ELE;
            #pragma unroll
            for (int l = 0; l < 4; l++) cpa16(As_ + aS[l], aG[l] + kt);
            #pragma unroll
            for (int l = 0; l < 4; l++) cpa16(Bs_ + bS[l], bG[l] + kt);
            CP_COMMIT();
            CP_WAIT1();
        } else {
            CP_WAIT0();
        }
        __syncthreads();

        const float* Asb = smf + (t & 1) * A_ELE;
        const float* Bsb = smf + 2 * A_ELE + (t & 1) * B_ELE;

        #pragma unroll
        for (int kk = 0; kk < 32; kk += 8) {
            const int c0 = kk + qd, c1 = c0 + 4;
            unsigned bf0[4], bf1[4];
            #pragma unroll
            for (int nt = 0; nt < 4; nt++) {
                const float* Bb = Bsb + (n0w + nt * 8 + grp) * 36;
                bf0[nt] = f2tf(Bb[c0]); bf1[nt] = f2tf(Bb[c1]);
            }
            #pragma unroll
            for (int mt = 0; mt < 4; mt++) {
                const float* Ar = Asb + (m0w + mt * 16 + grp) * 36;
                unsigned ah[4] = { f2tf(Ar[c0]), f2tf(Ar[8 * 36 + c0]),
                                   f2tf(Ar[c1]), f2tf(Ar[8 * 36 + c1]) };
                #pragma unroll
                for (int nt = 0; nt < 4; nt++) {
                    unsigned bh2[2] = { bf0[nt], bf1[nt] };
                    mma8(acc[mt][nt], ah, bh2);
                }
            }
        }
        __syncthreads();
    }

    #pragma unroll
    for (int mt = 0; mt < 4; mt++) {
        #pragma unroll
        for (int h = 0; h < 2; h++) {
            int mloc = m0w + mt * 16 + grp + h * 8;
            if (m0 + mloc >= cnt) continue;
            int fl = rowflat[mloc];
            float gtv = rowgate[mloc];
            #pragma unroll
            for (int nt = 0; nt < 4; nt++) {
                int gc = n0 + n0w + nt * 8 + 2 * qd;
                float v0 = gtv * (acc[mt][nt][2 * h + 0] + eb[(size_t)e * En + gc]);
                float v1 = gtv * (acc[mt][nt][2 * h + 1] + eb[(size_t)e * En + gc + 1]);
                *(float2*)(g_sel + (size_t)fl * En + gc) = make_float2(v0, v1);
            }
        }
    }
}

// ---------------- RoPE + transpose, pre-split q/k planes + plain v ----------------
__global__ void rope_transpose_kernel()
{
    int idx = blockIdx.x * blockDim.x + threadIdx.x;
    int i = idx & 31;
    int h = (idx >> 5) & 15;
    int s = (idx >> 9) & (Sn - 1);
    int b = idx >> 20;

    float inv = powf(10000.0f, -(float)(2 * i) / 64.0f);
    float sn, cs;
    sincosf((float)s * inv, &sn, &cs);

    size_t in_base  = ((size_t)(b * Sn + s)) * En + h * 64;
    size_t out_base = ((size_t)((b * Hn + h) * Sn + s)) * 64;
    const size_t lin_stride = (size_t)NTOK * En;

    {
        const float* src = g_lin + in_base;
        float x1 = src[i], x2 = src[i + 32];
        float r1 = x1 * cs - x2 * sn;
        float r2 = x2 * cs + x1 * sn;
        float h1, l1, h2, l2;
        split2(r1, h1, l1); split2(r2, h2, l2);
        g_qhi[out_base + i] = h1;      g_qlo[out_base + i] = l1;
        g_qhi[out_base + i + 32] = h2; g_qlo[out_base + i + 32] = l2;
    }
    {
        const float* src = g_lin + lin_stride + in_base;
        float x1 = src[i], x2 = src[i + 32];
        float r1 = x1 * cs - x2 * sn;
        float r2 = x2 * cs + x1 * sn;
        float h1, l1, h2, l2;
        split2(r1, h1, l1); split2(r2, h2, l2);
        g_khi[out_base + i] = h1;      g_klo[out_base + i] = l1;
        g_khi[out_base + i + 32] = h2; g_klo[out_base + i + 32] = l2;
    }
    {
        const float* src = g_lin + 2 * lin_stride + in_base;
        g_v[out_base + i]      = src[i];
        g_v[out_base + i + 32] = src[i + 32];
    }
}

// ---------------- V transpose + split: (bh, s, d) -> hi/lo (bh, d, s) ----------------
__global__ void __launch_bounds__(256)
vtrans_kernel()
{
    __shared__ float t[32][33];
    const int bh = blockIdx.z;
    const int s0 = blockIdx.x * 32;
    const int d0 = blockIdx.y * 32;
    const float* src = g_v + (size_t)bh * Sn * Dn;
    const size_t dstb = (size_t)bh * Dn * Sn;
    const int tx = threadIdx.x & 31, ty = threadIdx.x >> 5;
    #pragma unroll
    for (int i = ty; i < 32; i += 8)
        t[i][tx] = src[(size_t)(s0 + i) * Dn + d0 + tx];
    __syncthreads();
    #pragma unroll
    for (int i = ty; i < 32; i += 8) {
        float v = t[tx][i];
        float h, l;
        split2(v, h, l);
        g_vthi[dstb + (size_t)(d0 + i) * Sn + s0 + tx] = h;
        g_vtlo[dstb + (size_t)(d0 + i) * Sn + s0 + tx] = l;
    }
}

// ---------------- gate + top-2 + dispatch ----------------
__global__ void __launch_bounds__(128)
gate_topk_kernel(const float* __restrict__ gw, const float* __restrict__ gb)
{
    const int warp = threadIdx.x >> 5;
    const int lane = threadIdx.x & 31;
    const int t = blockIdx.x * 4 + warp;

    float acc[NEXP];
    #pragma unroll
    for (int e = 0; e < NEXP; e++) acc[e] = 0.f;
    const float* xr = g_attn + (size_t)t * En;
    for (int i = lane; i < En; i += 32) {
        float xv = xr[i];
        #pragma unroll
        for (int e = 0; e < NEXP; e++) acc[e] += xv * gw[e * En + i];
    }
    #pragma unroll
    for (int e = 0; e < NEXP; e++) {
        #pragma unroll
        for (int off = 16; off; off >>= 1)
            acc[e] += __shfl_xor_sync(0xffffffffu, acc[e], off);
    }
    if (lane == 0) {
        float lg[NEXP];
        float m = -1e30f;
        #pragma unroll
        for (int e = 0; e < NEXP; e++) { lg[e] = acc[e] + gb[e]; m = fmaxf(m, lg[e]); }
        float sum = 0.f;
        #pragma unroll
        for (int e = 0; e < NEXP; e++) { lg[e] = __expf(lg[e] - m); sum += lg[e]; }
        float invs = 1.f / sum;
        int i0 = 0;
        #pragma unroll
        for (int e = 1; e < NEXP; e++) if (lg[e] > lg[i0]) i0 = e;
        int i1 = (i0 == 0) ? 1 : 0;
        #pragma unroll
        for (int e = 0; e < NEXP; e++) if (e != i0 && lg[e] > lg[i1]) i1 = e;

        int p0 = atomicAdd(&g_cnt[i0], 1);
        g_list[i0 * NTOK + p0] = t * 2;
        g_gateflat[t * 2] = lg[i0] * invs;
        int p1 = atomicAdd(&g_cnt[i1], 1);
        g_list[i1 * NTOK + p1] = t * 2 + 1;
        g_gateflat[t * 2 + 1] = lg[i1] * invs;
    }
}

// ---------------- combine expert slots ----------------
__global__ void combine_kernel()
{
    size_t i = (size_t)blockIdx.x * blockDim.x + threadIdx.x;
    size_t row = i >> 8;
    size_t col = i & 255;
    const float4* s4 = (const float4*)g_sel;
    float4 a = s4[(2 * row) * 256 + col];
    float4 b = s4[(2 * row + 1) * 256 + col];
    ((float4*)g_moe)[i] = make_float4(a.x + b.x, a.y + b.y, a.z + b.z, a.w + b.w);
}

// ---------------- launch ----------------
extern "C" void kernel_launch(void* const* d_in, const int* in_sizes, int n_in,
                              void* d_out, int out_size)
{
    const float* x     = (const float*)d_in[0];
    const float* q_w   = (const float*)d_in[1];
    const float* q_b   = (const float*)d_in[2];
    const float* k_w   = (const float*)d_in[3];
    const float* k_b   = (const float*)d_in[4];
    const float* v_w   = (const float*)d_in[5];
    const float* v_b   = (const float*)d_in[6];
    const float* gatew = (const float*)d_in[7];
    const float* gateb = (const float*)d_in[8];
    const float* ew    = (const float*)d_in[9];
    const float* eb    = (const float*)d_in[10];
    const float* ffn_w = (const float*)d_in[11];
    const float* ffn_b = (const float*)d_in[12];
    float* out = (float*)d_out;

    float *lin, *xhi, *xlo, *whi, *wlo, *moe;
    cudaGetSymbolAddress((void**)&lin,   g_lin);
    cudaGetSymbolAddress((void**)&xhi,   g_xhi);
    cudaGetSymbolAddress((void**)&xlo,   g_xlo);
    cudaGetSymbolAddress((void**)&whi,   g_whi);
    cudaGetSymbolAddress((void**)&wlo,   g_wlo);
    cudaGetSymbolAddress((void**)&moe,   g_moe);

    const int SMPS  = (4 * 128 * 36 + 4 * 128 * 36) * 4;   // 147456
    const int SM128 = (2 * 128 * 36 + 2 * 128 * 36) * 4;   // 73728
    const int SMFL  = (2 * 128 * FSTR + 2 * 64 * FSTR + 2 * 64 * FSTR
                       + 2 * 128 * FSTR) * 4;              // 208896
    cudaFuncSetAttribute(gemm_ps<128>,    cudaFuncAttributeMaxDynamicSharedMemorySize, SMPS);
    cudaFuncSetAttribute(flash_attn,      cudaFuncAttributeMaxDynamicSharedMemorySize, SMFL);
    cudaFuncSetAttribute(mma_gemm<128,0>, cudaFuncAttributeMaxDynamicSharedMemorySize, SM128);
    cudaFuncSetAttribute(expert_mma,      cudaFuncAttributeMaxDynamicSharedMemorySize, SM128);

    zero_cnt_kernel<<<1, 32>>>();

    // pre-split x and qkv weights
    split_kernel<<<(NTOK * En / 4 + 255) / 256, 256>>>(x, xhi, xlo, NTOK * En / 4);
    split_kernel<<<(En * En / 4 + 255) / 256, 256>>>(q_w, whi, wlo, En * En / 4);
    split_kernel<<<(En * En / 4 + 255) / 256, 256>>>(k_w, whi + (size_t)En * En,
                                                     wlo + (size_t)En * En, En * En / 4);
    split_kernel<<<(En * En / 4 + 255) / 256, 256>>>(v_w, whi + (size_t)2 * En * En,
                                                     wlo + (size_t)2 * En * En, En * En / 4);

    // fused QKV projections (pre-split planes)
    gemm_ps<128><<<dim3(En / 128, NTOK / 128, 3), 256, SMPS>>>(
        xhi, xlo, whi, wlo, q_b, k_b, v_b, lin,
        En, En, 0, (long long)En * En, (long long)NTOK * En, 1.f);

    rope_transpose_kernel<<<(Bn * Sn * Hn * 32) / 256, 256>>>();
    vtrans_kernel<<<dim3(Sn / 32, Dn / 32, BHn), 256>>>();

    // fused attention: scores + softmax + PV in one kernel
    flash_attn<<<dim3(Sn / 128, BHn), 256, SMFL>>>();

    gate_topk_kernel<<<NTOK / 4, 128>>>(gatew, gateb);

    expert_mma<<<dim3(En / 128, NTOK / 128, NEXP), 256, SM128>>>(ew, eb);

    combine_kernel<<<(NTOK * (En / 4)) / 256, 256>>>();

    // final FFN + bias + residual (plain tf32)
    mma_gemm<128,0><<<dim3(En / 128, NTOK / 128, 1), 256, SM128>>>(
        moe, ffn_w, ffn_b, x, out,
        NTOK, En, En, 0, 0, 0, 1.f, 0);
}